// round 1
// baseline (speedup 1.0000x reference)
#include <cuda_runtime.h>
#include <math.h>

// ---------------------------------------------------------------------------
// Problem constants
// ---------------------------------------------------------------------------
#define Bc   4
#define Sq   2048
#define Dm   1024
#define Hh   16
#define DHd  64
#define Ee   8
#define Ff   4096
#define Ntok (Bc*Sq)          // 8192
#define CAP  1280             // int(1.25 * 8192 / 8)
#define SLOTS (Ee*CAP)        // 10240

// ---------------------------------------------------------------------------
// Device scratch (static, allowed)
// ---------------------------------------------------------------------------
__device__ float g_xln [Ntok*Dm];
__device__ float g_qkv [Ntok*3*Dm];
__device__ float g_attn[Ntok*Dm];
__device__ float g_src1[Ntok*Dm];
__device__ float g_x2  [Ntok*Dm];
__device__ float g_disp[SLOTS*Dm];
__device__ float g_hbuf[(size_t)SLOTS*Ff];
__device__ float g_obuf[SLOTS*Dm];
__device__ float g_probs[Ntok*Ee];
__device__ float g_zterm[Ntok];
__device__ float g_gate [Ntok];
__device__ int   g_eidx [Ntok];
__device__ int   g_keep [Ntok];
__device__ int   g_slot [Ntok];
__device__ int   g_tok  [SLOTS];
__device__ int   g_cnt  [Ee];

// ---------------------------------------------------------------------------
// LayerNorm: one block per token, 256 threads, D=1024 (one float4/thread)
// ---------------------------------------------------------------------------
__global__ __launch_bounds__(256) void ln_kernel(const float* __restrict__ in,
                                                 const float* __restrict__ g,
                                                 const float* __restrict__ b,
                                                 float* __restrict__ out)
{
    int n = blockIdx.x, tid = threadIdx.x;
    float4 v = ((const float4*)(in + (size_t)n*Dm))[tid];
    float s  = v.x+v.y+v.z+v.w;
    float s2 = v.x*v.x+v.y*v.y+v.z*v.z+v.w*v.w;
    __shared__ float r1[256], r2[256];
    r1[tid]=s; r2[tid]=s2; __syncthreads();
    for (int st=128; st; st>>=1) {
        if (tid<st) { r1[tid]+=r1[tid+st]; r2[tid]+=r2[tid+st]; }
        __syncthreads();
    }
    float mean = r1[0]*(1.0f/Dm);
    float var  = r2[0]*(1.0f/Dm) - mean*mean;
    float rstd = rsqrtf(var + 1e-5f);
    float4 gg = ((const float4*)g)[tid];
    float4 bb = ((const float4*)b)[tid];
    float4 o;
    o.x = (v.x-mean)*rstd*gg.x + bb.x;
    o.y = (v.y-mean)*rstd*gg.y + bb.y;
    o.z = (v.z-mean)*rstd*gg.z + bb.z;
    o.w = (v.w-mean)*rstd*gg.w + bb.w;
    ((float4*)(out + (size_t)n*Dm))[tid] = o;
}

// ---------------------------------------------------------------------------
// Generic fp32 GEMM: C[M,N] = A[M,K] * B (+bias, +relu, +residual)
//   BT=true : B stored [N,K] (row-major) -> C = A * B^T
//   BT=false: B stored [K,N] (row-major) -> C = A * B
// Per-expert weights: expert = row_tile_start / rowsPerExpert
// Tiles: 128x128x8, 256 threads, 8x8 microtile. M,N %128==0, K %8==0 assumed.
// ---------------------------------------------------------------------------
template<bool BT, bool RELU, bool RES>
__global__ __launch_bounds__(256) void gemm128(
    const float* __restrict__ A, const float* __restrict__ Bm,
    const float* __restrict__ bias, const float* __restrict__ Res,
    float* __restrict__ C, int M, int Nn, int K,
    int rowsPerExpert, long long bExpStride, int biasExpStride)
{
    __shared__ float As[8][128];
    __shared__ float Bs[8][128];
    const int tid = threadIdx.x;
    const int tx = tid & 15, ty = tid >> 4;
    const int row0 = blockIdx.y * 128, col0 = blockIdx.x * 128;
    const int expert = row0 / rowsPerExpert;
    const float* Bexp = Bm + (long long)expert * bExpStride;
    const float* bb   = bias + (long long)expert * biasExpStride;

    float acc[8][8];
#pragma unroll
    for (int i=0;i<8;i++)
#pragma unroll
        for (int j=0;j<8;j++) acc[i][j]=0.f;

    const int arow = tid >> 1, akk = (tid & 1) * 4;

    for (int k0 = 0; k0 < K; k0 += 8) {
        // load A tile (128x8) transposed into As[k][row]
        float4 a4 = *(const float4*)(A + (size_t)(row0+arow)*K + k0 + akk);
        As[akk+0][arow]=a4.x; As[akk+1][arow]=a4.y;
        As[akk+2][arow]=a4.z; As[akk+3][arow]=a4.w;
        if (BT) {
            int nn = tid >> 1, kk = (tid & 1) * 4;
            float4 b4 = *(const float4*)(Bexp + (size_t)(col0+nn)*K + k0 + kk);
            Bs[kk+0][nn]=b4.x; Bs[kk+1][nn]=b4.y;
            Bs[kk+2][nn]=b4.z; Bs[kk+3][nn]=b4.w;
        } else {
            int kr = tid >> 5, nc = (tid & 31) * 4;
            float4 b4 = *(const float4*)(Bexp + (size_t)(k0+kr)*Nn + col0 + nc);
            *(float4*)&Bs[kr][nc] = b4;
        }
        __syncthreads();
#pragma unroll
        for (int k=0;k<8;k++) {
            float4 a0 = *(const float4*)&As[k][ty*8];
            float4 a1 = *(const float4*)&As[k][ty*8+4];
            float4 b0 = *(const float4*)&Bs[k][tx*8];
            float4 b1 = *(const float4*)&Bs[k][tx*8+4];
            float ar[8]={a0.x,a0.y,a0.z,a0.w,a1.x,a1.y,a1.z,a1.w};
            float br[8]={b0.x,b0.y,b0.z,b0.w,b1.x,b1.y,b1.z,b1.w};
#pragma unroll
            for (int i=0;i<8;i++)
#pragma unroll
                for (int j=0;j<8;j++) acc[i][j] += ar[i]*br[j];
        }
        __syncthreads();
    }

    float bj[8];
#pragma unroll
    for (int j=0;j<8;j++) bj[j] = bb[col0 + tx*8 + j];
#pragma unroll
    for (int i=0;i<8;i++) {
        int gr = row0 + ty*8 + i;
#pragma unroll
        for (int j=0;j<8;j++) {
            int gc = col0 + tx*8 + j;
            float v = acc[i][j] + bj[j];
            if (RELU) v = fmaxf(v, 0.f);
            if (RES)  v += Res[(size_t)gr*Nn + gc];
            C[(size_t)gr*Nn + gc] = v;
        }
    }
}

// ---------------------------------------------------------------------------
// Fused flash attention (fp32). grid=(S/64, B*H), 256 threads.
// qkv layout: [token][3*1024], q at h*64, k at 1024+h*64, v at 2048+h*64.
// ---------------------------------------------------------------------------
#define ATTN_SMEM ((64*64 + 64*68 + 64*68 + 64) * 4)

__global__ __launch_bounds__(256) void attn_kernel(const float* __restrict__ qkv,
                                                   const unsigned char* __restrict__ pad,
                                                   float* __restrict__ out)
{
    extern __shared__ float sm[];
    float* Qt = sm;                 // [64 d][64 q], stride 64 (q pre-scaled)
    float* KP = Qt + 64*64;         // [64 d][68]: K^T, then reused as P^T [64 k][68 q]
    float* Vs = KP + 64*68;         // [64 k][68 d]
    float* mk = Vs + 64*68;         // [64] mask add

    const int tid = threadIdx.x;
    const int tx = tid & 15, ty = tid >> 4;
    const int bh = blockIdx.y;
    const int b = bh >> 4, h = bh & 15;
    const int q0 = blockIdx.x * 64;
    const float scale = 0.125f;     // 1/sqrt(64)

    // Load Q tile, transposed + pre-scaled
    for (int idx = tid; idx < 64*16; idx += 256) {
        int qi = idx >> 4, dd = (idx & 15) * 4;
        float4 v = *(const float4*)(qkv + (size_t)(b*Sq + q0 + qi)*3072 + h*64 + dd);
        Qt[(dd+0)*64+qi]=v.x*scale; Qt[(dd+1)*64+qi]=v.y*scale;
        Qt[(dd+2)*64+qi]=v.z*scale; Qt[(dd+3)*64+qi]=v.w*scale;
    }

    float m[4], l[4], o[4][4];
#pragma unroll
    for (int i=0;i<4;i++){ m[i]=-1e30f; l[i]=0.f;
#pragma unroll
        for (int j=0;j<4;j++) o[i][j]=0.f; }

    for (int kt = 0; kt < Sq/64; kt++) {
        const int k0 = kt * 64;
        __syncthreads();  // protect KP/Vs from previous iteration readers
        for (int idx = tid; idx < 64*16; idx += 256) {
            int kj = idx >> 4, dd = (idx & 15) * 4;
            const float* base = qkv + (size_t)(b*Sq + k0 + kj)*3072 + h*64;
            float4 kv = *(const float4*)(base + 1024 + dd);
            KP[(dd+0)*68+kj]=kv.x; KP[(dd+1)*68+kj]=kv.y;
            KP[(dd+2)*68+kj]=kv.z; KP[(dd+3)*68+kj]=kv.w;
            float4 vv = *(const float4*)(base + 2048 + dd);
            *(float4*)&Vs[kj*68 + dd] = vv;
        }
        if (tid < 64) mk[tid] = pad[b*Sq + k0 + tid] ? -1e9f : 0.f;
        __syncthreads();

        // scores s = (q*scale) . k  + mask
        float s[4][4];
#pragma unroll
        for (int i=0;i<4;i++)
#pragma unroll
            for (int j=0;j<4;j++) s[i][j]=0.f;
        for (int d=0; d<64; d++) {
            float4 qa = *(const float4*)&Qt[d*64 + ty*4];
            float4 kb = *(const float4*)&KP[d*68 + tx*4];
            float qr[4]={qa.x,qa.y,qa.z,qa.w};
            float kr[4]={kb.x,kb.y,kb.z,kb.w};
#pragma unroll
            for (int i=0;i<4;i++)
#pragma unroll
                for (int j=0;j<4;j++) s[i][j] += qr[i]*kr[j];
        }
#pragma unroll
        for (int i=0;i<4;i++)
#pragma unroll
            for (int j=0;j<4;j++) s[i][j] += mk[tx*4+j];

        // online softmax update (row stats shared across the 16 tx lanes)
#pragma unroll
        for (int i=0;i<4;i++) {
            float rm = fmaxf(fmaxf(s[i][0],s[i][1]), fmaxf(s[i][2],s[i][3]));
            for (int off=1; off<16; off<<=1)
                rm = fmaxf(rm, __shfl_xor_sync(0xffffffffu, rm, off));
            float nm = fmaxf(m[i], rm);
            float corr = __expf(m[i]-nm);
            m[i] = nm;
            float rs = 0.f;
#pragma unroll
            for (int j=0;j<4;j++) { s[i][j] = __expf(s[i][j]-nm); rs += s[i][j]; }
            for (int off=1; off<16; off<<=1)
                rs += __shfl_xor_sync(0xffffffffu, rs, off);
            l[i] = l[i]*corr + rs;
#pragma unroll
            for (int j=0;j<4;j++) o[i][j] *= corr;
        }

        __syncthreads();  // everyone done reading KP as K
        // store P transposed into KP: P^T[k][q]
#pragma unroll
        for (int i=0;i<4;i++)
#pragma unroll
            for (int j=0;j<4;j++)
                KP[(tx*4+j)*68 + ty*4 + i] = s[i][j];
        __syncthreads();

        // o += P @ V
        for (int k=0;k<64;k++) {
            float4 p4 = *(const float4*)&KP[k*68 + ty*4];
            float4 v4 = *(const float4*)&Vs[k*68 + tx*4];
            float pr[4]={p4.x,p4.y,p4.z,p4.w};
            float vr[4]={v4.x,v4.y,v4.z,v4.w};
#pragma unroll
            for (int i=0;i<4;i++)
#pragma unroll
                for (int j=0;j<4;j++) o[i][j] += pr[i]*vr[j];
        }
    }

#pragma unroll
    for (int i=0;i<4;i++) {
        float inv = 1.0f / l[i];
        int qrow = q0 + ty*4 + i;
#pragma unroll
        for (int j=0;j<4;j++)
            out[(size_t)(b*Sq + qrow)*Dm + h*64 + tx*4 + j] = o[i][j]*inv;
    }
}

// ---------------------------------------------------------------------------
// Router: one block per token. 8 warps each compute one expert logit.
// ---------------------------------------------------------------------------
__global__ __launch_bounds__(256) void router_kernel(const float* __restrict__ rw,
                                                     const float* __restrict__ rb,
                                                     const unsigned char* __restrict__ pad)
{
    int n = blockIdx.x, tid = threadIdx.x;
    __shared__ float xs[1024];
    __shared__ float lg[8];
    ((float4*)xs)[tid] = ((const float4*)(g_x2 + (size_t)n*Dm))[tid];
    __syncthreads();
    int w = tid >> 5, lane = tid & 31;
    float acc = 0.f;
    for (int i = lane; i < 1024; i += 32) acc += xs[i] * rw[i*8 + w];
    for (int off=16; off; off>>=1) acc += __shfl_xor_sync(0xffffffffu, acc, off);
    if (lane == 0) lg[w] = acc + rb[w];
    __syncthreads();
    if (tid == 0) {
        float mx = lg[0]; int ei = 0;
        for (int e=1;e<8;e++) if (lg[e] > mx) { mx = lg[e]; ei = e; }
        float pr[8], se = 0.f;
        for (int e=0;e<8;e++) { pr[e] = expf(lg[e]-mx); se += pr[e]; }
        float inv = 1.f/se;
        bool valid = (pad[n] == 0);
        float tm = valid ? 1.f : 0.f;
        for (int e=0;e<8;e++) g_probs[n*8+e] = pr[e]*inv*tm;
        g_gate[n] = pr[ei]*inv;
        g_eidx[n] = ei;
        float lse = mx + logf(se);
        g_zterm[n] = lse*lse*tm;
    }
}

// ---------------------------------------------------------------------------
// Token->slot scan, exact token order, single warp (deterministic).
// ---------------------------------------------------------------------------
__global__ void scan_kernel(const unsigned char* __restrict__ pad)
{
    int lane = threadIdx.x; // 32 threads
    __shared__ int base[8];
    if (lane < 8) base[lane] = 0;
    __syncwarp();
    for (int c = 0; c < Ntok/32; c++) {
        int i = c*32 + lane;
        int e = g_eidx[i];
        bool valid = (pad[i] == 0);
        unsigned peers = __match_any_sync(0xffffffffu, e);
        unsigned vmask = __ballot_sync(0xffffffffu, valid);
        unsigned pv = peers & vmask;
        int myrank = __popc(pv & ((1u << lane) - 1u));
        int b0 = base[e];
        __syncwarp();
        int pos = b0 + myrank;
        bool keep = valid && (pos < CAP);
        g_keep[i] = keep ? 1 : 0;
        int slot = e*CAP + pos;
        g_slot[i] = keep ? slot : 0;
        if (keep) g_tok[slot] = i;
        if (valid && lane == (__ffs(pv) - 1)) base[e] = b0 + __popc(pv);
        __syncwarp();
    }
    if (lane < 8) g_cnt[lane] = base[lane];
}

__global__ __launch_bounds__(256) void init_tok_kernel()
{
    int i = blockIdx.x*256 + threadIdx.x;
    if (i < SLOTS) g_tok[i] = -1;
}

__global__ __launch_bounds__(256) void dispatch_kernel()
{
    int slot = blockIdx.x, tid = threadIdx.x;
    int t = g_tok[slot];
    float4 v = make_float4(0.f,0.f,0.f,0.f);
    if (t >= 0) v = ((const float4*)(g_x2 + (size_t)t*Dm))[tid];
    ((float4*)(g_disp + (size_t)slot*Dm))[tid] = v;
}

__global__ __launch_bounds__(256) void combine_kernel(float* __restrict__ out)
{
    int n = blockIdx.x, tid = threadIdx.x;
    float4 s = ((const float4*)(g_src1 + (size_t)n*Dm))[tid];
    if (g_keep[n]) {
        float gte = g_gate[n];
        float4 o = ((const float4*)(g_obuf + (size_t)g_slot[n]*Dm))[tid];
        s.x += gte*o.x; s.y += gte*o.y; s.z += gte*o.z; s.w += gte*o.w;
    }
    ((float4*)(out + (size_t)n*Dm))[tid] = s;
}

// ---------------------------------------------------------------------------
// Loss reduction: single block, deterministic tree reduce.
// ---------------------------------------------------------------------------
__global__ __launch_bounds__(256) void loss_kernel(const unsigned char* __restrict__ pad,
                                                   float* __restrict__ out)
{
    int tid = threadIdx.x;
    float zs = 0.f, ps[8];
    int cnt = 0;
#pragma unroll
    for (int e=0;e<8;e++) ps[e]=0.f;
    for (int n = tid; n < Ntok; n += 256) {
        if (pad[n] == 0) cnt++;
        zs += g_zterm[n];
#pragma unroll
        for (int e=0;e<8;e++) ps[e] += g_probs[n*8+e];
    }
    __shared__ float red[256];
    __shared__ float res[10];
    float vals[10];
    vals[0] = (float)cnt; vals[1] = zs;
    for (int e=0;e<8;e++) vals[2+e] = ps[e];
    for (int q=0;q<10;q++) {
        red[tid] = vals[q]; __syncthreads();
        for (int st=128; st; st>>=1) {
            if (tid < st) red[tid] += red[tid+st];
            __syncthreads();
        }
        if (tid == 0) res[q] = red[0];
        __syncthreads();
    }
    if (tid == 0) {
        float denom = fmaxf(res[0], 1.f);
        float lb = 0.f;
        for (int e=0;e<8;e++) lb += ((float)g_cnt[e]/denom) * (res[2+e]/denom);
        lb *= (float)Ee;
        out[(size_t)Ntok*Dm]     = lb;
        out[(size_t)Ntok*Dm + 1] = res[1]/denom;
    }
}

// ---------------------------------------------------------------------------
// Launch
// ---------------------------------------------------------------------------
extern "C" void kernel_launch(void* const* d_in, const int* in_sizes, int n_in,
                              void* d_out, int out_size)
{
    const float* src  = (const float*)d_in[0];
    const unsigned char* pad = (const unsigned char*)d_in[1];
    const float* ln1g = (const float*)d_in[2];
    const float* ln1b = (const float*)d_in[3];
    const float* ipw  = (const float*)d_in[4];
    const float* ipb  = (const float*)d_in[5];
    const float* opw  = (const float*)d_in[6];
    const float* opb  = (const float*)d_in[7];
    const float* ln2g = (const float*)d_in[8];
    const float* ln2b = (const float*)d_in[9];
    const float* rw   = (const float*)d_in[10];
    const float* rb   = (const float*)d_in[11];
    const float* w1   = (const float*)d_in[12];
    const float* b1   = (const float*)d_in[13];
    const float* w2   = (const float*)d_in[14];
    const float* b2   = (const float*)d_in[15];
    float* out = (float*)d_out;

    float *xln, *qkv, *attn, *src1, *x2, *disp, *hb, *ob;
    cudaGetSymbolAddress((void**)&xln,  g_xln);
    cudaGetSymbolAddress((void**)&qkv,  g_qkv);
    cudaGetSymbolAddress((void**)&attn, g_attn);
    cudaGetSymbolAddress((void**)&src1, g_src1);
    cudaGetSymbolAddress((void**)&x2,   g_x2);
    cudaGetSymbolAddress((void**)&disp, g_disp);
    cudaGetSymbolAddress((void**)&hb,   g_hbuf);
    cudaGetSymbolAddress((void**)&ob,   g_obuf);

    cudaFuncSetAttribute(attn_kernel, cudaFuncAttributeMaxDynamicSharedMemorySize, ATTN_SMEM);

    // 1. LN1
    ln_kernel<<<Ntok, 256>>>(src, ln1g, ln1b, xln);
    // 2. QKV projection (B^T): [8192,3072] = xln[8192,1024] @ in_proj_w[3072,1024]^T
    gemm128<true,false,false><<<dim3(3072/128, Ntok/128), 256>>>(
        xln, ipw, ipb, nullptr, qkv, Ntok, 3072, 1024, 1<<30, 0, 0);
    // 3. Attention
    attn_kernel<<<dim3(Sq/64, Bc*Hh), 256, ATTN_SMEM>>>(qkv, pad, attn);
    // 4. out_proj + residual(src) -> src1
    gemm128<true,false,true><<<dim3(1024/128, Ntok/128), 256>>>(
        attn, opw, opb, src, src1, Ntok, 1024, 1024, 1<<30, 0, 0);
    // 5. LN2
    ln_kernel<<<Ntok, 256>>>(src1, ln2g, ln2b, x2);
    // 6. Router
    router_kernel<<<Ntok, 256>>>(rw, rb, pad);
    // 7-9. Scan + dispatch
    init_tok_kernel<<<(SLOTS+255)/256, 256>>>();
    scan_kernel<<<1, 32>>>(pad);
    dispatch_kernel<<<SLOTS, 256>>>();
    // 10. FFN1: [10240,4096] = disp @ w1[e] (+b1, relu)
    gemm128<false,true,false><<<dim3(Ff/128, SLOTS/128), 256>>>(
        disp, w1, b1, nullptr, hb, SLOTS, Ff, Dm, CAP, (long long)Dm*Ff, Ff);
    // 11. FFN2: [10240,1024] = h @ w2[e] (+b2)
    gemm128<false,false,false><<<dim3(Dm/128, SLOTS/128), 256>>>(
        hb, w2, b2, nullptr, ob, SLOTS, Dm, Ff, CAP, (long long)Ff*Dm, Dm);
    // 12. Combine + residual -> d_out
    combine_kernel<<<Ntok, 256>>>(out);
    // 13. Losses
    loss_kernel<<<1, 256>>>(pad, out);
}

// round 3
// speedup vs baseline: 1.8465x; 1.8465x over previous
#include <cuda_runtime.h>
#include <math.h>
#include <stdint.h>

// ---------------------------------------------------------------------------
// Problem constants
// ---------------------------------------------------------------------------
#define Bc   4
#define Sq   2048
#define Dm   1024
#define Hh   16
#define Ee   8
#define Ff   4096
#define Ntok (Bc*Sq)          // 8192
#define CAP  1280
#define SLOTS (Ee*CAP)        // 10240

// ---------------------------------------------------------------------------
// Device scratch
// ---------------------------------------------------------------------------
__device__ float g_xln [Ntok*Dm];
__device__ float g_qkv [Ntok*3*Dm];
__device__ float g_attn[Ntok*Dm];
__device__ float g_src1[Ntok*Dm];
__device__ float g_x2  [Ntok*Dm];
__device__ float g_disp[SLOTS*Dm];
__device__ float g_hbuf[(size_t)SLOTS*Ff];
__device__ float g_obuf[SLOTS*Dm];
__device__ float g_probs[Ntok*Ee];
__device__ float g_zterm[Ntok];
__device__ float g_gate [Ntok];
__device__ int   g_eidx [Ntok];
__device__ int   g_keep [Ntok];
__device__ int   g_slot [Ntok];
__device__ int   g_tok  [SLOTS];
__device__ int   g_cnt  [Ee];
// tf32-rounded weight copies / transposes ([N,K] layouts)
__device__ float g_ipw32[3*Dm*Dm];
__device__ float g_opw32[Dm*Dm];
__device__ float g_w1t [(size_t)Ee*Ff*Dm];   // [E][F][D]
__device__ float g_w2t [(size_t)Ee*Dm*Ff];   // [E][D][F]

// ---------------------------------------------------------------------------
// Helpers
// ---------------------------------------------------------------------------
__device__ __forceinline__ uint32_t smem_u32(const void* p) {
    uint32_t a;
    asm("{ .reg .u64 t; cvta.to.shared.u64 t, %1; cvt.u32.u64 %0, t; }"
        : "=r"(a) : "l"(p));
    return a;
}
__device__ __forceinline__ float to_tf32(float x) {
    uint32_t u;
    asm("cvt.rna.tf32.f32 %0, %1;" : "=r"(u) : "f"(x));
    return __uint_as_float(u);
}
__device__ __forceinline__ void cp16(uint32_t dst, const void* src) {
    asm volatile("cp.async.cg.shared.global [%0], [%1], 16;" :: "r"(dst), "l"(src));
}
__device__ __forceinline__ void mma_tf32(float* d, const uint32_t* a, const uint32_t* b) {
    asm volatile(
        "mma.sync.aligned.m16n8k8.row.col.f32.tf32.tf32.f32 "
        "{%0,%1,%2,%3}, {%4,%5,%6,%7}, {%8,%9}, {%0,%1,%2,%3};"
        : "+f"(d[0]), "+f"(d[1]), "+f"(d[2]), "+f"(d[3])
        : "r"(a[0]), "r"(a[1]), "r"(a[2]), "r"(a[3]), "r"(b[0]), "r"(b[1]));
}

// ---------------------------------------------------------------------------
// tf32 mma.sync GEMM: C[M,N] = A[M,K] @ B[N,K]^T (+bias, relu, residual, round)
// Block tile 128x128, BK=16, 8 warps (2m x 4n), warp tile 64x32.
// smem rows padded to 20 floats (80B, 16B-aligned) -> conflict-free frag LDS.
// 3-stage cp.async pipeline. A,B data must be pre-rounded to tf32.
// ---------------------------------------------------------------------------
#define BM 128
#define BN 128
#define BK 16
#define SSTR 20                       // floats per padded smem row
#define STAGE_F (BM*SSTR + BN*SSTR)   // floats per stage (A then B)
#define GEMM_SMEM (3*STAGE_F*4)       // 61440 bytes

template<bool RELU, bool RES, bool ROUND>
__global__ __launch_bounds__(256, 2) void gemm_mma(
    const float* __restrict__ A, const float* __restrict__ Bm,
    const float* __restrict__ bias, const float* __restrict__ Res,
    float* __restrict__ C, int Nld, int K,
    int rowsPerExpert, long long bExpStride, int biasExpStride)
{
    extern __shared__ float smem[];
    const uint32_t sb = smem_u32(smem);

    const int tid = threadIdx.x;
    const int wid = tid >> 5, lane = tid & 31;
    const int lr = lane >> 2, lc = lane & 3;
    const int row0 = blockIdx.y * BM;
    const int col0 = blockIdx.x * BN;
    const int expert = row0 / rowsPerExpert;
    const float* Bexp = Bm + (long long)expert * bExpStride;
    const float* bb   = bias + (long long)expert * biasExpStride;

    const int m0 = (wid & 1) * 64;    // warp m offset in tile
    const int n0 = (wid >> 1) * 32;   // warp n offset in tile

    const float* Abase = A    + (size_t)row0 * K;
    const float* Bbase = Bexp + (size_t)col0 * K;

    float acc[16][4];
#pragma unroll
    for (int t = 0; t < 16; t++)
#pragma unroll
        for (int q = 0; q < 4; q++) acc[t][q] = 0.f;

    const int nch = K / BK;

    // --- stage loader: 512 x 16B segments each for A and B; 256 threads x2 ---
    auto load_stage = [&](int s, int ch) {
        const uint32_t sa = sb + (uint32_t)(s * STAGE_F) * 4u;
        const uint32_t sbm = sa + BM * SSTR * 4u;
        const float* Ac = Abase + ch * BK;
        const float* Bcp = Bbase + ch * BK;
#pragma unroll
        for (int j = 0; j < 2; j++) {
            int seg = tid * 2 + j;                // 0..511
            int r = seg >> 2, s4 = seg & 3;
            cp16(sa  + (uint32_t)(r * 80 + s4 * 16), Ac  + (size_t)r * K + s4 * 4);
            cp16(sbm + (uint32_t)(r * 80 + s4 * 16), Bcp + (size_t)r * K + s4 * 4);
        }
    };

    load_stage(0, 0);
    asm volatile("cp.async.commit_group;");
    load_stage(1, 1);
    asm volatile("cp.async.commit_group;");

    for (int i = 0; i < nch; i++) {
        if (i + 2 < nch) load_stage((i + 2) % 3, i + 2);
        asm volatile("cp.async.commit_group;");
        asm volatile("cp.async.wait_group 2;");
        __syncthreads();

        const float* As = smem + (i % 3) * STAGE_F;
        const float* Bs = As + BM * SSTR;
#pragma unroll
        for (int kk = 0; kk < BK; kk += 8) {
            uint32_t a[4][4], b[4][2];
#pragma unroll
            for (int t = 0; t < 4; t++) {
                int r = m0 + t * 16 + lr;
                a[t][0] = __float_as_uint(As[ r      * SSTR + kk + lc]);
                a[t][1] = __float_as_uint(As[(r + 8) * SSTR + kk + lc]);
                a[t][2] = __float_as_uint(As[ r      * SSTR + kk + 4 + lc]);
                a[t][3] = __float_as_uint(As[(r + 8) * SSTR + kk + 4 + lc]);
            }
#pragma unroll
            for (int t = 0; t < 4; t++) {
                int c = n0 + t * 8 + lr;
                b[t][0] = __float_as_uint(Bs[c * SSTR + kk + lc]);
                b[t][1] = __float_as_uint(Bs[c * SSTR + kk + 4 + lc]);
            }
#pragma unroll
            for (int ti = 0; ti < 4; ti++)
#pragma unroll
                for (int tj = 0; tj < 4; tj++)
                    mma_tf32(acc[ti * 4 + tj], a[ti], b[tj]);
        }
        __syncthreads();
    }

    // --- epilogue ---
#pragma unroll
    for (int ti = 0; ti < 4; ti++) {
        const int gr0 = row0 + m0 + ti * 16 + lr;
#pragma unroll
        for (int tj = 0; tj < 4; tj++) {
            const int gc = col0 + n0 + tj * 8 + lc * 2;
            float* d = acc[ti * 4 + tj];
            float b0 = bb[gc], b1 = bb[gc + 1];
            float v0 = d[0] + b0, v1 = d[1] + b1;
            float v2 = d[2] + b0, v3 = d[3] + b1;
            if (RELU) {
                v0 = fmaxf(v0, 0.f); v1 = fmaxf(v1, 0.f);
                v2 = fmaxf(v2, 0.f); v3 = fmaxf(v3, 0.f);
            }
            if (RES) {
                float2 r0 = *(const float2*)(Res + (size_t)gr0 * Nld + gc);
                float2 r1 = *(const float2*)(Res + (size_t)(gr0 + 8) * Nld + gc);
                v0 += r0.x; v1 += r0.y; v2 += r1.x; v3 += r1.y;
            }
            if (ROUND) {
                v0 = to_tf32(v0); v1 = to_tf32(v1);
                v2 = to_tf32(v2); v3 = to_tf32(v3);
            }
            *(float2*)(C + (size_t)gr0 * Nld + gc)       = make_float2(v0, v1);
            *(float2*)(C + (size_t)(gr0 + 8) * Nld + gc) = make_float2(v2, v3);
        }
    }
}

// ---------------------------------------------------------------------------
// LayerNorm (optional tf32 rounding of output)
// ---------------------------------------------------------------------------
template<bool ROUND>
__global__ __launch_bounds__(256) void ln_kernel(const float* __restrict__ in,
                                                 const float* __restrict__ g,
                                                 const float* __restrict__ b,
                                                 float* __restrict__ out)
{
    int n = blockIdx.x, tid = threadIdx.x;
    float4 v = ((const float4*)(in + (size_t)n*Dm))[tid];
    float s  = v.x+v.y+v.z+v.w;
    float s2 = v.x*v.x+v.y*v.y+v.z*v.z+v.w*v.w;
    __shared__ float r1[256], r2[256];
    r1[tid]=s; r2[tid]=s2; __syncthreads();
    for (int st=128; st; st>>=1) {
        if (tid<st) { r1[tid]+=r1[tid+st]; r2[tid]+=r2[tid+st]; }
        __syncthreads();
    }
    float mean = r1[0]*(1.0f/Dm);
    float var  = r2[0]*(1.0f/Dm) - mean*mean;
    float rstd = rsqrtf(var + 1e-5f);
    float4 gg = ((const float4*)g)[tid];
    float4 bb = ((const float4*)b)[tid];
    float4 o;
    o.x = (v.x-mean)*rstd*gg.x + bb.x;
    o.y = (v.y-mean)*rstd*gg.y + bb.y;
    o.z = (v.z-mean)*rstd*gg.z + bb.z;
    o.w = (v.w-mean)*rstd*gg.w + bb.w;
    if (ROUND) { o.x=to_tf32(o.x); o.y=to_tf32(o.y); o.z=to_tf32(o.z); o.w=to_tf32(o.w); }
    ((float4*)(out + (size_t)n*Dm))[tid] = o;
}

// ---------------------------------------------------------------------------
// Weight prep
// ---------------------------------------------------------------------------
__global__ __launch_bounds__(256) void round_copy(const float* __restrict__ in,
                                                  float* __restrict__ out, int n4)
{
    int i = blockIdx.x*256 + threadIdx.x;
    if (i < n4) {
        float4 v = ((const float4*)in)[i];
        v.x=to_tf32(v.x); v.y=to_tf32(v.y); v.z=to_tf32(v.z); v.w=to_tf32(v.w);
        ((float4*)out)[i] = v;
    }
}

__global__ __launch_bounds__(256) void transpose_round(const float* __restrict__ in,
                                                       float* __restrict__ out,
                                                       int R, int Cc)
{
    __shared__ float t[32][33];
    int e = blockIdx.z;
    const float* ip = in  + (size_t)e*R*Cc;
    float* op       = out + (size_t)e*R*Cc;
    int c0 = blockIdx.x*32, r0 = blockIdx.y*32;
    int tx = threadIdx.x, ty = threadIdx.y;
#pragma unroll
    for (int j=0;j<32;j+=8)
        t[ty+j][tx] = to_tf32(ip[(size_t)(r0+ty+j)*Cc + c0+tx]);
    __syncthreads();
#pragma unroll
    for (int j=0;j<32;j+=8)
        op[(size_t)(c0+ty+j)*R + r0+tx] = t[tx][ty+j];
}

// ---------------------------------------------------------------------------
// Fused flash attention (fp32), output rounded to tf32
// ---------------------------------------------------------------------------
#define ATTN_SMEM ((64*64 + 64*68 + 64*68 + 64) * 4)

__global__ __launch_bounds__(256) void attn_kernel(const float* __restrict__ qkv,
                                                   const unsigned char* __restrict__ pad,
                                                   float* __restrict__ out)
{
    extern __shared__ float sm[];
    float* Qt = sm;
    float* KP = Qt + 64*64;
    float* Vs = KP + 64*68;
    float* mk = Vs + 64*68;

    const int tid = threadIdx.x;
    const int tx = tid & 15, ty = tid >> 4;
    const int bh = blockIdx.y;
    const int b = bh >> 4, h = bh & 15;
    const int q0 = blockIdx.x * 64;
    const float scale = 0.125f;

    for (int idx = tid; idx < 64*16; idx += 256) {
        int qi = idx >> 4, dd = (idx & 15) * 4;
        float4 v = *(const float4*)(qkv + (size_t)(b*Sq + q0 + qi)*3072 + h*64 + dd);
        Qt[(dd+0)*64+qi]=v.x*scale; Qt[(dd+1)*64+qi]=v.y*scale;
        Qt[(dd+2)*64+qi]=v.z*scale; Qt[(dd+3)*64+qi]=v.w*scale;
    }

    float m[4], l[4], o[4][4];
#pragma unroll
    for (int i=0;i<4;i++){ m[i]=-1e30f; l[i]=0.f;
#pragma unroll
        for (int j=0;j<4;j++) o[i][j]=0.f; }

    for (int kt = 0; kt < Sq/64; kt++) {
        const int k0 = kt * 64;
        __syncthreads();
        for (int idx = tid; idx < 64*16; idx += 256) {
            int kj = idx >> 4, dd = (idx & 15) * 4;
            const float* base = qkv + (size_t)(b*Sq + k0 + kj)*3072 + h*64;
            float4 kv = *(const float4*)(base + 1024 + dd);
            KP[(dd+0)*68+kj]=kv.x; KP[(dd+1)*68+kj]=kv.y;
            KP[(dd+2)*68+kj]=kv.z; KP[(dd+3)*68+kj]=kv.w;
            float4 vv = *(const float4*)(base + 2048 + dd);
            *(float4*)&Vs[kj*68 + dd] = vv;
        }
        if (tid < 64) mk[tid] = pad[b*Sq + k0 + tid] ? -1e9f : 0.f;
        __syncthreads();

        float s[4][4];
#pragma unroll
        for (int i=0;i<4;i++)
#pragma unroll
            for (int j=0;j<4;j++) s[i][j]=0.f;
        for (int d=0; d<64; d++) {
            float4 qa = *(const float4*)&Qt[d*64 + ty*4];
            float4 kb = *(const float4*)&KP[d*68 + tx*4];
            float qr[4]={qa.x,qa.y,qa.z,qa.w};
            float kr[4]={kb.x,kb.y,kb.z,kb.w};
#pragma unroll
            for (int i=0;i<4;i++)
#pragma unroll
                for (int j=0;j<4;j++) s[i][j] += qr[i]*kr[j];
        }
#pragma unroll
        for (int i=0;i<4;i++)
#pragma unroll
            for (int j=0;j<4;j++) s[i][j] += mk[tx*4+j];

#pragma unroll
        for (int i=0;i<4;i++) {
            float rm = fmaxf(fmaxf(s[i][0],s[i][1]), fmaxf(s[i][2],s[i][3]));
            for (int off=1; off<16; off<<=1)
                rm = fmaxf(rm, __shfl_xor_sync(0xffffffffu, rm, off));
            float nm = fmaxf(m[i], rm);
            float corr = __expf(m[i]-nm);
            m[i] = nm;
            float rs = 0.f;
#pragma unroll
            for (int j=0;j<4;j++) { s[i][j] = __expf(s[i][j]-nm); rs += s[i][j]; }
            for (int off=1; off<16; off<<=1)
                rs += __shfl_xor_sync(0xffffffffu, rs, off);
            l[i] = l[i]*corr + rs;
#pragma unroll
            for (int j=0;j<4;j++) o[i][j] *= corr;
        }

        __syncthreads();
#pragma unroll
        for (int i=0;i<4;i++)
#pragma unroll
            for (int j=0;j<4;j++)
                KP[(tx*4+j)*68 + ty*4 + i] = s[i][j];
        __syncthreads();

        for (int k=0;k<64;k++) {
            float4 p4 = *(const float4*)&KP[k*68 + ty*4];
            float4 v4 = *(const float4*)&Vs[k*68 + tx*4];
            float pr[4]={p4.x,p4.y,p4.z,p4.w};
            float vr[4]={v4.x,v4.y,v4.z,v4.w};
#pragma unroll
            for (int i=0;i<4;i++)
#pragma unroll
                for (int j=0;j<4;j++) o[i][j] += pr[i]*vr[j];
        }
    }

#pragma unroll
    for (int i=0;i<4;i++) {
        float inv = 1.0f / l[i];
        int qrow = q0 + ty*4 + i;
#pragma unroll
        for (int j=0;j<4;j++)
            out[(size_t)(b*Sq + qrow)*Dm + h*64 + tx*4 + j] = to_tf32(o[i][j]*inv);
    }
}

// ---------------------------------------------------------------------------
// Router
// ---------------------------------------------------------------------------
__global__ __launch_bounds__(256) void router_kernel(const float* __restrict__ rw,
                                                     const float* __restrict__ rb,
                                                     const unsigned char* __restrict__ pad)
{
    int n = blockIdx.x, tid = threadIdx.x;
    __shared__ float xs[1024];
    __shared__ float lg[8];
    ((float4*)xs)[tid] = ((const float4*)(g_x2 + (size_t)n*Dm))[tid];
    __syncthreads();
    int w = tid >> 5, lane = tid & 31;
    float acc = 0.f;
    for (int i = lane; i < 1024; i += 32) acc += xs[i] * rw[i*8 + w];
    for (int off=16; off; off>>=1) acc += __shfl_xor_sync(0xffffffffu, acc, off);
    if (lane == 0) lg[w] = acc + rb[w];
    __syncthreads();
    if (tid == 0) {
        float mx = lg[0]; int ei = 0;
        for (int e=1;e<8;e++) if (lg[e] > mx) { mx = lg[e]; ei = e; }
        float pr[8], se = 0.f;
        for (int e=0;e<8;e++) { pr[e] = expf(lg[e]-mx); se += pr[e]; }
        float inv = 1.f/se;
        bool valid = (pad[n] == 0);
        float tm = valid ? 1.f : 0.f;
        for (int e=0;e<8;e++) g_probs[n*8+e] = pr[e]*inv*tm;
        g_gate[n] = pr[ei]*inv;
        g_eidx[n] = ei;
        float lse = mx + logf(se);
        g_zterm[n] = lse*lse*tm;
    }
}

// ---------------------------------------------------------------------------
// Routing scan / dispatch / combine / loss
// ---------------------------------------------------------------------------
__global__ void scan_kernel(const unsigned char* __restrict__ pad)
{
    int lane = threadIdx.x;
    __shared__ int base[8];
    if (lane < 8) base[lane] = 0;
    __syncwarp();
    for (int c = 0; c < Ntok/32; c++) {
        int i = c*32 + lane;
        int e = g_eidx[i];
        bool valid = (pad[i] == 0);
        unsigned peers = __match_any_sync(0xffffffffu, e);
        unsigned vmask = __ballot_sync(0xffffffffu, valid);
        unsigned pv = peers & vmask;
        int myrank = __popc(pv & ((1u << lane) - 1u));
        int b0 = base[e];
        __syncwarp();
        int pos = b0 + myrank;
        bool keep = valid && (pos < CAP);
        g_keep[i] = keep ? 1 : 0;
        int slot = e*CAP + pos;
        g_slot[i] = keep ? slot : 0;
        if (keep) g_tok[slot] = i;
        if (valid && lane == (__ffs(pv) - 1)) base[e] = b0 + __popc(pv);
        __syncwarp();
    }
    if (lane < 8) g_cnt[lane] = base[lane];
}

__global__ __launch_bounds__(256) void init_tok_kernel()
{
    int i = blockIdx.x*256 + threadIdx.x;
    if (i < SLOTS) g_tok[i] = -1;
}

__global__ __launch_bounds__(256) void dispatch_kernel()
{
    int slot = blockIdx.x, tid = threadIdx.x;
    int t = g_tok[slot];
    float4 v = make_float4(0.f,0.f,0.f,0.f);
    if (t >= 0) {
        v = ((const float4*)(g_x2 + (size_t)t*Dm))[tid];
        v.x=to_tf32(v.x); v.y=to_tf32(v.y); v.z=to_tf32(v.z); v.w=to_tf32(v.w);
    }
    ((float4*)(g_disp + (size_t)slot*Dm))[tid] = v;
}

__global__ __launch_bounds__(256) void combine_kernel(float* __restrict__ out)
{
    int n = blockIdx.x, tid = threadIdx.x;
    float4 s = ((const float4*)(g_src1 + (size_t)n*Dm))[tid];
    if (g_keep[n]) {
        float gte = g_gate[n];
        float4 o = ((const float4*)(g_obuf + (size_t)g_slot[n]*Dm))[tid];
        s.x += gte*o.x; s.y += gte*o.y; s.z += gte*o.z; s.w += gte*o.w;
    }
    ((float4*)(out + (size_t)n*Dm))[tid] = s;
}

__global__ __launch_bounds__(256) void loss_kernel(const unsigned char* __restrict__ pad,
                                                   float* __restrict__ out)
{
    int tid = threadIdx.x;
    float zs = 0.f, ps[8];
    int cnt = 0;
#pragma unroll
    for (int e=0;e<8;e++) ps[e]=0.f;
    for (int n = tid; n < Ntok; n += 256) {
        if (pad[n] == 0) cnt++;
        zs += g_zterm[n];
#pragma unroll
        for (int e=0;e<8;e++) ps[e] += g_probs[n*8+e];
    }
    __shared__ float red[256];
    __shared__ float res[10];
    float vals[10];
    vals[0] = (float)cnt; vals[1] = zs;
    for (int e=0;e<8;e++) vals[2+e] = ps[e];
    for (int q=0;q<10;q++) {
        red[tid] = vals[q]; __syncthreads();
        for (int st=128; st; st>>=1) {
            if (tid < st) red[tid] += red[tid+st];
            __syncthreads();
        }
        if (tid == 0) res[q] = red[0];
        __syncthreads();
    }
    if (tid == 0) {
        float denom = fmaxf(res[0], 1.f);
        float lb = 0.f;
        for (int e=0;e<8;e++) lb += ((float)g_cnt[e]/denom) * (res[2+e]/denom);
        lb *= (float)Ee;
        out[(size_t)Ntok*Dm]     = lb;
        out[(size_t)Ntok*Dm + 1] = res[1]/denom;
    }
}

// ---------------------------------------------------------------------------
// Launch
// ---------------------------------------------------------------------------
extern "C" void kernel_launch(void* const* d_in, const int* in_sizes, int n_in,
                              void* d_out, int out_size)
{
    const float* src  = (const float*)d_in[0];
    const unsigned char* pad = (const unsigned char*)d_in[1];
    const float* ln1g = (const float*)d_in[2];
    const float* ln1b = (const float*)d_in[3];
    const float* ipw  = (const float*)d_in[4];
    const float* ipb  = (const float*)d_in[5];
    const float* opw  = (const float*)d_in[6];
    const float* opb  = (const float*)d_in[7];
    const float* ln2g = (const float*)d_in[8];
    const float* ln2b = (const float*)d_in[9];
    const float* rw   = (const float*)d_in[10];
    const float* rb   = (const float*)d_in[11];
    const float* w1   = (const float*)d_in[12];
    const float* b1   = (const float*)d_in[13];
    const float* w2   = (const float*)d_in[14];
    const float* b2   = (const float*)d_in[15];
    float* out = (float*)d_out;

    float *xln, *qkv, *attn, *src1, *x2, *disp, *hb, *ob;
    float *ipw32, *opw32, *w1t, *w2t;
    cudaGetSymbolAddress((void**)&xln,  g_xln);
    cudaGetSymbolAddress((void**)&qkv,  g_qkv);
    cudaGetSymbolAddress((void**)&attn, g_attn);
    cudaGetSymbolAddress((void**)&src1, g_src1);
    cudaGetSymbolAddress((void**)&x2,   g_x2);
    cudaGetSymbolAddress((void**)&disp, g_disp);
    cudaGetSymbolAddress((void**)&hb,   g_hbuf);
    cudaGetSymbolAddress((void**)&ob,   g_obuf);
    cudaGetSymbolAddress((void**)&ipw32, g_ipw32);
    cudaGetSymbolAddress((void**)&opw32, g_opw32);
    cudaGetSymbolAddress((void**)&w1t,  g_w1t);
    cudaGetSymbolAddress((void**)&w2t,  g_w2t);

    cudaFuncSetAttribute(attn_kernel, cudaFuncAttributeMaxDynamicSharedMemorySize, ATTN_SMEM);
    cudaFuncSetAttribute(gemm_mma<false,false,false>, cudaFuncAttributeMaxDynamicSharedMemorySize, GEMM_SMEM);
    cudaFuncSetAttribute(gemm_mma<false,true,false>,  cudaFuncAttributeMaxDynamicSharedMemorySize, GEMM_SMEM);
    cudaFuncSetAttribute(gemm_mma<true,false,true>,   cudaFuncAttributeMaxDynamicSharedMemorySize, GEMM_SMEM);

    // Weight prep
    round_copy<<<(3*Dm*Dm/4 + 255)/256, 256>>>(ipw, ipw32, 3*Dm*Dm/4);
    round_copy<<<(Dm*Dm/4 + 255)/256, 256>>>(opw, opw32, Dm*Dm/4);
    transpose_round<<<dim3(Ff/32, Dm/32, Ee), dim3(32,8)>>>(w1, w1t, Dm, Ff); // [D,F]->[F,D]
    transpose_round<<<dim3(Dm/32, Ff/32, Ee), dim3(32,8)>>>(w2, w2t, Ff, Dm); // [F,D]->[D,F]

    // 1. LN1 (tf32-rounded)
    ln_kernel<true><<<Ntok, 256>>>(src, ln1g, ln1b, xln);
    // 2. QKV
    gemm_mma<false,false,false><<<dim3(3072/BN, Ntok/BM), 256, GEMM_SMEM>>>(
        xln, ipw32, ipb, nullptr, qkv, 3072, 1024, 1<<30, 0, 0);
    // 3. Attention
    attn_kernel<<<dim3(Sq/64, Bc*Hh), 256, ATTN_SMEM>>>(qkv, pad, attn);
    // 4. out_proj + residual(src)
    gemm_mma<false,true,false><<<dim3(1024/BN, Ntok/BM), 256, GEMM_SMEM>>>(
        attn, opw32, opb, src, src1, 1024, 1024, 1<<30, 0, 0);
    // 5. LN2 (clean fp32 for router)
    ln_kernel<false><<<Ntok, 256>>>(src1, ln2g, ln2b, x2);
    // 6. Router + scan + dispatch
    router_kernel<<<Ntok, 256>>>(rw, rb, pad);
    init_tok_kernel<<<(SLOTS+255)/256, 256>>>();
    scan_kernel<<<1, 32>>>(pad);
    dispatch_kernel<<<SLOTS, 256>>>();
    // 7. FFN1 (relu, rounded -> feeds FFN2 A)
    gemm_mma<true,false,true><<<dim3(Ff/BN, SLOTS/BM), 256, GEMM_SMEM>>>(
        disp, w1t, b1, nullptr, hb, Ff, 1024, CAP, (long long)Dm*Ff, Ff);
    // 8. FFN2
    gemm_mma<false,false,false><<<dim3(Dm/BN, SLOTS/BM), 256, GEMM_SMEM>>>(
        hb, w2t, b2, nullptr, ob, Dm, Ff, CAP, (long long)Ff*Dm, Dm);
    // 9. Combine + losses
    combine_kernel<<<Ntok, 256>>>(out);
    loss_kernel<<<1, 256>>>(pad, out);
}

// round 4
// speedup vs baseline: 3.3416x; 1.8097x over previous
#include <cuda_runtime.h>
#include <cuda_bf16.h>
#include <math.h>
#include <stdint.h>

// ---------------------------------------------------------------------------
// Problem constants
// ---------------------------------------------------------------------------
#define Bc   4
#define Sq   2048
#define Dm   1024
#define Hh   16
#define Ee   8
#define Ff   4096
#define Ntok (Bc*Sq)          // 8192
#define CAP  1280
#define SLOTS (Ee*CAP)        // 10240

typedef __nv_bfloat16 bf16;
typedef __nv_bfloat162 bf162;

// ---------------------------------------------------------------------------
// Device scratch
// ---------------------------------------------------------------------------
__device__ bf16  g_xln [Ntok*Dm];
__device__ bf16  g_qkv [Ntok*3*Dm];
__device__ bf16  g_attn[Ntok*Dm];
__device__ float g_src1[Ntok*Dm];
__device__ float g_x2  [Ntok*Dm];
__device__ bf16  g_disp[SLOTS*Dm];
__device__ bf16  g_hbuf[(size_t)SLOTS*Ff];
__device__ float g_obuf[SLOTS*Dm];
__device__ float g_probs[Ntok*Ee];
__device__ float g_zterm[Ntok];
__device__ float g_gate [Ntok];
__device__ int   g_eidx [Ntok];
__device__ int   g_keep [Ntok];
__device__ int   g_slot [Ntok];
__device__ int   g_tok  [SLOTS];
__device__ int   g_cnt  [Ee];
// bf16 weight copies / transposes ([N,K] layouts)
__device__ bf16 g_ipw16[3*Dm*Dm];
__device__ bf16 g_opw16[Dm*Dm];
__device__ bf16 g_w1t [(size_t)Ee*Ff*Dm];   // [E][F][D]
__device__ bf16 g_w2t [(size_t)Ee*Dm*Ff];   // [E][D][F]

// ---------------------------------------------------------------------------
// Helpers
// ---------------------------------------------------------------------------
__device__ __forceinline__ uint32_t smem_u32(const void* p) {
    uint32_t a;
    asm("{ .reg .u64 t; cvta.to.shared.u64 t, %1; cvt.u32.u64 %0, t; }"
        : "=r"(a) : "l"(p));
    return a;
}
__device__ __forceinline__ void cp16(uint32_t dst, const void* src) {
    asm volatile("cp.async.cg.shared.global [%0], [%1], 16;" :: "r"(dst), "l"(src));
}
__device__ __forceinline__ void ldm_x4(uint32_t* r, uint32_t addr) {
    asm volatile("ldmatrix.sync.aligned.m8n8.x4.shared.b16 {%0,%1,%2,%3}, [%4];"
        : "=r"(r[0]), "=r"(r[1]), "=r"(r[2]), "=r"(r[3]) : "r"(addr));
}
__device__ __forceinline__ void ldm_x4t(uint32_t* r, uint32_t addr) {
    asm volatile("ldmatrix.sync.aligned.m8n8.x4.trans.shared.b16 {%0,%1,%2,%3}, [%4];"
        : "=r"(r[0]), "=r"(r[1]), "=r"(r[2]), "=r"(r[3]) : "r"(addr));
}
__device__ __forceinline__ void mma_bf16(float* d, const uint32_t* a,
                                         uint32_t b0, uint32_t b1) {
    asm volatile(
        "mma.sync.aligned.m16n8k16.row.col.f32.bf16.bf16.f32 "
        "{%0,%1,%2,%3}, {%4,%5,%6,%7}, {%8,%9}, {%0,%1,%2,%3};"
        : "+f"(d[0]), "+f"(d[1]), "+f"(d[2]), "+f"(d[3])
        : "r"(a[0]), "r"(a[1]), "r"(a[2]), "r"(a[3]), "r"(b0), "r"(b1));
}
__device__ __forceinline__ uint32_t pack_bf(float lo, float hi) {
    bf162 v = __float22bfloat162_rn(make_float2(lo, hi));
    return *(uint32_t*)&v;
}
// fast exp via exp2 polynomial on the FMA pipe (MUFU is slow on B300)
__device__ __forceinline__ float expp(float x) {
    float y = fmaxf(x * 1.4426950408889634f, -120.f);
    float t = y + 12582912.f;               // round-to-nearest via magic
    int   e = __float_as_int(t);
    float r = t - 12582912.f;
    float f = y - r;                        // f in [-0.5, 0.5]
    float p = 1.3333558146e-3f;
    p = fmaf(p, f, 9.6181291076e-3f);
    p = fmaf(p, f, 5.5504108664e-2f);
    p = fmaf(p, f, 2.4022650696e-1f);
    p = fmaf(p, f, 6.9314718056e-1f);
    p = fmaf(p, f, 1.0f);
    float sc = __int_as_float((e - 0x4b400000 + 127) << 23);
    return p * sc;
}

// output store helpers
__device__ __forceinline__ void store_pair(float* C, size_t off, float v0, float v1) {
    *(float2*)(C + off) = make_float2(v0, v1);
}
__device__ __forceinline__ void store_pair(bf16* C, size_t off, float v0, float v1) {
    *(bf162*)(C + off) = __float22bfloat162_rn(make_float2(v0, v1));
}

// ---------------------------------------------------------------------------
// bf16 mma GEMM: C[M,N] = A[M,K] @ B[N,K]^T (+bias, relu, residual)
// 128x128 tile, 32-half k-chunk, 3-stage cp.async, 8 warps (2m x 4n).
// smem rows: 64B data + 16B pad = 80B (conflict-free ldmatrix).
// ---------------------------------------------------------------------------
#define BM 128
#define BN 128
#define STAGE_B (BM*80 + BN*80)     // 20480 bytes
#define GEMM_SMEM (3*STAGE_B)       // 61440

template<typename TO, bool RELU, bool RES>
__global__ __launch_bounds__(256, 2) void gemm_mma(
    const bf16* __restrict__ A, const bf16* __restrict__ Bm,
    const float* __restrict__ bias, const float* __restrict__ Res,
    TO* __restrict__ C, int Nld, int K,
    int rowsPerExpert, long long bExpStride, int biasExpStride)
{
    extern __shared__ char smem[];
    const uint32_t sb0 = smem_u32(smem);
    const int tid = threadIdx.x;
    const int wid = tid >> 5, lane = tid & 31;
    const int j8 = lane & 7, gi = lane >> 3;
    const int lr = lane >> 2, lc = lane & 3;
    const int row0 = blockIdx.y * BM, col0 = blockIdx.x * BN;
    const int expert = row0 / rowsPerExpert;
    const bf16* Bexp = Bm + (long long)expert * bExpStride;
    const float* bb  = bias + (long long)expert * biasExpStride;
    const int m0 = (wid & 1) * 64, n0 = (wid >> 1) * 32;

    const bf16* Abase = A + (size_t)row0 * K;
    const bf16* Bbase = Bexp + (size_t)col0 * K;

    const int arow = j8 + (gi & 1) * 8;       // A frag addressing
    const int aoff = (gi >> 1) * 16;
    const int brow = j8 + (gi >> 1) * 8;      // B frag addressing
    const int boff = (gi & 1) * 16;

    float acc[16][4];
#pragma unroll
    for (int t = 0; t < 16; t++)
#pragma unroll
        for (int q = 0; q < 4; q++) acc[t][q] = 0.f;

    const int nch = K / 32;                   // 32 halves per chunk

    auto load_stage = [&](int s, int ch) {
        const uint32_t sa  = sb0 + (uint32_t)s * STAGE_B;
        const uint32_t sbm = sa + BM * 80;
        const bf16* Ac = Abase + ch * 32;
        const bf16* Bcp = Bbase + ch * 32;
#pragma unroll
        for (int q = 0; q < 2; q++) {
            int seg = tid * 2 + q;            // 0..511
            int r = seg >> 2, c = seg & 3;
            cp16(sa  + (uint32_t)(r * 80 + c * 16), Ac  + (size_t)r * K + c * 8);
            cp16(sbm + (uint32_t)(r * 80 + c * 16), Bcp + (size_t)r * K + c * 8);
        }
    };

    load_stage(0, 0);
    asm volatile("cp.async.commit_group;");
    load_stage(1, 1);
    asm volatile("cp.async.commit_group;");

    for (int i = 0; i < nch; i++) {
        if (i + 2 < nch) load_stage((i + 2) % 3, i + 2);
        asm volatile("cp.async.commit_group;");
        asm volatile("cp.async.wait_group 2;");
        __syncthreads();

        const uint32_t sa  = sb0 + (uint32_t)(i % 3) * STAGE_B;
        const uint32_t sbm = sa + BM * 80;
#pragma unroll
        for (int kk = 0; kk < 2; kk++) {
            uint32_t af[4][4];
#pragma unroll
            for (int mt = 0; mt < 4; mt++)
                ldm_x4(af[mt], sa + (uint32_t)((m0 + mt * 16 + arow) * 80 + aoff + kk * 32));
#pragma unroll
            for (int pr = 0; pr < 2; pr++) {
                uint32_t bfr[4];
                ldm_x4(bfr, sbm + (uint32_t)((n0 + pr * 16 + brow) * 80 + boff + kk * 32));
#pragma unroll
                for (int mt = 0; mt < 4; mt++) {
                    mma_bf16(acc[mt * 4 + pr * 2 + 0], af[mt], bfr[0], bfr[1]);
                    mma_bf16(acc[mt * 4 + pr * 2 + 1], af[mt], bfr[2], bfr[3]);
                }
            }
        }
        __syncthreads();
    }

    // epilogue
#pragma unroll
    for (int mt = 0; mt < 4; mt++) {
        const int gr = row0 + m0 + mt * 16 + lr;
#pragma unroll
        for (int tj = 0; tj < 4; tj++) {
            const int gc = col0 + n0 + tj * 8 + lc * 2;
            float* d = acc[mt * 4 + tj];
            float b0 = bb[gc], b1 = bb[gc + 1];
            float v0 = d[0] + b0, v1 = d[1] + b1;
            float v2 = d[2] + b0, v3 = d[3] + b1;
            if (RELU) {
                v0 = fmaxf(v0, 0.f); v1 = fmaxf(v1, 0.f);
                v2 = fmaxf(v2, 0.f); v3 = fmaxf(v3, 0.f);
            }
            if (RES) {
                float2 r0 = *(const float2*)(Res + (size_t)gr * Nld + gc);
                float2 r1 = *(const float2*)(Res + (size_t)(gr + 8) * Nld + gc);
                v0 += r0.x; v1 += r0.y; v2 += r1.x; v3 += r1.y;
            }
            store_pair(C, (size_t)gr * Nld + gc, v0, v1);
            store_pair(C, (size_t)(gr + 8) * Nld + gc, v2, v3);
        }
    }
}

// ---------------------------------------------------------------------------
// Flash attention, bf16 mma. 128 threads (4 warps), q-tile 64, k-tiles of 64.
// smem: Q 64x144B, K/V double-buffered 64x144B each, masks 2x64 floats.
// ---------------------------------------------------------------------------
#define AT_SMEM (9216*5 + 512)

__global__ __launch_bounds__(128) void attn_mma(
    const bf16* __restrict__ qkv,
    const unsigned char* __restrict__ pad,
    bf16* __restrict__ outp)
{
    extern __shared__ char smem[];
    const uint32_t sQ  = smem_u32(smem);
    const uint32_t sK0 = sQ + 9216;
    const uint32_t sV0 = sQ + 9216 * 3;
    float* mkp = (float*)(smem + 9216 * 5);

    const int tid = threadIdx.x;
    const int wid = tid >> 5, lane = tid & 31;
    const int j8 = lane & 7, gi = lane >> 3;
    const int lc = lane & 3, lr = lane >> 2;
    const int bh = blockIdx.y, b = bh >> 4, h = bh & 15;
    const int q0 = blockIdx.x * 64;
    const size_t tokBase = (size_t)b * Sq;

    // Q load (group 0)
    {
        const bf16* qb = qkv + (tokBase + q0) * 3072 + h * 64;
#pragma unroll
        for (int q = 0; q < 4; q++) {
            int seg = tid + 128 * q;
            int r = seg >> 3, c = seg & 7;
            cp16(sQ + (uint32_t)(r * 144 + c * 16), qb + (size_t)r * 3072 + c * 8);
        }
    }
    asm volatile("cp.async.commit_group;");

    auto prefetch = [&](int st, int kt) {
        const int k0 = kt * 64;
        const bf16* kb = qkv + (tokBase + k0) * 3072 + 1024 + h * 64;
        const bf16* vb = qkv + (tokBase + k0) * 3072 + 2048 + h * 64;
        const uint32_t sk = sK0 + (uint32_t)st * 9216, sv = sV0 + (uint32_t)st * 9216;
#pragma unroll
        for (int q = 0; q < 4; q++) {
            int seg = tid + 128 * q;
            int r = seg >> 3, c = seg & 7;
            cp16(sk + (uint32_t)(r * 144 + c * 16), kb + (size_t)r * 3072 + c * 8);
            cp16(sv + (uint32_t)(r * 144 + c * 16), vb + (size_t)r * 3072 + c * 8);
        }
        if (tid < 64) mkp[st * 64 + tid] = pad[tokBase + k0 + tid] ? -1e9f : 0.f;
    };

    prefetch(0, 0);
    asm volatile("cp.async.commit_group;");
    asm volatile("cp.async.wait_group 1;");   // Q ready
    __syncthreads();

    const int arow = j8 + (gi & 1) * 8, aoff = (gi >> 1) * 16;  // A / V-trans rows
    const int brow = j8 + (gi >> 1) * 8, boff = (gi & 1) * 16;  // B (K) rows

    uint32_t qa[4][4];
#pragma unroll
    for (int kd = 0; kd < 4; kd++)
        ldm_x4(qa[kd], sQ + (uint32_t)((wid * 16 + arow) * 144 + kd * 32 + aoff));

    float m0v = -1e30f, m1v = -1e30f, l0 = 0.f, l1 = 0.f;
    float o[8][4];
#pragma unroll
    for (int dt = 0; dt < 8; dt++)
#pragma unroll
        for (int q = 0; q < 4; q++) o[dt][q] = 0.f;

    for (int kt = 0; kt < Sq / 64; kt++) {
        const int st = kt & 1;
        if (kt + 1 < Sq / 64) prefetch(st ^ 1, kt + 1);
        asm volatile("cp.async.commit_group;");
        asm volatile("cp.async.wait_group 1;");
        __syncthreads();

        const uint32_t sk = sK0 + (uint32_t)st * 9216, sv = sV0 + (uint32_t)st * 9216;
        float s[8][4];
#pragma unroll
        for (int j = 0; j < 8; j++)
#pragma unroll
            for (int q = 0; q < 4; q++) s[j][q] = 0.f;

#pragma unroll
        for (int jp = 0; jp < 4; jp++) {
#pragma unroll
            for (int kd = 0; kd < 4; kd++) {
                uint32_t bfr[4];
                ldm_x4(bfr, sk + (uint32_t)((jp * 16 + brow) * 144 + kd * 32 + boff));
                mma_bf16(s[2 * jp],     qa[kd], bfr[0], bfr[1]);
                mma_bf16(s[2 * jp + 1], qa[kd], bfr[2], bfr[3]);
            }
        }

        // scale + mask + row max
        float rmax0 = -1e30f, rmax1 = -1e30f;
#pragma unroll
        for (int j = 0; j < 8; j++) {
            float mka = mkp[st * 64 + j * 8 + 2 * lc];
            float mkb = mkp[st * 64 + j * 8 + 2 * lc + 1];
            s[j][0] = fmaf(s[j][0], 0.125f, mka);
            s[j][1] = fmaf(s[j][1], 0.125f, mkb);
            s[j][2] = fmaf(s[j][2], 0.125f, mka);
            s[j][3] = fmaf(s[j][3], 0.125f, mkb);
            rmax0 = fmaxf(rmax0, fmaxf(s[j][0], s[j][1]));
            rmax1 = fmaxf(rmax1, fmaxf(s[j][2], s[j][3]));
        }
        rmax0 = fmaxf(rmax0, __shfl_xor_sync(0xffffffffu, rmax0, 1));
        rmax0 = fmaxf(rmax0, __shfl_xor_sync(0xffffffffu, rmax0, 2));
        rmax1 = fmaxf(rmax1, __shfl_xor_sync(0xffffffffu, rmax1, 1));
        rmax1 = fmaxf(rmax1, __shfl_xor_sync(0xffffffffu, rmax1, 2));
        float nm0 = fmaxf(m0v, rmax0), nm1 = fmaxf(m1v, rmax1);
        float c0 = expp(m0v - nm0), c1 = expp(m1v - nm1);
        m0v = nm0; m1v = nm1;
        float rs0 = 0.f, rs1 = 0.f;
#pragma unroll
        for (int j = 0; j < 8; j++) {
            s[j][0] = expp(s[j][0] - nm0); s[j][1] = expp(s[j][1] - nm0);
            s[j][2] = expp(s[j][2] - nm1); s[j][3] = expp(s[j][3] - nm1);
            rs0 += s[j][0] + s[j][1];
            rs1 += s[j][2] + s[j][3];
        }
        rs0 += __shfl_xor_sync(0xffffffffu, rs0, 1);
        rs0 += __shfl_xor_sync(0xffffffffu, rs0, 2);
        rs1 += __shfl_xor_sync(0xffffffffu, rs1, 1);
        rs1 += __shfl_xor_sync(0xffffffffu, rs1, 2);
        l0 = l0 * c0 + rs0; l1 = l1 * c1 + rs1;
#pragma unroll
        for (int dt = 0; dt < 8; dt++) {
            o[dt][0] *= c0; o[dt][1] *= c0; o[dt][2] *= c1; o[dt][3] *= c1;
        }

        // pack P into A-frags (C-layout maps directly)
        uint32_t pa[4][4];
#pragma unroll
        for (int t = 0; t < 4; t++) {
            pa[t][0] = pack_bf(s[2 * t][0],     s[2 * t][1]);
            pa[t][1] = pack_bf(s[2 * t][2],     s[2 * t][3]);
            pa[t][2] = pack_bf(s[2 * t + 1][0], s[2 * t + 1][1]);
            pa[t][3] = pack_bf(s[2 * t + 1][2], s[2 * t + 1][3]);
        }
        // P @ V
#pragma unroll
        for (int t = 0; t < 4; t++) {
#pragma unroll
            for (int dp = 0; dp < 4; dp++) {
                uint32_t vf[4];
                ldm_x4t(vf, sv + (uint32_t)((t * 16 + arow) * 144 + dp * 32 + aoff));
                mma_bf16(o[2 * dp],     pa[t], vf[0], vf[1]);
                mma_bf16(o[2 * dp + 1], pa[t], vf[2], vf[3]);
            }
        }
        __syncthreads();
    }

    float inv0 = 1.f / l0, inv1 = 1.f / l1;
    const int rg = q0 + wid * 16 + lr;
    bf16* ob = outp + (tokBase + rg) * Dm + h * 64;
#pragma unroll
    for (int dt = 0; dt < 8; dt++) {
        *(bf162*)(ob + dt * 8 + 2 * lc) =
            __float22bfloat162_rn(make_float2(o[dt][0] * inv0, o[dt][1] * inv0));
        *(bf162*)(ob + (size_t)8 * Dm + dt * 8 + 2 * lc) =
            __float22bfloat162_rn(make_float2(o[dt][2] * inv1, o[dt][3] * inv1));
    }
}

// ---------------------------------------------------------------------------
// LayerNorm (templated output type)
// ---------------------------------------------------------------------------
template<typename TO>
__global__ __launch_bounds__(256) void ln_kernel(const float* __restrict__ in,
                                                 const float* __restrict__ g,
                                                 const float* __restrict__ b,
                                                 TO* __restrict__ out)
{
    int n = blockIdx.x, tid = threadIdx.x;
    float4 v = ((const float4*)(in + (size_t)n*Dm))[tid];
    float s  = v.x+v.y+v.z+v.w;
    float s2 = v.x*v.x+v.y*v.y+v.z*v.z+v.w*v.w;
    __shared__ float r1[256], r2[256];
    r1[tid]=s; r2[tid]=s2; __syncthreads();
    for (int st=128; st; st>>=1) {
        if (tid<st) { r1[tid]+=r1[tid+st]; r2[tid]+=r2[tid+st]; }
        __syncthreads();
    }
    float mean = r1[0]*(1.0f/Dm);
    float var  = r2[0]*(1.0f/Dm) - mean*mean;
    float rstd = rsqrtf(var + 1e-5f);
    float4 gg = ((const float4*)g)[tid];
    float4 bb = ((const float4*)b)[tid];
    float o0 = (v.x-mean)*rstd*gg.x + bb.x;
    float o1 = (v.y-mean)*rstd*gg.y + bb.y;
    float o2 = (v.z-mean)*rstd*gg.z + bb.z;
    float o3 = (v.w-mean)*rstd*gg.w + bb.w;
    size_t base = (size_t)n*Dm + tid*4;
    store_pair(out, base, o0, o1);
    store_pair(out, base + 2, o2, o3);
}

// ---------------------------------------------------------------------------
// Weight prep
// ---------------------------------------------------------------------------
__global__ __launch_bounds__(256) void bf16_copy(const float* __restrict__ in,
                                                 bf16* __restrict__ out, int n4)
{
    int i = blockIdx.x*256 + threadIdx.x;
    if (i < n4) {
        float4 v = ((const float4*)in)[i];
        ((bf162*)out)[i*2]   = __float22bfloat162_rn(make_float2(v.x, v.y));
        ((bf162*)out)[i*2+1] = __float22bfloat162_rn(make_float2(v.z, v.w));
    }
}

__global__ __launch_bounds__(256) void transpose_bf16(const float* __restrict__ in,
                                                      bf16* __restrict__ out,
                                                      int R, int Cc)
{
    __shared__ float t[32][33];
    int e = blockIdx.z;
    const float* ip = in  + (size_t)e*R*Cc;
    bf16* op        = out + (size_t)e*R*Cc;
    int c0 = blockIdx.x*32, r0 = blockIdx.y*32;
    int tx = threadIdx.x, ty = threadIdx.y;
#pragma unroll
    for (int j=0;j<32;j+=8)
        t[ty+j][tx] = ip[(size_t)(r0+ty+j)*Cc + c0+tx];
    __syncthreads();
#pragma unroll
    for (int j=0;j<32;j+=8)
        op[(size_t)(c0+ty+j)*R + r0+tx] = __float2bfloat16_rn(t[tx][ty+j]);
}

// ---------------------------------------------------------------------------
// Router (fp32)
// ---------------------------------------------------------------------------
__global__ __launch_bounds__(256) void router_kernel(const float* __restrict__ rw,
                                                     const float* __restrict__ rb,
                                                     const unsigned char* __restrict__ pad)
{
    int n = blockIdx.x, tid = threadIdx.x;
    __shared__ float xs[1024];
    __shared__ float lg[8];
    ((float4*)xs)[tid] = ((const float4*)(g_x2 + (size_t)n*Dm))[tid];
    __syncthreads();
    int w = tid >> 5, lane = tid & 31;
    float acc = 0.f;
    for (int i = lane; i < 1024; i += 32) acc += xs[i] * rw[i*8 + w];
    for (int off=16; off; off>>=1) acc += __shfl_xor_sync(0xffffffffu, acc, off);
    if (lane == 0) lg[w] = acc + rb[w];
    __syncthreads();
    if (tid == 0) {
        float mx = lg[0]; int ei = 0;
        for (int e=1;e<8;e++) if (lg[e] > mx) { mx = lg[e]; ei = e; }
        float pr[8], se = 0.f;
        for (int e=0;e<8;e++) { pr[e] = expf(lg[e]-mx); se += pr[e]; }
        float inv = 1.f/se;
        bool valid = (pad[n] == 0);
        float tm = valid ? 1.f : 0.f;
        for (int e=0;e<8;e++) g_probs[n*8+e] = pr[e]*inv*tm;
        g_gate[n] = pr[ei]*inv;
        g_eidx[n] = ei;
        float lse = mx + logf(se);
        g_zterm[n] = lse*lse*tm;
    }
}

// ---------------------------------------------------------------------------
// Routing scan / dispatch / combine / loss
// ---------------------------------------------------------------------------
__global__ void scan_kernel(const unsigned char* __restrict__ pad)
{
    int lane = threadIdx.x;
    __shared__ int base[8];
    if (lane < 8) base[lane] = 0;
    __syncwarp();
    for (int c = 0; c < Ntok/32; c++) {
        int i = c*32 + lane;
        int e = g_eidx[i];
        bool valid = (pad[i] == 0);
        unsigned peers = __match_any_sync(0xffffffffu, e);
        unsigned vmask = __ballot_sync(0xffffffffu, valid);
        unsigned pv = peers & vmask;
        int myrank = __popc(pv & ((1u << lane) - 1u));
        int b0 = base[e];
        __syncwarp();
        int pos = b0 + myrank;
        bool keep = valid && (pos < CAP);
        g_keep[i] = keep ? 1 : 0;
        int slot = e*CAP + pos;
        g_slot[i] = keep ? slot : 0;
        if (keep) g_tok[slot] = i;
        if (valid && lane == (__ffs(pv) - 1)) base[e] = b0 + __popc(pv);
        __syncwarp();
    }
    if (lane < 8) g_cnt[lane] = base[lane];
}

__global__ __launch_bounds__(256) void init_tok_kernel()
{
    int i = blockIdx.x*256 + threadIdx.x;
    if (i < SLOTS) g_tok[i] = -1;
}

__global__ __launch_bounds__(256) void dispatch_kernel()
{
    int slot = blockIdx.x, tid = threadIdx.x;
    int t = g_tok[slot];
    float4 v = make_float4(0.f,0.f,0.f,0.f);
    if (t >= 0) v = ((const float4*)(g_x2 + (size_t)t*Dm))[tid];
    bf162* dp = (bf162*)(g_disp + (size_t)slot*Dm);
    dp[tid*2]   = __float22bfloat162_rn(make_float2(v.x, v.y));
    dp[tid*2+1] = __float22bfloat162_rn(make_float2(v.z, v.w));
}

__global__ __launch_bounds__(256) void combine_kernel(float* __restrict__ out)
{
    int n = blockIdx.x, tid = threadIdx.x;
    float4 s = ((const float4*)(g_src1 + (size_t)n*Dm))[tid];
    if (g_keep[n]) {
        float gte = g_gate[n];
        float4 o = ((const float4*)(g_obuf + (size_t)g_slot[n]*Dm))[tid];
        s.x += gte*o.x; s.y += gte*o.y; s.z += gte*o.z; s.w += gte*o.w;
    }
    ((float4*)(out + (size_t)n*Dm))[tid] = s;
}

__global__ __launch_bounds__(256) void loss_kernel(const unsigned char* __restrict__ pad,
                                                   float* __restrict__ out)
{
    int tid = threadIdx.x;
    float zs = 0.f, ps[8];
    int cnt = 0;
#pragma unroll
    for (int e=0;e<8;e++) ps[e]=0.f;
    for (int n = tid; n < Ntok; n += 256) {
        if (pad[n] == 0) cnt++;
        zs += g_zterm[n];
#pragma unroll
        for (int e=0;e<8;e++) ps[e] += g_probs[n*8+e];
    }
    __shared__ float red[256];
    __shared__ float res[10];
    float vals[10];
    vals[0] = (float)cnt; vals[1] = zs;
    for (int e=0;e<8;e++) vals[2+e] = ps[e];
    for (int q=0;q<10;q++) {
        red[tid] = vals[q]; __syncthreads();
        for (int st=128; st; st>>=1) {
            if (tid < st) red[tid] += red[tid+st];
            __syncthreads();
        }
        if (tid == 0) res[q] = red[0];
        __syncthreads();
    }
    if (tid == 0) {
        float denom = fmaxf(res[0], 1.f);
        float lb = 0.f;
        for (int e=0;e<8;e++) lb += ((float)g_cnt[e]/denom) * (res[2+e]/denom);
        lb *= (float)Ee;
        out[(size_t)Ntok*Dm]     = lb;
        out[(size_t)Ntok*Dm + 1] = res[1]/denom;
    }
}

// ---------------------------------------------------------------------------
// Launch
// ---------------------------------------------------------------------------
extern "C" void kernel_launch(void* const* d_in, const int* in_sizes, int n_in,
                              void* d_out, int out_size)
{
    const float* src  = (const float*)d_in[0];
    const unsigned char* pad = (const unsigned char*)d_in[1];
    const float* ln1g = (const float*)d_in[2];
    const float* ln1b = (const float*)d_in[3];
    const float* ipw  = (const float*)d_in[4];
    const float* ipb  = (const float*)d_in[5];
    const float* opw  = (const float*)d_in[6];
    const float* opb  = (const float*)d_in[7];
    const float* ln2g = (const float*)d_in[8];
    const float* ln2b = (const float*)d_in[9];
    const float* rw   = (const float*)d_in[10];
    const float* rb   = (const float*)d_in[11];
    const float* w1   = (const float*)d_in[12];
    const float* b1   = (const float*)d_in[13];
    const float* w2   = (const float*)d_in[14];
    const float* b2   = (const float*)d_in[15];
    float* out = (float*)d_out;

    bf16 *xln, *qkv, *attn, *disp, *hb, *ipw16, *opw16, *w1t, *w2t;
    float *src1, *x2, *ob;
    cudaGetSymbolAddress((void**)&xln,  g_xln);
    cudaGetSymbolAddress((void**)&qkv,  g_qkv);
    cudaGetSymbolAddress((void**)&attn, g_attn);
    cudaGetSymbolAddress((void**)&src1, g_src1);
    cudaGetSymbolAddress((void**)&x2,   g_x2);
    cudaGetSymbolAddress((void**)&disp, g_disp);
    cudaGetSymbolAddress((void**)&hb,   g_hbuf);
    cudaGetSymbolAddress((void**)&ob,   g_obuf);
    cudaGetSymbolAddress((void**)&ipw16, g_ipw16);
    cudaGetSymbolAddress((void**)&opw16, g_opw16);
    cudaGetSymbolAddress((void**)&w1t,  g_w1t);
    cudaGetSymbolAddress((void**)&w2t,  g_w2t);

    cudaFuncSetAttribute(attn_mma, cudaFuncAttributeMaxDynamicSharedMemorySize, AT_SMEM);
    cudaFuncSetAttribute(gemm_mma<bf16,false,false>, cudaFuncAttributeMaxDynamicSharedMemorySize, GEMM_SMEM);
    cudaFuncSetAttribute(gemm_mma<float,false,true>, cudaFuncAttributeMaxDynamicSharedMemorySize, GEMM_SMEM);
    cudaFuncSetAttribute(gemm_mma<bf16,true,false>,  cudaFuncAttributeMaxDynamicSharedMemorySize, GEMM_SMEM);
    cudaFuncSetAttribute(gemm_mma<float,false,false>,cudaFuncAttributeMaxDynamicSharedMemorySize, GEMM_SMEM);

    // Weight prep
    bf16_copy<<<(3*Dm*Dm/4 + 255)/256, 256>>>(ipw, ipw16, 3*Dm*Dm/4);
    bf16_copy<<<(Dm*Dm/4 + 255)/256, 256>>>(opw, opw16, Dm*Dm/4);
    transpose_bf16<<<dim3(Ff/32, Dm/32, Ee), dim3(32,8)>>>(w1, w1t, Dm, Ff); // [D,F]->[F,D]
    transpose_bf16<<<dim3(Dm/32, Ff/32, Ee), dim3(32,8)>>>(w2, w2t, Ff, Dm); // [F,D]->[D,F]

    // 1. LN1 -> bf16
    ln_kernel<bf16><<<Ntok, 256>>>(src, ln1g, ln1b, xln);
    // 2. QKV -> bf16
    gemm_mma<bf16,false,false><<<dim3(3072/BN, Ntok/BM), 256, GEMM_SMEM>>>(
        xln, ipw16, ipb, nullptr, qkv, 3072, 1024, 1<<30, 0, 0);
    // 3. Attention -> bf16
    attn_mma<<<dim3(Sq/64, Bc*Hh), 128, AT_SMEM>>>(qkv, pad, attn);
    // 4. out_proj + residual(src) -> fp32
    gemm_mma<float,false,true><<<dim3(1024/BN, Ntok/BM), 256, GEMM_SMEM>>>(
        attn, opw16, opb, src, src1, 1024, 1024, 1<<30, 0, 0);
    // 5. LN2 -> fp32 (router needs clean fp32)
    ln_kernel<float><<<Ntok, 256>>>(src1, ln2g, ln2b, x2);
    // 6. Router + scan + dispatch
    router_kernel<<<Ntok, 256>>>(rw, rb, pad);
    init_tok_kernel<<<(SLOTS+255)/256, 256>>>();
    scan_kernel<<<1, 32>>>(pad);
    dispatch_kernel<<<SLOTS, 256>>>();
    // 7. FFN1 (relu) -> bf16
    gemm_mma<bf16,true,false><<<dim3(Ff/BN, SLOTS/BM), 256, GEMM_SMEM>>>(
        disp, w1t, b1, nullptr, hb, Ff, 1024, CAP, (long long)Dm*Ff, Ff);
    // 8. FFN2 -> fp32
    gemm_mma<float,false,false><<<dim3(Dm/BN, SLOTS/BM), 256, GEMM_SMEM>>>(
        hb, w2t, b2, nullptr, ob, Dm, Ff, CAP, (long long)Ff*Dm, Dm);
    // 9. Combine + losses
    combine_kernel<<<Ntok, 256>>>(out);
    loss_kernel<<<1, 256>>>(pad, out);
}

// round 5
// speedup vs baseline: 4.3823x; 1.3114x over previous
#include <cuda_runtime.h>
#include <cuda_bf16.h>
#include <math.h>
#include <stdint.h>

// ---------------------------------------------------------------------------
// Problem constants
// ---------------------------------------------------------------------------
#define Bc   4
#define Sq   2048
#define Dm   1024
#define Hh   16
#define Ee   8
#define Ff   4096
#define Ntok (Bc*Sq)          // 8192
#define CAP  1280
#define SLOTS (Ee*CAP)        // 10240

typedef __nv_bfloat16 bf16;
typedef __nv_bfloat162 bf162;

// ---------------------------------------------------------------------------
// Device scratch
// ---------------------------------------------------------------------------
__device__ bf16  g_xln [Ntok*Dm];
__device__ bf16  g_qkv [Ntok*3*Dm];
__device__ bf16  g_attn[Ntok*Dm];
__device__ float g_src1[Ntok*Dm];
__device__ float g_x2  [Ntok*Dm];
__device__ bf16  g_disp[SLOTS*Dm];
__device__ bf16  g_hbuf[(size_t)SLOTS*Ff];
__device__ float g_obuf[SLOTS*Dm];
__device__ float g_probs[Ntok*Ee];
__device__ float g_zterm[Ntok];
__device__ float g_gate [Ntok];
__device__ int   g_eidx [Ntok];
__device__ int   g_keep [Ntok];
__device__ int   g_slot [Ntok];
__device__ int   g_tok  [SLOTS];
__device__ int   g_cnt  [Ee];
// bf16 weight copies / transposes ([N,K] layouts)
__device__ bf16 g_ipw16[3*Dm*Dm];
__device__ bf16 g_opw16[Dm*Dm];
__device__ bf16 g_w1t [(size_t)Ee*Ff*Dm];   // [E][F][D]
__device__ bf16 g_w2t [(size_t)Ee*Dm*Ff];   // [E][D][F]

// ---------------------------------------------------------------------------
// Helpers
// ---------------------------------------------------------------------------
__device__ __forceinline__ uint32_t smem_u32(const void* p) {
    uint32_t a;
    asm("{ .reg .u64 t; cvta.to.shared.u64 t, %1; cvt.u32.u64 %0, t; }"
        : "=r"(a) : "l"(p));
    return a;
}
__device__ __forceinline__ void cp16(uint32_t dst, const void* src) {
    asm volatile("cp.async.cg.shared.global [%0], [%1], 16;" :: "r"(dst), "l"(src));
}
__device__ __forceinline__ void ldm_x4(uint32_t* r, uint32_t addr) {
    asm volatile("ldmatrix.sync.aligned.m8n8.x4.shared.b16 {%0,%1,%2,%3}, [%4];"
        : "=r"(r[0]), "=r"(r[1]), "=r"(r[2]), "=r"(r[3]) : "r"(addr));
}
__device__ __forceinline__ void ldm_x4t(uint32_t* r, uint32_t addr) {
    asm volatile("ldmatrix.sync.aligned.m8n8.x4.trans.shared.b16 {%0,%1,%2,%3}, [%4];"
        : "=r"(r[0]), "=r"(r[1]), "=r"(r[2]), "=r"(r[3]) : "r"(addr));
}
__device__ __forceinline__ void mma_bf16(float* d, const uint32_t* a,
                                         uint32_t b0, uint32_t b1) {
    asm volatile(
        "mma.sync.aligned.m16n8k16.row.col.f32.bf16.bf16.f32 "
        "{%0,%1,%2,%3}, {%4,%5,%6,%7}, {%8,%9}, {%0,%1,%2,%3};"
        : "+f"(d[0]), "+f"(d[1]), "+f"(d[2]), "+f"(d[3])
        : "r"(a[0]), "r"(a[1]), "r"(a[2]), "r"(a[3]), "r"(b0), "r"(b1));
}
__device__ __forceinline__ uint32_t pack_bf(float lo, float hi) {
    bf162 v = __float22bfloat162_rn(make_float2(lo, hi));
    return *(uint32_t*)&v;
}
// fast exp via exp2 polynomial on the FMA pipe (MUFU is slow on B300)
__device__ __forceinline__ float expp(float x) {
    float y = fmaxf(x * 1.4426950408889634f, -120.f);
    float t = y + 12582912.f;
    int   e = __float_as_int(t);
    float r = t - 12582912.f;
    float f = y - r;
    float p = 1.3333558146e-3f;
    p = fmaf(p, f, 9.6181291076e-3f);
    p = fmaf(p, f, 5.5504108664e-2f);
    p = fmaf(p, f, 2.4022650696e-1f);
    p = fmaf(p, f, 6.9314718056e-1f);
    p = fmaf(p, f, 1.0f);
    float sc = __int_as_float((e - 0x4b400000 + 127) << 23);
    return p * sc;
}

__device__ __forceinline__ void store_pair(float* C, size_t off, float v0, float v1) {
    *(float2*)(C + off) = make_float2(v0, v1);
}
__device__ __forceinline__ void store_pair(bf16* C, size_t off, float v0, float v1) {
    *(bf162*)(C + off) = __float22bfloat162_rn(make_float2(v0, v1));
}

// ---------------------------------------------------------------------------
// bf16 mma GEMM: C[M,N] = A[M,K] @ B[N,K]^T (+bias, relu, residual)
// 128x256 block tile, 32-half k-chunk, 3-stage cp.async, 8 warps (2m x 4n),
// warp tile 64x64. smem rows: 64B data + 16B pad = 80B.
// ---------------------------------------------------------------------------
#define BM 128
#define BN 256
#define STAGE_B (BM*80 + BN*80)     // 30720 bytes
#define GEMM_SMEM (3*STAGE_B)       // 92160

template<typename TO, bool RELU, bool RES>
__global__ __launch_bounds__(256, 1) void gemm_mma(
    const bf16* __restrict__ A, const bf16* __restrict__ Bm,
    const float* __restrict__ bias, const float* __restrict__ Res,
    TO* __restrict__ C, int Nld, int K,
    int rowsPerExpert, long long bExpStride, int biasExpStride)
{
    extern __shared__ char smem[];
    const uint32_t sb0 = smem_u32(smem);
    const int tid = threadIdx.x;
    const int wid = tid >> 5, lane = tid & 31;
    const int j8 = lane & 7, gi = lane >> 3;
    const int lr = lane >> 2, lc = lane & 3;
    const int row0 = blockIdx.y * BM, col0 = blockIdx.x * BN;
    const int expert = row0 / rowsPerExpert;
    const bf16* Bexp = Bm + (long long)expert * bExpStride;
    const float* bb  = bias + (long long)expert * biasExpStride;
    const int m0 = (wid & 1) * 64, n0 = (wid >> 1) * 64;

    const bf16* Abase = A + (size_t)row0 * K;
    const bf16* Bbase = Bexp + (size_t)col0 * K;

    const int arow = j8 + (gi & 1) * 8;
    const int aoff = (gi >> 1) * 16;
    const int brow = j8 + (gi >> 1) * 8;
    const int boff = (gi & 1) * 16;

    float acc[4][8][4];
#pragma unroll
    for (int mt = 0; mt < 4; mt++)
#pragma unroll
        for (int t = 0; t < 8; t++)
#pragma unroll
            for (int q = 0; q < 4; q++) acc[mt][t][q] = 0.f;

    const int nch = K / 32;

    auto load_stage = [&](int s, int ch) {
        const uint32_t sa  = sb0 + (uint32_t)s * STAGE_B;
        const uint32_t sbm = sa + BM * 80;
        const bf16* Ac = Abase + ch * 32;
        const bf16* Bcp = Bbase + ch * 32;
#pragma unroll
        for (int q = 0; q < 2; q++) {          // A: 512 segs
            int seg = tid + 256 * q;
            int r = seg >> 2, c = seg & 3;
            cp16(sa + (uint32_t)(r * 80 + c * 16), Ac + (size_t)r * K + c * 8);
        }
#pragma unroll
        for (int q = 0; q < 4; q++) {          // B: 1024 segs (r = tid)
            cp16(sbm + (uint32_t)(tid * 80 + q * 16), Bcp + (size_t)tid * K + q * 8);
        }
    };

    load_stage(0, 0);
    asm volatile("cp.async.commit_group;");
    load_stage(1, 1);
    asm volatile("cp.async.commit_group;");

    for (int i = 0; i < nch; i++) {
        if (i + 2 < nch) load_stage((i + 2) % 3, i + 2);
        asm volatile("cp.async.commit_group;");
        asm volatile("cp.async.wait_group 2;");
        __syncthreads();

        const uint32_t sa  = sb0 + (uint32_t)(i % 3) * STAGE_B;
        const uint32_t sbm = sa + BM * 80;
#pragma unroll
        for (int kk = 0; kk < 2; kk++) {
            uint32_t af[4][4];
#pragma unroll
            for (int mt = 0; mt < 4; mt++)
                ldm_x4(af[mt], sa + (uint32_t)((m0 + mt * 16 + arow) * 80 + kk * 32 + aoff));
#pragma unroll
            for (int nt = 0; nt < 4; nt++) {
                uint32_t bfr[4];
                ldm_x4(bfr, sbm + (uint32_t)((n0 + nt * 16 + brow) * 80 + kk * 32 + boff));
#pragma unroll
                for (int mt = 0; mt < 4; mt++) {
                    mma_bf16(acc[mt][nt * 2 + 0], af[mt], bfr[0], bfr[1]);
                    mma_bf16(acc[mt][nt * 2 + 1], af[mt], bfr[2], bfr[3]);
                }
            }
        }
        __syncthreads();
    }

    // epilogue
#pragma unroll
    for (int mt = 0; mt < 4; mt++) {
        const int gr = row0 + m0 + mt * 16 + lr;
#pragma unroll
        for (int nt = 0; nt < 4; nt++) {
#pragma unroll
            for (int pr = 0; pr < 2; pr++) {
                const int gc = col0 + n0 + nt * 16 + pr * 8 + lc * 2;
                float* d = acc[mt][nt * 2 + pr];
                float b0 = bb[gc], b1 = bb[gc + 1];
                float v0 = d[0] + b0, v1 = d[1] + b1;
                float v2 = d[2] + b0, v3 = d[3] + b1;
                if (RELU) {
                    v0 = fmaxf(v0, 0.f); v1 = fmaxf(v1, 0.f);
                    v2 = fmaxf(v2, 0.f); v3 = fmaxf(v3, 0.f);
                }
                if (RES) {
                    float2 r0 = *(const float2*)(Res + (size_t)gr * Nld + gc);
                    float2 r1 = *(const float2*)(Res + (size_t)(gr + 8) * Nld + gc);
                    v0 += r0.x; v1 += r0.y; v2 += r1.x; v3 += r1.y;
                }
                store_pair(C, (size_t)gr * Nld + gc, v0, v1);
                store_pair(C, (size_t)(gr + 8) * Nld + gc, v2, v3);
            }
        }
    }
}

// ---------------------------------------------------------------------------
// Flash attention, bf16 mma. 256 threads (8 warps), q-tile 128, k-tiles of 64.
// smem: Q 128x144B, K/V double-buffered 64x144B each, masks 2x64 floats.
// ---------------------------------------------------------------------------
#define AT_SMEM (18432 + 9216*4 + 512)

__global__ __launch_bounds__(256) void attn_mma(
    const bf16* __restrict__ qkv,
    const unsigned char* __restrict__ pad,
    bf16* __restrict__ outp)
{
    extern __shared__ char smem[];
    const uint32_t sQ  = smem_u32(smem);
    const uint32_t sK0 = sQ + 18432;
    const uint32_t sV0 = sK0 + 9216 * 2;
    float* mkp = (float*)(smem + 18432 + 9216 * 4);

    const int tid = threadIdx.x;
    const int wid = tid >> 5, lane = tid & 31;
    const int j8 = lane & 7, gi = lane >> 3;
    const int lc = lane & 3, lr = lane >> 2;
    const int bh = blockIdx.y, b = bh >> 4, h = bh & 15;
    const int q0 = blockIdx.x * 128;
    const size_t tokBase = (size_t)b * Sq;

    // Q load: 128 rows x 8 segs = 1024
    {
        const bf16* qb = qkv + (tokBase + q0) * 3072 + h * 64;
#pragma unroll
        for (int q = 0; q < 4; q++) {
            int seg = tid + 256 * q;
            int r = seg >> 3, c = seg & 7;
            cp16(sQ + (uint32_t)(r * 144 + c * 16), qb + (size_t)r * 3072 + c * 8);
        }
    }
    asm volatile("cp.async.commit_group;");

    auto prefetch = [&](int st, int kt) {
        const int k0 = kt * 64;
        const bf16* kb = qkv + (tokBase + k0) * 3072 + 1024 + h * 64;
        const bf16* vb = qkv + (tokBase + k0) * 3072 + 2048 + h * 64;
        const uint32_t sk = sK0 + (uint32_t)st * 9216, sv = sV0 + (uint32_t)st * 9216;
#pragma unroll
        for (int q = 0; q < 2; q++) {
            int seg = tid + 256 * q;
            int r = seg >> 3, c = seg & 7;
            cp16(sk + (uint32_t)(r * 144 + c * 16), kb + (size_t)r * 3072 + c * 8);
            cp16(sv + (uint32_t)(r * 144 + c * 16), vb + (size_t)r * 3072 + c * 8);
        }
        if (tid < 64) mkp[st * 64 + tid] = pad[tokBase + k0 + tid] ? -1e9f : 0.f;
    };

    prefetch(0, 0);
    asm volatile("cp.async.commit_group;");
    asm volatile("cp.async.wait_group 1;");   // Q ready
    __syncthreads();

    const int arow = j8 + (gi & 1) * 8, aoff = (gi >> 1) * 16;
    const int brow = j8 + (gi >> 1) * 8, boff = (gi & 1) * 16;

    uint32_t qa[4][4];
#pragma unroll
    for (int kd = 0; kd < 4; kd++)
        ldm_x4(qa[kd], sQ + (uint32_t)((wid * 16 + arow) * 144 + kd * 32 + aoff));

    float m0v = -1e30f, m1v = -1e30f, l0 = 0.f, l1 = 0.f;
    float o[8][4];
#pragma unroll
    for (int dt = 0; dt < 8; dt++)
#pragma unroll
        for (int q = 0; q < 4; q++) o[dt][q] = 0.f;

    for (int kt = 0; kt < Sq / 64; kt++) {
        const int st = kt & 1;
        if (kt + 1 < Sq / 64) prefetch(st ^ 1, kt + 1);
        asm volatile("cp.async.commit_group;");
        asm volatile("cp.async.wait_group 1;");
        __syncthreads();

        const uint32_t sk = sK0 + (uint32_t)st * 9216, sv = sV0 + (uint32_t)st * 9216;
        float s[8][4];
#pragma unroll
        for (int j = 0; j < 8; j++)
#pragma unroll
            for (int q = 0; q < 4; q++) s[j][q] = 0.f;

#pragma unroll
        for (int jp = 0; jp < 4; jp++) {
#pragma unroll
            for (int kd = 0; kd < 4; kd++) {
                uint32_t bfr[4];
                ldm_x4(bfr, sk + (uint32_t)((jp * 16 + brow) * 144 + kd * 32 + boff));
                mma_bf16(s[2 * jp],     qa[kd], bfr[0], bfr[1]);
                mma_bf16(s[2 * jp + 1], qa[kd], bfr[2], bfr[3]);
            }
        }

        float rmax0 = -1e30f, rmax1 = -1e30f;
#pragma unroll
        for (int j = 0; j < 8; j++) {
            float mka = mkp[st * 64 + j * 8 + 2 * lc];
            float mkb = mkp[st * 64 + j * 8 + 2 * lc + 1];
            s[j][0] = fmaf(s[j][0], 0.125f, mka);
            s[j][1] = fmaf(s[j][1], 0.125f, mkb);
            s[j][2] = fmaf(s[j][2], 0.125f, mka);
            s[j][3] = fmaf(s[j][3], 0.125f, mkb);
            rmax0 = fmaxf(rmax0, fmaxf(s[j][0], s[j][1]));
            rmax1 = fmaxf(rmax1, fmaxf(s[j][2], s[j][3]));
        }
        rmax0 = fmaxf(rmax0, __shfl_xor_sync(0xffffffffu, rmax0, 1));
        rmax0 = fmaxf(rmax0, __shfl_xor_sync(0xffffffffu, rmax0, 2));
        rmax1 = fmaxf(rmax1, __shfl_xor_sync(0xffffffffu, rmax1, 1));
        rmax1 = fmaxf(rmax1, __shfl_xor_sync(0xffffffffu, rmax1, 2));
        float nm0 = fmaxf(m0v, rmax0), nm1 = fmaxf(m1v, rmax1);
        float c0 = expp(m0v - nm0), c1 = expp(m1v - nm1);
        m0v = nm0; m1v = nm1;
        float rs0 = 0.f, rs1 = 0.f;
#pragma unroll
        for (int j = 0; j < 8; j++) {
            s[j][0] = expp(s[j][0] - nm0); s[j][1] = expp(s[j][1] - nm0);
            s[j][2] = expp(s[j][2] - nm1); s[j][3] = expp(s[j][3] - nm1);
            rs0 += s[j][0] + s[j][1];
            rs1 += s[j][2] + s[j][3];
        }
        rs0 += __shfl_xor_sync(0xffffffffu, rs0, 1);
        rs0 += __shfl_xor_sync(0xffffffffu, rs0, 2);
        rs1 += __shfl_xor_sync(0xffffffffu, rs1, 1);
        rs1 += __shfl_xor_sync(0xffffffffu, rs1, 2);
        l0 = l0 * c0 + rs0; l1 = l1 * c1 + rs1;
#pragma unroll
        for (int dt = 0; dt < 8; dt++) {
            o[dt][0] *= c0; o[dt][1] *= c0; o[dt][2] *= c1; o[dt][3] *= c1;
        }

        uint32_t pa[4][4];
#pragma unroll
        for (int t = 0; t < 4; t++) {
            pa[t][0] = pack_bf(s[2 * t][0],     s[2 * t][1]);
            pa[t][1] = pack_bf(s[2 * t][2],     s[2 * t][3]);
            pa[t][2] = pack_bf(s[2 * t + 1][0], s[2 * t + 1][1]);
            pa[t][3] = pack_bf(s[2 * t + 1][2], s[2 * t + 1][3]);
        }
#pragma unroll
        for (int t = 0; t < 4; t++) {
#pragma unroll
            for (int dp = 0; dp < 4; dp++) {
                uint32_t vf[4];
                ldm_x4t(vf, sv + (uint32_t)((t * 16 + arow) * 144 + dp * 32 + aoff));
                mma_bf16(o[2 * dp],     pa[t], vf[0], vf[1]);
                mma_bf16(o[2 * dp + 1], pa[t], vf[2], vf[3]);
            }
        }
        __syncthreads();
    }

    float inv0 = 1.f / l0, inv1 = 1.f / l1;
    const int rg = q0 + wid * 16 + lr;
    bf16* ob = outp + (tokBase + rg) * Dm + h * 64;
#pragma unroll
    for (int dt = 0; dt < 8; dt++) {
        *(bf162*)(ob + dt * 8 + 2 * lc) =
            __float22bfloat162_rn(make_float2(o[dt][0] * inv0, o[dt][1] * inv0));
        *(bf162*)(ob + (size_t)8 * Dm + dt * 8 + 2 * lc) =
            __float22bfloat162_rn(make_float2(o[dt][2] * inv1, o[dt][3] * inv1));
    }
}

// ---------------------------------------------------------------------------
// LayerNorm (templated output type)
// ---------------------------------------------------------------------------
template<typename TO>
__global__ __launch_bounds__(256) void ln_kernel(const float* __restrict__ in,
                                                 const float* __restrict__ g,
                                                 const float* __restrict__ b,
                                                 TO* __restrict__ out)
{
    int n = blockIdx.x, tid = threadIdx.x;
    float4 v = ((const float4*)(in + (size_t)n*Dm))[tid];
    float s  = v.x+v.y+v.z+v.w;
    float s2 = v.x*v.x+v.y*v.y+v.z*v.z+v.w*v.w;
    __shared__ float r1[256], r2[256];
    r1[tid]=s; r2[tid]=s2; __syncthreads();
    for (int st=128; st; st>>=1) {
        if (tid<st) { r1[tid]+=r1[tid+st]; r2[tid]+=r2[tid+st]; }
        __syncthreads();
    }
    float mean = r1[0]*(1.0f/Dm);
    float var  = r2[0]*(1.0f/Dm) - mean*mean;
    float rstd = rsqrtf(var + 1e-5f);
    float4 gg = ((const float4*)g)[tid];
    float4 bb = ((const float4*)b)[tid];
    float o0 = (v.x-mean)*rstd*gg.x + bb.x;
    float o1 = (v.y-mean)*rstd*gg.y + bb.y;
    float o2 = (v.z-mean)*rstd*gg.z + bb.z;
    float o3 = (v.w-mean)*rstd*gg.w + bb.w;
    size_t base = (size_t)n*Dm + tid*4;
    store_pair(out, base, o0, o1);
    store_pair(out, base + 2, o2, o3);
}

// ---------------------------------------------------------------------------
// Weight prep
// ---------------------------------------------------------------------------
__global__ __launch_bounds__(256) void bf16_copy(const float* __restrict__ in,
                                                 bf16* __restrict__ out, int n4)
{
    int i = blockIdx.x*256 + threadIdx.x;
    if (i < n4) {
        float4 v = ((const float4*)in)[i];
        ((bf162*)out)[i*2]   = __float22bfloat162_rn(make_float2(v.x, v.y));
        ((bf162*)out)[i*2+1] = __float22bfloat162_rn(make_float2(v.z, v.w));
    }
}

__global__ __launch_bounds__(256) void transpose_bf16(const float* __restrict__ in,
                                                      bf16* __restrict__ out,
                                                      int R, int Cc)
{
    __shared__ float t[32][33];
    int e = blockIdx.z;
    const float* ip = in  + (size_t)e*R*Cc;
    bf16* op        = out + (size_t)e*R*Cc;
    int c0 = blockIdx.x*32, r0 = blockIdx.y*32;
    int tx = threadIdx.x, ty = threadIdx.y;
#pragma unroll
    for (int j=0;j<32;j+=8)
        t[ty+j][tx] = ip[(size_t)(r0+ty+j)*Cc + c0+tx];
    __syncthreads();
#pragma unroll
    for (int j=0;j<32;j+=8)
        op[(size_t)(c0+ty+j)*R + r0+tx] = __float2bfloat16_rn(t[tx][ty+j]);
}

// ---------------------------------------------------------------------------
// Router (fp32)
// ---------------------------------------------------------------------------
__global__ __launch_bounds__(256) void router_kernel(const float* __restrict__ rw,
                                                     const float* __restrict__ rb,
                                                     const unsigned char* __restrict__ pad)
{
    int n = blockIdx.x, tid = threadIdx.x;
    __shared__ float xs[1024];
    __shared__ float lg[8];
    ((float4*)xs)[tid] = ((const float4*)(g_x2 + (size_t)n*Dm))[tid];
    __syncthreads();
    int w = tid >> 5, lane = tid & 31;
    float acc = 0.f;
    for (int i = lane; i < 1024; i += 32) acc += xs[i] * rw[i*8 + w];
    for (int off=16; off; off>>=1) acc += __shfl_xor_sync(0xffffffffu, acc, off);
    if (lane == 0) lg[w] = acc + rb[w];
    __syncthreads();
    if (tid == 0) {
        float mx = lg[0]; int ei = 0;
        for (int e=1;e<8;e++) if (lg[e] > mx) { mx = lg[e]; ei = e; }
        float pr[8], se = 0.f;
        for (int e=0;e<8;e++) { pr[e] = expf(lg[e]-mx); se += pr[e]; }
        float inv = 1.f/se;
        bool valid = (pad[n] == 0);
        float tm = valid ? 1.f : 0.f;
        for (int e=0;e<8;e++) g_probs[n*8+e] = pr[e]*inv*tm;
        g_gate[n] = pr[ei]*inv;
        g_eidx[n] = ei;
        float lse = mx + logf(se);
        g_zterm[n] = lse*lse*tm;
    }
}

// ---------------------------------------------------------------------------
// Routing scan / dispatch / combine / loss
// ---------------------------------------------------------------------------
__global__ void scan_kernel(const unsigned char* __restrict__ pad)
{
    int lane = threadIdx.x;
    __shared__ int base[8];
    if (lane < 8) base[lane] = 0;
    __syncwarp();
    for (int c = 0; c < Ntok/32; c++) {
        int i = c*32 + lane;
        int e = g_eidx[i];
        bool valid = (pad[i] == 0);
        unsigned peers = __match_any_sync(0xffffffffu, e);
        unsigned vmask = __ballot_sync(0xffffffffu, valid);
        unsigned pv = peers & vmask;
        int myrank = __popc(pv & ((1u << lane) - 1u));
        int b0 = base[e];
        __syncwarp();
        int pos = b0 + myrank;
        bool keep = valid && (pos < CAP);
        g_keep[i] = keep ? 1 : 0;
        int slot = e*CAP + pos;
        g_slot[i] = keep ? slot : 0;
        if (keep) g_tok[slot] = i;
        if (valid && lane == (__ffs(pv) - 1)) base[e] = b0 + __popc(pv);
        __syncwarp();
    }
    if (lane < 8) g_cnt[lane] = base[lane];
}

__global__ __launch_bounds__(256) void init_tok_kernel()
{
    int i = blockIdx.x*256 + threadIdx.x;
    if (i < SLOTS) g_tok[i] = -1;
}

__global__ __launch_bounds__(256) void dispatch_kernel()
{
    int slot = blockIdx.x, tid = threadIdx.x;
    int t = g_tok[slot];
    float4 v = make_float4(0.f,0.f,0.f,0.f);
    if (t >= 0) v = ((const float4*)(g_x2 + (size_t)t*Dm))[tid];
    bf162* dp = (bf162*)(g_disp + (size_t)slot*Dm);
    dp[tid*2]   = __float22bfloat162_rn(make_float2(v.x, v.y));
    dp[tid*2+1] = __float22bfloat162_rn(make_float2(v.z, v.w));
}

__global__ __launch_bounds__(256) void combine_kernel(float* __restrict__ out)
{
    int n = blockIdx.x, tid = threadIdx.x;
    float4 s = ((const float4*)(g_src1 + (size_t)n*Dm))[tid];
    if (g_keep[n]) {
        float gte = g_gate[n];
        float4 o = ((const float4*)(g_obuf + (size_t)g_slot[n]*Dm))[tid];
        s.x += gte*o.x; s.y += gte*o.y; s.z += gte*o.z; s.w += gte*o.w;
    }
    ((float4*)(out + (size_t)n*Dm))[tid] = s;
}

__global__ __launch_bounds__(256) void loss_kernel(const unsigned char* __restrict__ pad,
                                                   float* __restrict__ out)
{
    int tid = threadIdx.x;
    float zs = 0.f, ps[8];
    int cnt = 0;
#pragma unroll
    for (int e=0;e<8;e++) ps[e]=0.f;
    for (int n = tid; n < Ntok; n += 256) {
        if (pad[n] == 0) cnt++;
        zs += g_zterm[n];
#pragma unroll
        for (int e=0;e<8;e++) ps[e] += g_probs[n*8+e];
    }
    __shared__ float red[256];
    __shared__ float res[10];
    float vals[10];
    vals[0] = (float)cnt; vals[1] = zs;
    for (int e=0;e<8;e++) vals[2+e] = ps[e];
    for (int q=0;q<10;q++) {
        red[tid] = vals[q]; __syncthreads();
        for (int st=128; st; st>>=1) {
            if (tid < st) red[tid] += red[tid+st];
            __syncthreads();
        }
        if (tid == 0) res[q] = red[0];
        __syncthreads();
    }
    if (tid == 0) {
        float denom = fmaxf(res[0], 1.f);
        float lb = 0.f;
        for (int e=0;e<8;e++) lb += ((float)g_cnt[e]/denom) * (res[2+e]/denom);
        lb *= (float)Ee;
        out[(size_t)Ntok*Dm]     = lb;
        out[(size_t)Ntok*Dm + 1] = res[1]/denom;
    }
}

// ---------------------------------------------------------------------------
// Launch
// ---------------------------------------------------------------------------
extern "C" void kernel_launch(void* const* d_in, const int* in_sizes, int n_in,
                              void* d_out, int out_size)
{
    const float* src  = (const float*)d_in[0];
    const unsigned char* pad = (const unsigned char*)d_in[1];
    const float* ln1g = (const float*)d_in[2];
    const float* ln1b = (const float*)d_in[3];
    const float* ipw  = (const float*)d_in[4];
    const float* ipb  = (const float*)d_in[5];
    const float* opw  = (const float*)d_in[6];
    const float* opb  = (const float*)d_in[7];
    const float* ln2g = (const float*)d_in[8];
    const float* ln2b = (const float*)d_in[9];
    const float* rw   = (const float*)d_in[10];
    const float* rb   = (const float*)d_in[11];
    const float* w1   = (const float*)d_in[12];
    const float* b1   = (const float*)d_in[13];
    const float* w2   = (const float*)d_in[14];
    const float* b2   = (const float*)d_in[15];
    float* out = (float*)d_out;

    bf16 *xln, *qkv, *attn, *disp, *hb, *ipw16, *opw16, *w1t, *w2t;
    float *src1, *x2, *ob;
    cudaGetSymbolAddress((void**)&xln,  g_xln);
    cudaGetSymbolAddress((void**)&qkv,  g_qkv);
    cudaGetSymbolAddress((void**)&attn, g_attn);
    cudaGetSymbolAddress((void**)&src1, g_src1);
    cudaGetSymbolAddress((void**)&x2,   g_x2);
    cudaGetSymbolAddress((void**)&disp, g_disp);
    cudaGetSymbolAddress((void**)&hb,   g_hbuf);
    cudaGetSymbolAddress((void**)&ob,   g_obuf);
    cudaGetSymbolAddress((void**)&ipw16, g_ipw16);
    cudaGetSymbolAddress((void**)&opw16, g_opw16);
    cudaGetSymbolAddress((void**)&w1t,  g_w1t);
    cudaGetSymbolAddress((void**)&w2t,  g_w2t);

    cudaFuncSetAttribute(attn_mma, cudaFuncAttributeMaxDynamicSharedMemorySize, AT_SMEM);
    cudaFuncSetAttribute(gemm_mma<bf16,false,false>, cudaFuncAttributeMaxDynamicSharedMemorySize, GEMM_SMEM);
    cudaFuncSetAttribute(gemm_mma<float,false,true>, cudaFuncAttributeMaxDynamicSharedMemorySize, GEMM_SMEM);
    cudaFuncSetAttribute(gemm_mma<bf16,true,false>,  cudaFuncAttributeMaxDynamicSharedMemorySize, GEMM_SMEM);
    cudaFuncSetAttribute(gemm_mma<float,false,false>,cudaFuncAttributeMaxDynamicSharedMemorySize, GEMM_SMEM);

    // Weight prep
    bf16_copy<<<(3*Dm*Dm/4 + 255)/256, 256>>>(ipw, ipw16, 3*Dm*Dm/4);
    bf16_copy<<<(Dm*Dm/4 + 255)/256, 256>>>(opw, opw16, Dm*Dm/4);
    transpose_bf16<<<dim3(Ff/32, Dm/32, Ee), dim3(32,8)>>>(w1, w1t, Dm, Ff); // [D,F]->[F,D]
    transpose_bf16<<<dim3(Dm/32, Ff/32, Ee), dim3(32,8)>>>(w2, w2t, Ff, Dm); // [F,D]->[D,F]

    // 1. LN1 -> bf16
    ln_kernel<bf16><<<Ntok, 256>>>(src, ln1g, ln1b, xln);
    // 2. QKV -> bf16
    gemm_mma<bf16,false,false><<<dim3(3072/BN, Ntok/BM), 256, GEMM_SMEM>>>(
        xln, ipw16, ipb, nullptr, qkv, 3072, 1024, 1<<30, 0, 0);
    // 3. Attention -> bf16
    attn_mma<<<dim3(Sq/128, Bc*Hh), 256, AT_SMEM>>>(qkv, pad, attn);
    // 4. out_proj + residual(src) -> fp32
    gemm_mma<float,false,true><<<dim3(1024/BN, Ntok/BM), 256, GEMM_SMEM>>>(
        attn, opw16, opb, src, src1, 1024, 1024, 1<<30, 0, 0);
    // 5. LN2 -> fp32 (router needs clean fp32)
    ln_kernel<float><<<Ntok, 256>>>(src1, ln2g, ln2b, x2);
    // 6. Router + scan + dispatch
    router_kernel<<<Ntok, 256>>>(rw, rb, pad);
    init_tok_kernel<<<(SLOTS+255)/256, 256>>>();
    scan_kernel<<<1, 32>>>(pad);
    dispatch_kernel<<<SLOTS, 256>>>();
    // 7. FFN1 (relu) -> bf16
    gemm_mma<bf16,true,false><<<dim3(Ff/BN, SLOTS/BM), 256, GEMM_SMEM>>>(
        disp, w1t, b1, nullptr, hb, Ff, 1024, CAP, (long long)Dm*Ff, Ff);
    // 8. FFN2 -> fp32
    gemm_mma<float,false,false><<<dim3(Dm/BN, SLOTS/BM), 256, GEMM_SMEM>>>(
        hb, w2t, b2, nullptr, ob, Dm, Ff, CAP, (long long)Ff*Dm, Dm);
    // 9. Combine + losses
    combine_kernel<<<Ntok, 256>>>(out);
    loss_kernel<<<1, 256>>>(pad, out);
}

// round 6
// speedup vs baseline: 4.4862x; 1.0237x over previous
#include <cuda_runtime.h>
#include <cuda_bf16.h>
#include <math.h>
#include <stdint.h>

// ---------------------------------------------------------------------------
// Problem constants
// ---------------------------------------------------------------------------
#define Bc   4
#define Sq   2048
#define Dm   1024
#define Hh   16
#define Ee   8
#define Ff   4096
#define Ntok (Bc*Sq)          // 8192
#define CAP  1280
#define SLOTS (Ee*CAP)        // 10240

typedef __nv_bfloat16 bf16;
typedef __nv_bfloat162 bf162;

// ---------------------------------------------------------------------------
// Device scratch
// ---------------------------------------------------------------------------
__device__ bf16  g_xln [Ntok*Dm];
__device__ bf16  g_qkv [Ntok*3*Dm];
__device__ bf16  g_attn[Ntok*Dm];
__device__ float g_src1[Ntok*Dm];
__device__ float g_x2  [Ntok*Dm];
__device__ bf16  g_x2b [Ntok*Dm];
__device__ bf16  g_hbuf[(size_t)SLOTS*Ff];
__device__ float g_probs[Ntok*Ee];
__device__ float g_zterm[Ntok];
__device__ float g_gate [Ntok];
__device__ int   g_eidx [Ntok];
__device__ int   g_tok  [SLOTS];
__device__ int   g_cnt  [Ee];
// bf16 weight copies / transposes ([N,K] layouts)
__device__ bf16 g_ipw16[3*Dm*Dm];
__device__ bf16 g_opw16[Dm*Dm];
__device__ bf16 g_w1t [(size_t)Ee*Ff*Dm];   // [E][F][D]
__device__ bf16 g_w2t [(size_t)Ee*Dm*Ff];   // [E][D][F]

// ---------------------------------------------------------------------------
// Helpers
// ---------------------------------------------------------------------------
__device__ __forceinline__ uint32_t smem_u32(const void* p) {
    uint32_t a;
    asm("{ .reg .u64 t; cvta.to.shared.u64 t, %1; cvt.u32.u64 %0, t; }"
        : "=r"(a) : "l"(p));
    return a;
}
__device__ __forceinline__ void cp16(uint32_t dst, const void* src) {
    asm volatile("cp.async.cg.shared.global [%0], [%1], 16;" :: "r"(dst), "l"(src));
}
__device__ __forceinline__ void cp16z(uint32_t dst, const void* src, uint32_t sz) {
    asm volatile("cp.async.cg.shared.global [%0], [%1], 16, %2;"
                 :: "r"(dst), "l"(src), "r"(sz));
}
__device__ __forceinline__ void ldm_x4(uint32_t* r, uint32_t addr) {
    asm volatile("ldmatrix.sync.aligned.m8n8.x4.shared.b16 {%0,%1,%2,%3}, [%4];"
        : "=r"(r[0]), "=r"(r[1]), "=r"(r[2]), "=r"(r[3]) : "r"(addr));
}
__device__ __forceinline__ void ldm_x4t(uint32_t* r, uint32_t addr) {
    asm volatile("ldmatrix.sync.aligned.m8n8.x4.trans.shared.b16 {%0,%1,%2,%3}, [%4];"
        : "=r"(r[0]), "=r"(r[1]), "=r"(r[2]), "=r"(r[3]) : "r"(addr));
}
__device__ __forceinline__ void mma_bf16(float* d, const uint32_t* a,
                                         uint32_t b0, uint32_t b1) {
    asm volatile(
        "mma.sync.aligned.m16n8k16.row.col.f32.bf16.bf16.f32 "
        "{%0,%1,%2,%3}, {%4,%5,%6,%7}, {%8,%9}, {%0,%1,%2,%3};"
        : "+f"(d[0]), "+f"(d[1]), "+f"(d[2]), "+f"(d[3])
        : "r"(a[0]), "r"(a[1]), "r"(a[2]), "r"(a[3]), "r"(b0), "r"(b1));
}
__device__ __forceinline__ uint32_t pack_bf(float lo, float hi) {
    bf162 v = __float22bfloat162_rn(make_float2(lo, hi));
    return *(uint32_t*)&v;
}
// fast exp via exp2 polynomial on the FMA pipe (MUFU is slow on B300)
__device__ __forceinline__ float expp(float x) {
    float y = fmaxf(x * 1.4426950408889634f, -120.f);
    float t = y + 12582912.f;
    int   e = __float_as_int(t);
    float r = t - 12582912.f;
    float f = y - r;
    float p = 1.3333558146e-3f;
    p = fmaf(p, f, 9.6181291076e-3f);
    p = fmaf(p, f, 5.5504108664e-2f);
    p = fmaf(p, f, 2.4022650696e-1f);
    p = fmaf(p, f, 6.9314718056e-1f);
    p = fmaf(p, f, 1.0f);
    float sc = __int_as_float((e - 0x4b400000 + 127) << 23);
    return p * sc;
}

__device__ __forceinline__ void store_pair(float* C, size_t off, float v0, float v1) {
    *(float2*)(C + off) = make_float2(v0, v1);
}
__device__ __forceinline__ void store_pair(bf16* C, size_t off, float v0, float v1) {
    *(bf162*)(C + off) = __float22bfloat162_rn(make_float2(v0, v1));
}

// ---------------------------------------------------------------------------
// bf16 mma GEMM: C[M,N] = A[M,K] @ B[N,K]^T (+bias, relu, residual)
// 128x256 block tile, 32-half k-chunk, 3-stage cp.async, 8 warps (2m x 4n).
// GATHER: A rows indirected through tokIdx (negative -> zero row).
// SCATTER: epilogue does out[tok[row]] += gate[tok] * (acc + bias).
// ---------------------------------------------------------------------------
#define BM 128
#define BN 256
#define STAGE_B (BM*80 + BN*80)     // 30720 bytes
#define GEMM_SMEM (3*STAGE_B + 512) // + gather index stash

template<typename TO, bool RELU, bool RES, bool GATHER, bool SCATTER>
__global__ __launch_bounds__(256, 1) void gemm_mma(
    const bf16* __restrict__ A, const bf16* __restrict__ Bm,
    const float* __restrict__ bias, const float* __restrict__ Res,
    TO* __restrict__ C, int Nld, int K,
    int rowsPerExpert, long long bExpStride, int biasExpStride,
    const int* __restrict__ tokIdx, const float* __restrict__ gate)
{
    extern __shared__ char smem[];
    const uint32_t sb0 = smem_u32(smem);
    int* stok = (int*)(smem + 3*STAGE_B);
    const int tid = threadIdx.x;
    const int wid = tid >> 5, lane = tid & 31;
    const int j8 = lane & 7, gi = lane >> 3;
    const int lr = lane >> 2, lc = lane & 3;
    const int row0 = blockIdx.y * BM, col0 = blockIdx.x * BN;
    const int expert = row0 / rowsPerExpert;
    const bf16* Bexp = Bm + (long long)expert * bExpStride;
    const float* bb  = bias + (long long)expert * biasExpStride;
    const int m0 = (wid & 1) * 64, n0 = (wid >> 1) * 64;

    const bf16* Abase = GATHER ? A : A + (size_t)row0 * K;
    const bf16* Bbase = Bexp + (size_t)col0 * K;

    if (GATHER) {
        if (tid < BM) stok[tid] = tokIdx[row0 + tid];
        __syncthreads();
    }

    const int arow = j8 + (gi & 1) * 8;
    const int aoff = (gi >> 1) * 16;
    const int brow = j8 + (gi >> 1) * 8;
    const int boff = (gi & 1) * 16;

    float acc[4][8][4];
#pragma unroll
    for (int mt = 0; mt < 4; mt++)
#pragma unroll
        for (int t = 0; t < 8; t++)
#pragma unroll
            for (int q = 0; q < 4; q++) acc[mt][t][q] = 0.f;

    const int nch = K / 32;

    auto load_stage = [&](int s, int ch) {
        const uint32_t sa  = sb0 + (uint32_t)s * STAGE_B;
        const uint32_t sbm = sa + BM * 80;
        const bf16* Bcp = Bbase + ch * 32;
#pragma unroll
        for (int q = 0; q < 2; q++) {          // A: 512 segs
            int seg = tid + 256 * q;
            int r = seg >> 2, c = seg & 3;
            if (GATHER) {
                int t = stok[r];
                uint32_t sz = (t >= 0) ? 16u : 0u;
                const bf16* srcp = Abase + (size_t)(t >= 0 ? t : 0) * K + ch * 32 + c * 8;
                cp16z(sa + (uint32_t)(r * 80 + c * 16), srcp, sz);
            } else {
                cp16(sa + (uint32_t)(r * 80 + c * 16),
                     Abase + (size_t)r * K + ch * 32 + c * 8);
            }
        }
#pragma unroll
        for (int q = 0; q < 4; q++) {          // B: 1024 segs
            cp16(sbm + (uint32_t)(tid * 80 + q * 16), Bcp + (size_t)tid * K + q * 8);
        }
    };

    load_stage(0, 0);
    asm volatile("cp.async.commit_group;");
    load_stage(1, 1);
    asm volatile("cp.async.commit_group;");

    for (int i = 0; i < nch; i++) {
        if (i + 2 < nch) load_stage((i + 2) % 3, i + 2);
        asm volatile("cp.async.commit_group;");
        asm volatile("cp.async.wait_group 2;");
        __syncthreads();

        const uint32_t sa  = sb0 + (uint32_t)(i % 3) * STAGE_B;
        const uint32_t sbm = sa + BM * 80;
#pragma unroll
        for (int kk = 0; kk < 2; kk++) {
            uint32_t af[4][4];
#pragma unroll
            for (int mt = 0; mt < 4; mt++)
                ldm_x4(af[mt], sa + (uint32_t)((m0 + mt * 16 + arow) * 80 + kk * 32 + aoff));
#pragma unroll
            for (int nt = 0; nt < 4; nt++) {
                uint32_t bfr[4];
                ldm_x4(bfr, sbm + (uint32_t)((n0 + nt * 16 + brow) * 80 + kk * 32 + boff));
#pragma unroll
                for (int mt = 0; mt < 4; mt++) {
                    mma_bf16(acc[mt][nt * 2 + 0], af[mt], bfr[0], bfr[1]);
                    mma_bf16(acc[mt][nt * 2 + 1], af[mt], bfr[2], bfr[3]);
                }
            }
        }
        __syncthreads();
    }

    // epilogue
#pragma unroll
    for (int mt = 0; mt < 4; mt++) {
        const int gr = row0 + m0 + mt * 16 + lr;
        int t0 = 0, t1 = 0;
        float g0 = 0.f, g1 = 0.f;
        if (SCATTER) {
            t0 = tokIdx[gr]; t1 = tokIdx[gr + 8];
            g0 = (t0 >= 0) ? gate[t0] : 0.f;
            g1 = (t1 >= 0) ? gate[t1] : 0.f;
        }
#pragma unroll
        for (int nt = 0; nt < 4; nt++) {
#pragma unroll
            for (int pr = 0; pr < 2; pr++) {
                const int gc = col0 + n0 + nt * 16 + pr * 8 + lc * 2;
                float* d = acc[mt][nt * 2 + pr];
                float b0 = bb[gc], b1 = bb[gc + 1];
                float v0 = d[0] + b0, v1 = d[1] + b1;
                float v2 = d[2] + b0, v3 = d[3] + b1;
                if (RELU) {
                    v0 = fmaxf(v0, 0.f); v1 = fmaxf(v1, 0.f);
                    v2 = fmaxf(v2, 0.f); v3 = fmaxf(v3, 0.f);
                }
                if (RES) {
                    float2 r0 = *(const float2*)(Res + (size_t)gr * Nld + gc);
                    float2 r1 = *(const float2*)(Res + (size_t)(gr + 8) * Nld + gc);
                    v0 += r0.x; v1 += r0.y; v2 += r1.x; v3 += r1.y;
                }
                if (SCATTER) {
                    if (t0 >= 0) {
                        float2 cur = *(float2*)((float*)C + (size_t)t0 * Nld + gc);
                        *(float2*)((float*)C + (size_t)t0 * Nld + gc) =
                            make_float2(cur.x + g0 * v0, cur.y + g0 * v1);
                    }
                    if (t1 >= 0) {
                        float2 cur = *(float2*)((float*)C + (size_t)t1 * Nld + gc);
                        *(float2*)((float*)C + (size_t)t1 * Nld + gc) =
                            make_float2(cur.x + g1 * v2, cur.y + g1 * v3);
                    }
                } else {
                    store_pair(C, (size_t)gr * Nld + gc, v0, v1);
                    store_pair(C, (size_t)(gr + 8) * Nld + gc, v2, v3);
                }
            }
        }
    }
}

// ---------------------------------------------------------------------------
// Flash attention, bf16 mma. 256 threads (8 warps), q-tile 128, k-tiles of 64.
// ---------------------------------------------------------------------------
#define AT_SMEM (18432 + 9216*4 + 512)

__global__ __launch_bounds__(256) void attn_mma(
    const bf16* __restrict__ qkv,
    const unsigned char* __restrict__ pad,
    bf16* __restrict__ outp)
{
    extern __shared__ char smem[];
    const uint32_t sQ  = smem_u32(smem);
    const uint32_t sK0 = sQ + 18432;
    const uint32_t sV0 = sK0 + 9216 * 2;
    float* mkp = (float*)(smem + 18432 + 9216 * 4);

    const int tid = threadIdx.x;
    const int wid = tid >> 5, lane = tid & 31;
    const int j8 = lane & 7, gi = lane >> 3;
    const int lc = lane & 3, lr = lane >> 2;
    const int bh = blockIdx.y, b = bh >> 4, h = bh & 15;
    const int q0 = blockIdx.x * 128;
    const size_t tokBase = (size_t)b * Sq;

    {
        const bf16* qb = qkv + (tokBase + q0) * 3072 + h * 64;
#pragma unroll
        for (int q = 0; q < 4; q++) {
            int seg = tid + 256 * q;
            int r = seg >> 3, c = seg & 7;
            cp16(sQ + (uint32_t)(r * 144 + c * 16), qb + (size_t)r * 3072 + c * 8);
        }
    }
    asm volatile("cp.async.commit_group;");

    auto prefetch = [&](int st, int kt) {
        const int k0 = kt * 64;
        const bf16* kb = qkv + (tokBase + k0) * 3072 + 1024 + h * 64;
        const bf16* vb = qkv + (tokBase + k0) * 3072 + 2048 + h * 64;
        const uint32_t sk = sK0 + (uint32_t)st * 9216, sv = sV0 + (uint32_t)st * 9216;
#pragma unroll
        for (int q = 0; q < 2; q++) {
            int seg = tid + 256 * q;
            int r = seg >> 3, c = seg & 7;
            cp16(sk + (uint32_t)(r * 144 + c * 16), kb + (size_t)r * 3072 + c * 8);
            cp16(sv + (uint32_t)(r * 144 + c * 16), vb + (size_t)r * 3072 + c * 8);
        }
        if (tid < 64) mkp[st * 64 + tid] = pad[tokBase + k0 + tid] ? -1e9f : 0.f;
    };

    prefetch(0, 0);
    asm volatile("cp.async.commit_group;");
    asm volatile("cp.async.wait_group 1;");
    __syncthreads();

    const int arow = j8 + (gi & 1) * 8, aoff = (gi >> 1) * 16;
    const int brow = j8 + (gi >> 1) * 8, boff = (gi & 1) * 16;

    uint32_t qa[4][4];
#pragma unroll
    for (int kd = 0; kd < 4; kd++)
        ldm_x4(qa[kd], sQ + (uint32_t)((wid * 16 + arow) * 144 + kd * 32 + aoff));

    float m0v = -1e30f, m1v = -1e30f, l0 = 0.f, l1 = 0.f;
    float o[8][4];
#pragma unroll
    for (int dt = 0; dt < 8; dt++)
#pragma unroll
        for (int q = 0; q < 4; q++) o[dt][q] = 0.f;

    for (int kt = 0; kt < Sq / 64; kt++) {
        const int st = kt & 1;
        if (kt + 1 < Sq / 64) prefetch(st ^ 1, kt + 1);
        asm volatile("cp.async.commit_group;");
        asm volatile("cp.async.wait_group 1;");
        __syncthreads();

        const uint32_t sk = sK0 + (uint32_t)st * 9216, sv = sV0 + (uint32_t)st * 9216;
        float s[8][4];
#pragma unroll
        for (int j = 0; j < 8; j++)
#pragma unroll
            for (int q = 0; q < 4; q++) s[j][q] = 0.f;

#pragma unroll
        for (int jp = 0; jp < 4; jp++) {
#pragma unroll
            for (int kd = 0; kd < 4; kd++) {
                uint32_t bfr[4];
                ldm_x4(bfr, sk + (uint32_t)((jp * 16 + brow) * 144 + kd * 32 + boff));
                mma_bf16(s[2 * jp],     qa[kd], bfr[0], bfr[1]);
                mma_bf16(s[2 * jp + 1], qa[kd], bfr[2], bfr[3]);
            }
        }

        float rmax0 = -1e30f, rmax1 = -1e30f;
#pragma unroll
        for (int j = 0; j < 8; j++) {
            float mka = mkp[st * 64 + j * 8 + 2 * lc];
            float mkb = mkp[st * 64 + j * 8 + 2 * lc + 1];
            s[j][0] = fmaf(s[j][0], 0.125f, mka);
            s[j][1] = fmaf(s[j][1], 0.125f, mkb);
            s[j][2] = fmaf(s[j][2], 0.125f, mka);
            s[j][3] = fmaf(s[j][3], 0.125f, mkb);
            rmax0 = fmaxf(rmax0, fmaxf(s[j][0], s[j][1]));
            rmax1 = fmaxf(rmax1, fmaxf(s[j][2], s[j][3]));
        }
        rmax0 = fmaxf(rmax0, __shfl_xor_sync(0xffffffffu, rmax0, 1));
        rmax0 = fmaxf(rmax0, __shfl_xor_sync(0xffffffffu, rmax0, 2));
        rmax1 = fmaxf(rmax1, __shfl_xor_sync(0xffffffffu, rmax1, 1));
        rmax1 = fmaxf(rmax1, __shfl_xor_sync(0xffffffffu, rmax1, 2));
        float nm0 = fmaxf(m0v, rmax0), nm1 = fmaxf(m1v, rmax1);
        float c0 = expp(m0v - nm0), c1 = expp(m1v - nm1);
        m0v = nm0; m1v = nm1;
        float rs0 = 0.f, rs1 = 0.f;
#pragma unroll
        for (int j = 0; j < 8; j++) {
            s[j][0] = expp(s[j][0] - nm0); s[j][1] = expp(s[j][1] - nm0);
            s[j][2] = expp(s[j][2] - nm1); s[j][3] = expp(s[j][3] - nm1);
            rs0 += s[j][0] + s[j][1];
            rs1 += s[j][2] + s[j][3];
        }
        rs0 += __shfl_xor_sync(0xffffffffu, rs0, 1);
        rs0 += __shfl_xor_sync(0xffffffffu, rs0, 2);
        rs1 += __shfl_xor_sync(0xffffffffu, rs1, 1);
        rs1 += __shfl_xor_sync(0xffffffffu, rs1, 2);
        l0 = l0 * c0 + rs0; l1 = l1 * c1 + rs1;
#pragma unroll
        for (int dt = 0; dt < 8; dt++) {
            o[dt][0] *= c0; o[dt][1] *= c0; o[dt][2] *= c1; o[dt][3] *= c1;
        }

        uint32_t pa[4][4];
#pragma unroll
        for (int t = 0; t < 4; t++) {
            pa[t][0] = pack_bf(s[2 * t][0],     s[2 * t][1]);
            pa[t][1] = pack_bf(s[2 * t][2],     s[2 * t][3]);
            pa[t][2] = pack_bf(s[2 * t + 1][0], s[2 * t + 1][1]);
            pa[t][3] = pack_bf(s[2 * t + 1][2], s[2 * t + 1][3]);
        }
#pragma unroll
        for (int t = 0; t < 4; t++) {
#pragma unroll
            for (int dp = 0; dp < 4; dp++) {
                uint32_t vf[4];
                ldm_x4t(vf, sv + (uint32_t)((t * 16 + arow) * 144 + dp * 32 + aoff));
                mma_bf16(o[2 * dp],     pa[t], vf[0], vf[1]);
                mma_bf16(o[2 * dp + 1], pa[t], vf[2], vf[3]);
            }
        }
        __syncthreads();
    }

    float inv0 = 1.f / l0, inv1 = 1.f / l1;
    const int rg = q0 + wid * 16 + lr;
    bf16* ob = outp + (tokBase + rg) * Dm + h * 64;
#pragma unroll
    for (int dt = 0; dt < 8; dt++) {
        *(bf162*)(ob + dt * 8 + 2 * lc) =
            __float22bfloat162_rn(make_float2(o[dt][0] * inv0, o[dt][1] * inv0));
        *(bf162*)(ob + (size_t)8 * Dm + dt * 8 + 2 * lc) =
            __float22bfloat162_rn(make_float2(o[dt][2] * inv1, o[dt][3] * inv1));
    }
}

// ---------------------------------------------------------------------------
// LayerNorm (single-output, and dual fp32+bf16 for LN2)
// ---------------------------------------------------------------------------
template<typename TO>
__global__ __launch_bounds__(256) void ln_kernel(const float* __restrict__ in,
                                                 const float* __restrict__ g,
                                                 const float* __restrict__ b,
                                                 TO* __restrict__ out)
{
    int n = blockIdx.x, tid = threadIdx.x;
    float4 v = ((const float4*)(in + (size_t)n*Dm))[tid];
    float s  = v.x+v.y+v.z+v.w;
    float s2 = v.x*v.x+v.y*v.y+v.z*v.z+v.w*v.w;
    __shared__ float r1[256], r2[256];
    r1[tid]=s; r2[tid]=s2; __syncthreads();
    for (int st=128; st; st>>=1) {
        if (tid<st) { r1[tid]+=r1[tid+st]; r2[tid]+=r2[tid+st]; }
        __syncthreads();
    }
    float mean = r1[0]*(1.0f/Dm);
    float var  = r2[0]*(1.0f/Dm) - mean*mean;
    float rstd = rsqrtf(var + 1e-5f);
    float4 gg = ((const float4*)g)[tid];
    float4 bb = ((const float4*)b)[tid];
    float o0 = (v.x-mean)*rstd*gg.x + bb.x;
    float o1 = (v.y-mean)*rstd*gg.y + bb.y;
    float o2 = (v.z-mean)*rstd*gg.z + bb.z;
    float o3 = (v.w-mean)*rstd*gg.w + bb.w;
    size_t base = (size_t)n*Dm + tid*4;
    store_pair(out, base, o0, o1);
    store_pair(out, base + 2, o2, o3);
}

__global__ __launch_bounds__(256) void ln2_dual(const float* __restrict__ in,
                                                const float* __restrict__ g,
                                                const float* __restrict__ b,
                                                float* __restrict__ outf,
                                                bf16* __restrict__ outh)
{
    int n = blockIdx.x, tid = threadIdx.x;
    float4 v = ((const float4*)(in + (size_t)n*Dm))[tid];
    float s  = v.x+v.y+v.z+v.w;
    float s2 = v.x*v.x+v.y*v.y+v.z*v.z+v.w*v.w;
    __shared__ float r1[256], r2[256];
    r1[tid]=s; r2[tid]=s2; __syncthreads();
    for (int st=128; st; st>>=1) {
        if (tid<st) { r1[tid]+=r1[tid+st]; r2[tid]+=r2[tid+st]; }
        __syncthreads();
    }
    float mean = r1[0]*(1.0f/Dm);
    float var  = r2[0]*(1.0f/Dm) - mean*mean;
    float rstd = rsqrtf(var + 1e-5f);
    float4 gg = ((const float4*)g)[tid];
    float4 bb = ((const float4*)b)[tid];
    float4 o;
    o.x = (v.x-mean)*rstd*gg.x + bb.x;
    o.y = (v.y-mean)*rstd*gg.y + bb.y;
    o.z = (v.z-mean)*rstd*gg.z + bb.z;
    o.w = (v.w-mean)*rstd*gg.w + bb.w;
    ((float4*)(outf + (size_t)n*Dm))[tid] = o;
    bf162* hp = (bf162*)(outh + (size_t)n*Dm);
    hp[tid*2]   = __float22bfloat162_rn(make_float2(o.x, o.y));
    hp[tid*2+1] = __float22bfloat162_rn(make_float2(o.z, o.w));
}

// ---------------------------------------------------------------------------
// Weight prep
// ---------------------------------------------------------------------------
__global__ __launch_bounds__(256) void bf16_copy(const float* __restrict__ in,
                                                 bf16* __restrict__ out, int n4)
{
    int i = blockIdx.x*256 + threadIdx.x;
    if (i < n4) {
        float4 v = ((const float4*)in)[i];
        ((bf162*)out)[i*2]   = __float22bfloat162_rn(make_float2(v.x, v.y));
        ((bf162*)out)[i*2+1] = __float22bfloat162_rn(make_float2(v.z, v.w));
    }
}

__global__ __launch_bounds__(256) void transpose_bf16(const float* __restrict__ in,
                                                      bf16* __restrict__ out,
                                                      int R, int Cc)
{
    __shared__ float t[32][33];
    int e = blockIdx.z;
    const float* ip = in  + (size_t)e*R*Cc;
    bf16* op        = out + (size_t)e*R*Cc;
    int c0 = blockIdx.x*32, r0 = blockIdx.y*32;
    int tx = threadIdx.x, ty = threadIdx.y;
#pragma unroll
    for (int j=0;j<32;j+=8)
        t[ty+j][tx] = ip[(size_t)(r0+ty+j)*Cc + c0+tx];
    __syncthreads();
#pragma unroll
    for (int j=0;j<32;j+=8)
        op[(size_t)(c0+ty+j)*R + r0+tx] = __float2bfloat16_rn(t[tx][ty+j]);
}

// ---------------------------------------------------------------------------
// Router (fp32)
// ---------------------------------------------------------------------------
__global__ __launch_bounds__(256) void router_kernel(const float* __restrict__ rw,
                                                     const float* __restrict__ rb,
                                                     const unsigned char* __restrict__ pad)
{
    int n = blockIdx.x, tid = threadIdx.x;
    __shared__ float xs[1024];
    __shared__ float lg[8];
    ((float4*)xs)[tid] = ((const float4*)(g_x2 + (size_t)n*Dm))[tid];
    __syncthreads();
    int w = tid >> 5, lane = tid & 31;
    float acc = 0.f;
    for (int i = lane; i < 1024; i += 32) acc += xs[i] * rw[i*8 + w];
    for (int off=16; off; off>>=1) acc += __shfl_xor_sync(0xffffffffu, acc, off);
    if (lane == 0) lg[w] = acc + rb[w];
    __syncthreads();
    if (tid == 0) {
        float mx = lg[0]; int ei = 0;
        for (int e=1;e<8;e++) if (lg[e] > mx) { mx = lg[e]; ei = e; }
        float pr[8], se = 0.f;
        for (int e=0;e<8;e++) { pr[e] = expf(lg[e]-mx); se += pr[e]; }
        float inv = 1.f/se;
        bool valid = (pad[n] == 0);
        float tm = valid ? 1.f : 0.f;
        for (int e=0;e<8;e++) g_probs[n*8+e] = pr[e]*inv*tm;
        g_gate[n] = pr[ei]*inv;
        g_eidx[n] = ei;
        float lse = mx + logf(se);
        g_zterm[n] = lse*lse*tm;
    }
}

// ---------------------------------------------------------------------------
// Routing scan: smem-staged, warp 0 does exact token-order scan.
// Also initializes g_tok.
// ---------------------------------------------------------------------------
__global__ __launch_bounds__(1024) void scan_kernel(const unsigned char* __restrict__ pad)
{
    __shared__ unsigned char sc[Ntok];
    __shared__ int base[8];
    int tid = threadIdx.x;
    for (int i = tid; i < SLOTS; i += 1024) g_tok[i] = -1;
    for (int i = tid; i < Ntok; i += 1024)
        sc[i] = (unsigned char)(g_eidx[i] | (pad[i] ? 0 : 16));
    if (tid < 8) base[tid] = 0;
    __syncthreads();
    if (tid < 32) {
        int lane = tid;
        for (int c = 0; c < Ntok/32; c++) {
            int i = c*32 + lane;
            int code = sc[i];
            int e = code & 7;
            bool valid = (code & 16) != 0;
            unsigned peers = __match_any_sync(0xffffffffu, e);
            unsigned vmask = __ballot_sync(0xffffffffu, valid);
            unsigned pv = peers & vmask;
            int myrank = __popc(pv & ((1u << lane) - 1u));
            int b0 = base[e];
            __syncwarp();
            int pos = b0 + myrank;
            bool keep = valid && (pos < CAP);
            if (keep) g_tok[e*CAP + pos] = i;
            if (valid && lane == (__ffs(pv) - 1)) base[e] = b0 + __popc(pv);
            __syncwarp();
        }
        if (lane < 8) g_cnt[lane] = base[lane];
    }
}

// ---------------------------------------------------------------------------
// Prefill out = src1 (FFN scatter adds on top) / loss
// ---------------------------------------------------------------------------
__global__ __launch_bounds__(256) void prefill_kernel(float* __restrict__ out)
{
    int n = blockIdx.x, tid = threadIdx.x;
    ((float4*)(out + (size_t)n*Dm))[tid] = ((const float4*)(g_src1 + (size_t)n*Dm))[tid];
}

__global__ __launch_bounds__(256) void loss_kernel(const unsigned char* __restrict__ pad,
                                                   float* __restrict__ out)
{
    int tid = threadIdx.x;
    float zs = 0.f, ps[8];
    int cnt = 0;
#pragma unroll
    for (int e=0;e<8;e++) ps[e]=0.f;
    for (int n = tid; n < Ntok; n += 256) {
        if (pad[n] == 0) cnt++;
        zs += g_zterm[n];
#pragma unroll
        for (int e=0;e<8;e++) ps[e] += g_probs[n*8+e];
    }
    __shared__ float red[256];
    __shared__ float res[10];
    float vals[10];
    vals[0] = (float)cnt; vals[1] = zs;
    for (int e=0;e<8;e++) vals[2+e] = ps[e];
    for (int q=0;q<10;q++) {
        red[tid] = vals[q]; __syncthreads();
        for (int st=128; st; st>>=1) {
            if (tid < st) red[tid] += red[tid+st];
            __syncthreads();
        }
        if (tid == 0) res[q] = red[0];
        __syncthreads();
    }
    if (tid == 0) {
        float denom = fmaxf(res[0], 1.f);
        float lb = 0.f;
        for (int e=0;e<8;e++) lb += ((float)g_cnt[e]/denom) * (res[2+e]/denom);
        lb *= (float)Ee;
        out[(size_t)Ntok*Dm]     = lb;
        out[(size_t)Ntok*Dm + 1] = res[1]/denom;
    }
}

// ---------------------------------------------------------------------------
// Launch
// ---------------------------------------------------------------------------
extern "C" void kernel_launch(void* const* d_in, const int* in_sizes, int n_in,
                              void* d_out, int out_size)
{
    const float* src  = (const float*)d_in[0];
    const unsigned char* pad = (const unsigned char*)d_in[1];
    const float* ln1g = (const float*)d_in[2];
    const float* ln1b = (const float*)d_in[3];
    const float* ipw  = (const float*)d_in[4];
    const float* ipb  = (const float*)d_in[5];
    const float* opw  = (const float*)d_in[6];
    const float* opb  = (const float*)d_in[7];
    const float* ln2g = (const float*)d_in[8];
    const float* ln2b = (const float*)d_in[9];
    const float* rw   = (const float*)d_in[10];
    const float* rb   = (const float*)d_in[11];
    const float* w1   = (const float*)d_in[12];
    const float* b1   = (const float*)d_in[13];
    const float* w2   = (const float*)d_in[14];
    const float* b2   = (const float*)d_in[15];
    float* out = (float*)d_out;

    bf16 *xln, *qkv, *attn, *x2b, *hb, *ipw16, *opw16, *w1t, *w2t;
    float *src1, *x2, *gate;
    int *tok;
    cudaGetSymbolAddress((void**)&xln,  g_xln);
    cudaGetSymbolAddress((void**)&qkv,  g_qkv);
    cudaGetSymbolAddress((void**)&attn, g_attn);
    cudaGetSymbolAddress((void**)&src1, g_src1);
    cudaGetSymbolAddress((void**)&x2,   g_x2);
    cudaGetSymbolAddress((void**)&x2b,  g_x2b);
    cudaGetSymbolAddress((void**)&hb,   g_hbuf);
    cudaGetSymbolAddress((void**)&ipw16, g_ipw16);
    cudaGetSymbolAddress((void**)&opw16, g_opw16);
    cudaGetSymbolAddress((void**)&w1t,  g_w1t);
    cudaGetSymbolAddress((void**)&w2t,  g_w2t);
    cudaGetSymbolAddress((void**)&tok,  g_tok);
    cudaGetSymbolAddress((void**)&gate, g_gate);

    cudaFuncSetAttribute(attn_mma, cudaFuncAttributeMaxDynamicSharedMemorySize, AT_SMEM);
    cudaFuncSetAttribute(gemm_mma<bf16,false,false,false,false>, cudaFuncAttributeMaxDynamicSharedMemorySize, GEMM_SMEM);
    cudaFuncSetAttribute(gemm_mma<float,false,true,false,false>, cudaFuncAttributeMaxDynamicSharedMemorySize, GEMM_SMEM);
    cudaFuncSetAttribute(gemm_mma<bf16,true,false,true,false>,   cudaFuncAttributeMaxDynamicSharedMemorySize, GEMM_SMEM);
    cudaFuncSetAttribute(gemm_mma<float,false,false,false,true>, cudaFuncAttributeMaxDynamicSharedMemorySize, GEMM_SMEM);

    // Weight prep
    bf16_copy<<<(3*Dm*Dm/4 + 255)/256, 256>>>(ipw, ipw16, 3*Dm*Dm/4);
    bf16_copy<<<(Dm*Dm/4 + 255)/256, 256>>>(opw, opw16, Dm*Dm/4);
    transpose_bf16<<<dim3(Ff/32, Dm/32, Ee), dim3(32,8)>>>(w1, w1t, Dm, Ff);
    transpose_bf16<<<dim3(Dm/32, Ff/32, Ee), dim3(32,8)>>>(w2, w2t, Ff, Dm);

    // 1. LN1 -> bf16
    ln_kernel<bf16><<<Ntok, 256>>>(src, ln1g, ln1b, xln);
    // 2. QKV -> bf16
    gemm_mma<bf16,false,false,false,false><<<dim3(3072/BN, Ntok/BM), 256, GEMM_SMEM>>>(
        xln, ipw16, ipb, nullptr, qkv, 3072, 1024, 1<<30, 0, 0, nullptr, nullptr);
    // 3. Attention -> bf16
    attn_mma<<<dim3(Sq/128, Bc*Hh), 256, AT_SMEM>>>(qkv, pad, attn);
    // 4. out_proj + residual(src) -> src1 (fp32)
    gemm_mma<float,false,true,false,false><<<dim3(1024/BN, Ntok/BM), 256, GEMM_SMEM>>>(
        attn, opw16, opb, src, src1, 1024, 1024, 1<<30, 0, 0, nullptr, nullptr);
    // 5. LN2 -> fp32 (router) + bf16 (FFN gather)
    ln2_dual<<<Ntok, 256>>>(src1, ln2g, ln2b, x2, x2b);
    // 6. Router + scan
    router_kernel<<<Ntok, 256>>>(rw, rb, pad);
    scan_kernel<<<1, 1024>>>(pad);
    // 7. Prefill out = src1
    prefill_kernel<<<Ntok, 256>>>(out);
    // 8. FFN1 (gathered A, relu) -> bf16 hbuf
    gemm_mma<bf16,true,false,true,false><<<dim3(Ff/BN, SLOTS/BM), 256, GEMM_SMEM>>>(
        x2b, w1t, b1, nullptr, hb, Ff, 1024, CAP, (long long)Dm*Ff, Ff, tok, nullptr);
    // 9. FFN2 (scatter-add into out with gate)
    gemm_mma<float,false,false,false,true><<<dim3(Dm/BN, SLOTS/BM), 256, GEMM_SMEM>>>(
        hb, w2t, b2, nullptr, out, Dm, Ff, CAP, (long long)Ff*Dm, Dm, tok, gate);
    // 10. Losses
    loss_kernel<<<1, 256>>>(pad, out);
}

// round 7
// speedup vs baseline: 6.2850x; 1.4010x over previous
#include <cuda_runtime.h>
#include <cuda_bf16.h>
#include <math.h>
#include <stdint.h>

// ---------------------------------------------------------------------------
// Problem constants
// ---------------------------------------------------------------------------
#define Bc   4
#define Sq   2048
#define Dm   1024
#define Hh   16
#define Ee   8
#define Ff   4096
#define Ntok (Bc*Sq)          // 8192
#define CAP  1280
#define SLOTS (Ee*CAP)        // 10240

typedef __nv_bfloat16 bf16;
typedef __nv_bfloat162 bf162;

// ---------------------------------------------------------------------------
// Device scratch
// ---------------------------------------------------------------------------
__device__ bf16  g_xln [Ntok*Dm];
__device__ bf16  g_qkv [Ntok*3*Dm];
__device__ bf16  g_attn[Ntok*Dm];
__device__ float g_src1[Ntok*Dm];
__device__ bf16  g_x2b [Ntok*Dm];
__device__ bf16  g_hbuf[(size_t)SLOTS*Ff];
__device__ float g_probs[Ntok*Ee];
__device__ float g_zterm[Ntok];
__device__ float g_gate [Ntok];
__device__ int   g_eidx [Ntok];
__device__ int   g_tok  [SLOTS];
__device__ int   g_cnt  [Ee];
// bf16 weight copies / transposes ([N,K] layouts)
__device__ bf16 g_ipw16[3*Dm*Dm];
__device__ bf16 g_opw16[Dm*Dm];
__device__ bf16 g_w1t [(size_t)Ee*Ff*Dm];   // [E][F][D]
__device__ bf16 g_w2t [(size_t)Ee*Dm*Ff];   // [E][D][F]

// ---------------------------------------------------------------------------
// Helpers
// ---------------------------------------------------------------------------
__device__ __forceinline__ uint32_t smem_u32(const void* p) {
    uint32_t a;
    asm("{ .reg .u64 t; cvta.to.shared.u64 t, %1; cvt.u32.u64 %0, t; }"
        : "=r"(a) : "l"(p));
    return a;
}
__device__ __forceinline__ void cp16(uint32_t dst, const void* src) {
    asm volatile("cp.async.cg.shared.global [%0], [%1], 16;" :: "r"(dst), "l"(src));
}
__device__ __forceinline__ void cp16z(uint32_t dst, const void* src, uint32_t sz) {
    asm volatile("cp.async.cg.shared.global [%0], [%1], 16, %2;"
                 :: "r"(dst), "l"(src), "r"(sz));
}
__device__ __forceinline__ void ldm_x4(uint32_t* r, uint32_t addr) {
    asm volatile("ldmatrix.sync.aligned.m8n8.x4.shared.b16 {%0,%1,%2,%3}, [%4];"
        : "=r"(r[0]), "=r"(r[1]), "=r"(r[2]), "=r"(r[3]) : "r"(addr));
}
__device__ __forceinline__ void ldm_x4t(uint32_t* r, uint32_t addr) {
    asm volatile("ldmatrix.sync.aligned.m8n8.x4.trans.shared.b16 {%0,%1,%2,%3}, [%4];"
        : "=r"(r[0]), "=r"(r[1]), "=r"(r[2]), "=r"(r[3]) : "r"(addr));
}
__device__ __forceinline__ void mma_bf16(float* d, const uint32_t* a,
                                         uint32_t b0, uint32_t b1) {
    asm volatile(
        "mma.sync.aligned.m16n8k16.row.col.f32.bf16.bf16.f32 "
        "{%0,%1,%2,%3}, {%4,%5,%6,%7}, {%8,%9}, {%0,%1,%2,%3};"
        : "+f"(d[0]), "+f"(d[1]), "+f"(d[2]), "+f"(d[3])
        : "r"(a[0]), "r"(a[1]), "r"(a[2]), "r"(a[3]), "r"(b0), "r"(b1));
}
__device__ __forceinline__ uint32_t pack_bf(float lo, float hi) {
    bf162 v = __float22bfloat162_rn(make_float2(lo, hi));
    return *(uint32_t*)&v;
}
// fast exp via exp2 polynomial on the FMA pipe (MUFU is slow on B300)
__device__ __forceinline__ float expp(float x) {
    float y = fmaxf(x * 1.4426950408889634f, -120.f);
    float t = y + 12582912.f;
    int   e = __float_as_int(t);
    float r = t - 12582912.f;
    float f = y - r;
    float p = 1.3333558146e-3f;
    p = fmaf(p, f, 9.6181291076e-3f);
    p = fmaf(p, f, 5.5504108664e-2f);
    p = fmaf(p, f, 2.4022650696e-1f);
    p = fmaf(p, f, 6.9314718056e-1f);
    p = fmaf(p, f, 1.0f);
    float sc = __int_as_float((e - 0x4b400000 + 127) << 23);
    return p * sc;
}

__device__ __forceinline__ void store_pair(float* C, size_t off, float v0, float v1) {
    *(float2*)(C + off) = make_float2(v0, v1);
}
__device__ __forceinline__ void store_pair(bf16* C, size_t off, float v0, float v1) {
    *(bf162*)(C + off) = __float22bfloat162_rn(make_float2(v0, v1));
}

// ---------------------------------------------------------------------------
// bf16 mma GEMM: C[M,N] = A[M,K] @ B[N,K]^T (+bias, relu, residual)
// 128x256 block tile, 64-half k-chunk (144B padded rows), 3-stage cp.async,
// 8 warps (2m x 4n), warp tile 64x64.
// GATHER: A rows indirected through tokIdx (negative -> zero row).
// SCATTER: epilogue does out[tok[row]] += gate[tok] * (acc + bias).
// Empty-tile early exit when all 128 row tokens are -1.
// DUAL: additionally store results to C2 (fp32 path only).
// ---------------------------------------------------------------------------
#define BM 128
#define BN 256
#define RSTR 144
#define STAGE_B ((BM+BN)*RSTR)      // 55296 bytes
#define GEMM_SMEM (3*STAGE_B + 512)

template<typename TO, bool RELU, bool RES, bool GATHER, bool SCATTER, bool DUAL>
__global__ __launch_bounds__(256, 1) void gemm_mma(
    const bf16* __restrict__ A, const bf16* __restrict__ Bm,
    const float* __restrict__ bias, const float* __restrict__ Res,
    TO* __restrict__ C, float* __restrict__ C2, int Nld, int K,
    int rowsPerExpert, long long bExpStride, int biasExpStride,
    const int* __restrict__ tokIdx, const float* __restrict__ gate)
{
    extern __shared__ char smem[];
    const uint32_t sb0 = smem_u32(smem);
    int* stok = (int*)(smem + 3*STAGE_B);
    const int tid = threadIdx.x;
    const int wid = tid >> 5, lane = tid & 31;
    const int j8 = lane & 7, gi = lane >> 3;
    const int lr = lane >> 2, lc = lane & 3;
    const int row0 = blockIdx.y * BM, col0 = blockIdx.x * BN;
    const int expert = row0 / rowsPerExpert;
    const bf16* Bexp = Bm + (long long)expert * bExpStride;
    const float* bb  = bias + (long long)expert * biasExpStride;
    const int m0 = (wid & 1) * 64, n0 = (wid >> 1) * 64;

    const bf16* Abase = GATHER ? A : A + (size_t)row0 * K;
    const bf16* Bbase = Bexp + (size_t)col0 * K;

    if (GATHER || SCATTER) {
        int v = 0;
        if (tid < BM) {
            int t = tokIdx[row0 + tid];
            stok[tid] = t;
            v = (t >= 0);
        }
        if (!__syncthreads_or(v)) return;   // whole tile empty -> no effect
    }

    const int arow = j8 + (gi & 1) * 8;
    const int aoff = (gi >> 1) * 16;
    const int brow = j8 + (gi >> 1) * 8;
    const int boff = (gi & 1) * 16;

    float acc[4][8][4];
#pragma unroll
    for (int mt = 0; mt < 4; mt++)
#pragma unroll
        for (int t = 0; t < 8; t++)
#pragma unroll
            for (int q = 0; q < 4; q++) acc[mt][t][q] = 0.f;

    const int nch = K / 64;

    auto load_stage = [&](int s, int ch) {
        const uint32_t sa  = sb0 + (uint32_t)s * STAGE_B;
        const uint32_t sbm = sa + BM * RSTR;
        const bf16* Bcp = Bbase + ch * 64;
#pragma unroll
        for (int q = 0; q < 4; q++) {          // A: 1024 segs of 16B
            int seg = tid + 256 * q;
            int r = seg >> 3, c = seg & 7;
            if (GATHER) {
                int t = stok[r];
                uint32_t sz = (t >= 0) ? 16u : 0u;
                const bf16* srcp = Abase + (size_t)(t >= 0 ? t : 0) * K + ch * 64 + c * 8;
                cp16z(sa + (uint32_t)(r * RSTR + c * 16), srcp, sz);
            } else {
                cp16(sa + (uint32_t)(r * RSTR + c * 16),
                     Abase + (size_t)r * K + ch * 64 + c * 8);
            }
        }
#pragma unroll
        for (int q = 0; q < 8; q++) {          // B: 2048 segs of 16B
            int seg = tid + 256 * q;
            int r = seg >> 3, c = seg & 7;
            cp16(sbm + (uint32_t)(r * RSTR + c * 16), Bcp + (size_t)r * K + c * 8);
        }
    };

    load_stage(0, 0);
    asm volatile("cp.async.commit_group;");
    load_stage(1, 1);
    asm volatile("cp.async.commit_group;");

    for (int i = 0; i < nch; i++) {
        if (i + 2 < nch) load_stage((i + 2) % 3, i + 2);
        asm volatile("cp.async.commit_group;");
        asm volatile("cp.async.wait_group 2;");
        __syncthreads();

        const uint32_t sa  = sb0 + (uint32_t)(i % 3) * STAGE_B;
        const uint32_t sbm = sa + BM * RSTR;
#pragma unroll
        for (int kk = 0; kk < 4; kk++) {
            uint32_t af[4][4];
#pragma unroll
            for (int mt = 0; mt < 4; mt++)
                ldm_x4(af[mt], sa + (uint32_t)((m0 + mt * 16 + arow) * RSTR + kk * 32 + aoff));
#pragma unroll
            for (int nt = 0; nt < 4; nt++) {
                uint32_t bfr[4];
                ldm_x4(bfr, sbm + (uint32_t)((n0 + nt * 16 + brow) * RSTR + kk * 32 + boff));
#pragma unroll
                for (int mt = 0; mt < 4; mt++) {
                    mma_bf16(acc[mt][nt * 2 + 0], af[mt], bfr[0], bfr[1]);
                    mma_bf16(acc[mt][nt * 2 + 1], af[mt], bfr[2], bfr[3]);
                }
            }
        }
        __syncthreads();
    }

    // epilogue
#pragma unroll
    for (int mt = 0; mt < 4; mt++) {
        const int gr = row0 + m0 + mt * 16 + lr;
        int t0 = 0, t1 = 0;
        float g0 = 0.f, g1 = 0.f;
        if (SCATTER) {
            t0 = stok[m0 + mt * 16 + lr]; t1 = stok[m0 + mt * 16 + lr + 8];
            g0 = (t0 >= 0) ? gate[t0] : 0.f;
            g1 = (t1 >= 0) ? gate[t1] : 0.f;
        }
#pragma unroll
        for (int nt = 0; nt < 4; nt++) {
#pragma unroll
            for (int pr = 0; pr < 2; pr++) {
                const int gc = col0 + n0 + nt * 16 + pr * 8 + lc * 2;
                float* d = acc[mt][nt * 2 + pr];
                float b0 = bb[gc], b1 = bb[gc + 1];
                float v0 = d[0] + b0, v1 = d[1] + b1;
                float v2 = d[2] + b0, v3 = d[3] + b1;
                if (RELU) {
                    v0 = fmaxf(v0, 0.f); v1 = fmaxf(v1, 0.f);
                    v2 = fmaxf(v2, 0.f); v3 = fmaxf(v3, 0.f);
                }
                if (RES) {
                    float2 r0 = *(const float2*)(Res + (size_t)gr * Nld + gc);
                    float2 r1 = *(const float2*)(Res + (size_t)(gr + 8) * Nld + gc);
                    v0 += r0.x; v1 += r0.y; v2 += r1.x; v3 += r1.y;
                }
                if (SCATTER) {
                    if (t0 >= 0) {
                        float2 cur = *(float2*)((float*)C + (size_t)t0 * Nld + gc);
                        *(float2*)((float*)C + (size_t)t0 * Nld + gc) =
                            make_float2(cur.x + g0 * v0, cur.y + g0 * v1);
                    }
                    if (t1 >= 0) {
                        float2 cur = *(float2*)((float*)C + (size_t)t1 * Nld + gc);
                        *(float2*)((float*)C + (size_t)t1 * Nld + gc) =
                            make_float2(cur.x + g1 * v2, cur.y + g1 * v3);
                    }
                } else {
                    store_pair(C, (size_t)gr * Nld + gc, v0, v1);
                    store_pair(C, (size_t)(gr + 8) * Nld + gc, v2, v3);
                    if (DUAL) {
                        store_pair(C2, (size_t)gr * Nld + gc, v0, v1);
                        store_pair(C2, (size_t)(gr + 8) * Nld + gc, v2, v3);
                    }
                }
            }
        }
    }
}

// ---------------------------------------------------------------------------
// Flash attention, bf16 mma. 256 threads (8 warps), q-tile 128, k-tiles of 64.
// ---------------------------------------------------------------------------
#define AT_SMEM (18432 + 9216*4 + 512)

__global__ __launch_bounds__(256) void attn_mma(
    const bf16* __restrict__ qkv,
    const unsigned char* __restrict__ pad,
    bf16* __restrict__ outp)
{
    extern __shared__ char smem[];
    const uint32_t sQ  = smem_u32(smem);
    const uint32_t sK0 = sQ + 18432;
    const uint32_t sV0 = sK0 + 9216 * 2;
    float* mkp = (float*)(smem + 18432 + 9216 * 4);

    const int tid = threadIdx.x;
    const int wid = tid >> 5, lane = tid & 31;
    const int j8 = lane & 7, gi = lane >> 3;
    const int lc = lane & 3, lr = lane >> 2;
    const int bh = blockIdx.y, b = bh >> 4, h = bh & 15;
    const int q0 = blockIdx.x * 128;
    const size_t tokBase = (size_t)b * Sq;

    {
        const bf16* qb = qkv + (tokBase + q0) * 3072 + h * 64;
#pragma unroll
        for (int q = 0; q < 4; q++) {
            int seg = tid + 256 * q;
            int r = seg >> 3, c = seg & 7;
            cp16(sQ + (uint32_t)(r * 144 + c * 16), qb + (size_t)r * 3072 + c * 8);
        }
    }
    asm volatile("cp.async.commit_group;");

    auto prefetch = [&](int st, int kt) {
        const int k0 = kt * 64;
        const bf16* kb = qkv + (tokBase + k0) * 3072 + 1024 + h * 64;
        const bf16* vb = qkv + (tokBase + k0) * 3072 + 2048 + h * 64;
        const uint32_t sk = sK0 + (uint32_t)st * 9216, sv = sV0 + (uint32_t)st * 9216;
#pragma unroll
        for (int q = 0; q < 2; q++) {
            int seg = tid + 256 * q;
            int r = seg >> 3, c = seg & 7;
            cp16(sk + (uint32_t)(r * 144 + c * 16), kb + (size_t)r * 3072 + c * 8);
            cp16(sv + (uint32_t)(r * 144 + c * 16), vb + (size_t)r * 3072 + c * 8);
        }
        if (tid < 64) mkp[st * 64 + tid] = pad[tokBase + k0 + tid] ? -1e9f : 0.f;
    };

    prefetch(0, 0);
    asm volatile("cp.async.commit_group;");
    asm volatile("cp.async.wait_group 1;");
    __syncthreads();

    const int arow = j8 + (gi & 1) * 8, aoff = (gi >> 1) * 16;
    const int brow = j8 + (gi >> 1) * 8, boff = (gi & 1) * 16;

    uint32_t qa[4][4];
#pragma unroll
    for (int kd = 0; kd < 4; kd++)
        ldm_x4(qa[kd], sQ + (uint32_t)((wid * 16 + arow) * 144 + kd * 32 + aoff));

    float m0v = -1e30f, m1v = -1e30f, l0 = 0.f, l1 = 0.f;
    float o[8][4];
#pragma unroll
    for (int dt = 0; dt < 8; dt++)
#pragma unroll
        for (int q = 0; q < 4; q++) o[dt][q] = 0.f;

    for (int kt = 0; kt < Sq / 64; kt++) {
        const int st = kt & 1;
        if (kt + 1 < Sq / 64) prefetch(st ^ 1, kt + 1);
        asm volatile("cp.async.commit_group;");
        asm volatile("cp.async.wait_group 1;");
        __syncthreads();

        const uint32_t sk = sK0 + (uint32_t)st * 9216, sv = sV0 + (uint32_t)st * 9216;
        float s[8][4];
#pragma unroll
        for (int j = 0; j < 8; j++)
#pragma unroll
            for (int q = 0; q < 4; q++) s[j][q] = 0.f;

#pragma unroll
        for (int jp = 0; jp < 4; jp++) {
#pragma unroll
            for (int kd = 0; kd < 4; kd++) {
                uint32_t bfr[4];
                ldm_x4(bfr, sk + (uint32_t)((jp * 16 + brow) * 144 + kd * 32 + boff));
                mma_bf16(s[2 * jp],     qa[kd], bfr[0], bfr[1]);
                mma_bf16(s[2 * jp + 1], qa[kd], bfr[2], bfr[3]);
            }
        }

        float rmax0 = -1e30f, rmax1 = -1e30f;
#pragma unroll
        for (int j = 0; j < 8; j++) {
            float mka = mkp[st * 64 + j * 8 + 2 * lc];
            float mkb = mkp[st * 64 + j * 8 + 2 * lc + 1];
            s[j][0] = fmaf(s[j][0], 0.125f, mka);
            s[j][1] = fmaf(s[j][1], 0.125f, mkb);
            s[j][2] = fmaf(s[j][2], 0.125f, mka);
            s[j][3] = fmaf(s[j][3], 0.125f, mkb);
            rmax0 = fmaxf(rmax0, fmaxf(s[j][0], s[j][1]));
            rmax1 = fmaxf(rmax1, fmaxf(s[j][2], s[j][3]));
        }
        rmax0 = fmaxf(rmax0, __shfl_xor_sync(0xffffffffu, rmax0, 1));
        rmax0 = fmaxf(rmax0, __shfl_xor_sync(0xffffffffu, rmax0, 2));
        rmax1 = fmaxf(rmax1, __shfl_xor_sync(0xffffffffu, rmax1, 1));
        rmax1 = fmaxf(rmax1, __shfl_xor_sync(0xffffffffu, rmax1, 2));
        float nm0 = fmaxf(m0v, rmax0), nm1 = fmaxf(m1v, rmax1);
        float c0 = expp(m0v - nm0), c1 = expp(m1v - nm1);
        m0v = nm0; m1v = nm1;
        float rs0 = 0.f, rs1 = 0.f;
#pragma unroll
        for (int j = 0; j < 8; j++) {
            s[j][0] = expp(s[j][0] - nm0); s[j][1] = expp(s[j][1] - nm0);
            s[j][2] = expp(s[j][2] - nm1); s[j][3] = expp(s[j][3] - nm1);
            rs0 += s[j][0] + s[j][1];
            rs1 += s[j][2] + s[j][3];
        }
        rs0 += __shfl_xor_sync(0xffffffffu, rs0, 1);
        rs0 += __shfl_xor_sync(0xffffffffu, rs0, 2);
        rs1 += __shfl_xor_sync(0xffffffffu, rs1, 1);
        rs1 += __shfl_xor_sync(0xffffffffu, rs1, 2);
        l0 = l0 * c0 + rs0; l1 = l1 * c1 + rs1;
#pragma unroll
        for (int dt = 0; dt < 8; dt++) {
            o[dt][0] *= c0; o[dt][1] *= c0; o[dt][2] *= c1; o[dt][3] *= c1;
        }

        uint32_t pa[4][4];
#pragma unroll
        for (int t = 0; t < 4; t++) {
            pa[t][0] = pack_bf(s[2 * t][0],     s[2 * t][1]);
            pa[t][1] = pack_bf(s[2 * t][2],     s[2 * t][3]);
            pa[t][2] = pack_bf(s[2 * t + 1][0], s[2 * t + 1][1]);
            pa[t][3] = pack_bf(s[2 * t + 1][2], s[2 * t + 1][3]);
        }
#pragma unroll
        for (int t = 0; t < 4; t++) {
#pragma unroll
            for (int dp = 0; dp < 4; dp++) {
                uint32_t vf[4];
                ldm_x4t(vf, sv + (uint32_t)((t * 16 + arow) * 144 + dp * 32 + aoff));
                mma_bf16(o[2 * dp],     pa[t], vf[0], vf[1]);
                mma_bf16(o[2 * dp + 1], pa[t], vf[2], vf[3]);
            }
        }
        __syncthreads();
    }

    float inv0 = 1.f / l0, inv1 = 1.f / l1;
    const int rg = q0 + wid * 16 + lr;
    bf16* ob = outp + (tokBase + rg) * Dm + h * 64;
#pragma unroll
    for (int dt = 0; dt < 8; dt++) {
        *(bf162*)(ob + dt * 8 + 2 * lc) =
            __float22bfloat162_rn(make_float2(o[dt][0] * inv0, o[dt][1] * inv0));
        *(bf162*)(ob + (size_t)8 * Dm + dt * 8 + 2 * lc) =
            __float22bfloat162_rn(make_float2(o[dt][2] * inv1, o[dt][3] * inv1));
    }
}

// ---------------------------------------------------------------------------
// LayerNorm (bf16 out, for LN1)
// ---------------------------------------------------------------------------
__global__ __launch_bounds__(256) void ln_kernel(const float* __restrict__ in,
                                                 const float* __restrict__ g,
                                                 const float* __restrict__ b,
                                                 bf16* __restrict__ out)
{
    int n = blockIdx.x, tid = threadIdx.x;
    float4 v = ((const float4*)(in + (size_t)n*Dm))[tid];
    float s  = v.x+v.y+v.z+v.w;
    float s2 = v.x*v.x+v.y*v.y+v.z*v.z+v.w*v.w;
    __shared__ float r1[256], r2[256];
    r1[tid]=s; r2[tid]=s2; __syncthreads();
    for (int st=128; st; st>>=1) {
        if (tid<st) { r1[tid]+=r1[tid+st]; r2[tid]+=r2[tid+st]; }
        __syncthreads();
    }
    float mean = r1[0]*(1.0f/Dm);
    float var  = r2[0]*(1.0f/Dm) - mean*mean;
    float rstd = rsqrtf(var + 1e-5f);
    float4 gg = ((const float4*)g)[tid];
    float4 bb = ((const float4*)b)[tid];
    float o0 = (v.x-mean)*rstd*gg.x + bb.x;
    float o1 = (v.y-mean)*rstd*gg.y + bb.y;
    float o2 = (v.z-mean)*rstd*gg.z + bb.z;
    float o3 = (v.w-mean)*rstd*gg.w + bb.w;
    size_t base = (size_t)n*Dm + tid*4;
    store_pair(out, base, o0, o1);
    store_pair(out, base + 2, o2, o3);
}

// ---------------------------------------------------------------------------
// LN2 + router fused: LN(src1) -> bf16 x2b, plus router probs/gate/eidx/zterm
// ---------------------------------------------------------------------------
__global__ __launch_bounds__(256) void ln2_router(const float* __restrict__ in,
                                                  const float* __restrict__ g,
                                                  const float* __restrict__ b,
                                                  bf16* __restrict__ outh,
                                                  const float* __restrict__ rw,
                                                  const float* __restrict__ rb,
                                                  const unsigned char* __restrict__ pad)
{
    int n = blockIdx.x, tid = threadIdx.x;
    __shared__ float r1[256], r2[256];
    __shared__ float xs[1024];
    __shared__ float lg[8];
    float4 v = ((const float4*)(in + (size_t)n*Dm))[tid];
    float s  = v.x+v.y+v.z+v.w;
    float s2 = v.x*v.x+v.y*v.y+v.z*v.z+v.w*v.w;
    r1[tid]=s; r2[tid]=s2; __syncthreads();
    for (int st=128; st; st>>=1) {
        if (tid<st) { r1[tid]+=r1[tid+st]; r2[tid]+=r2[tid+st]; }
        __syncthreads();
    }
    float mean = r1[0]*(1.0f/Dm);
    float var  = r2[0]*(1.0f/Dm) - mean*mean;
    float rstd = rsqrtf(var + 1e-5f);
    float4 gg = ((const float4*)g)[tid];
    float4 bb = ((const float4*)b)[tid];
    float4 o;
    o.x = (v.x-mean)*rstd*gg.x + bb.x;
    o.y = (v.y-mean)*rstd*gg.y + bb.y;
    o.z = (v.z-mean)*rstd*gg.z + bb.z;
    o.w = (v.w-mean)*rstd*gg.w + bb.w;
    bf162* hp = (bf162*)(outh + (size_t)n*Dm);
    hp[tid*2]   = __float22bfloat162_rn(make_float2(o.x, o.y));
    hp[tid*2+1] = __float22bfloat162_rn(make_float2(o.z, o.w));
    ((float4*)xs)[tid] = o;
    __syncthreads();
    // router: 8 warps, one expert each (same accumulation order as before)
    int w = tid >> 5, lane = tid & 31;
    float acc = 0.f;
    for (int i = lane; i < 1024; i += 32) acc += xs[i] * rw[i*8 + w];
    for (int off=16; off; off>>=1) acc += __shfl_xor_sync(0xffffffffu, acc, off);
    if (lane == 0) lg[w] = acc + rb[w];
    __syncthreads();
    if (tid == 0) {
        float mx = lg[0]; int ei = 0;
        for (int e=1;e<8;e++) if (lg[e] > mx) { mx = lg[e]; ei = e; }
        float pr[8], se = 0.f;
        for (int e=0;e<8;e++) { pr[e] = expf(lg[e]-mx); se += pr[e]; }
        float inv = 1.f/se;
        bool valid = (pad[n] == 0);
        float tm = valid ? 1.f : 0.f;
        for (int e=0;e<8;e++) g_probs[n*8+e] = pr[e]*inv*tm;
        g_gate[n] = pr[ei]*inv;
        g_eidx[n] = ei;
        float lse = mx + logf(se);
        g_zterm[n] = lse*lse*tm;
    }
}

// ---------------------------------------------------------------------------
// Weight prep
// ---------------------------------------------------------------------------
__global__ __launch_bounds__(256) void bf16_copy(const float* __restrict__ in,
                                                 bf16* __restrict__ out, int n4)
{
    int i = blockIdx.x*256 + threadIdx.x;
    if (i < n4) {
        float4 v = ((const float4*)in)[i];
        ((bf162*)out)[i*2]   = __float22bfloat162_rn(make_float2(v.x, v.y));
        ((bf162*)out)[i*2+1] = __float22bfloat162_rn(make_float2(v.z, v.w));
    }
}

__global__ __launch_bounds__(256) void transpose_bf16(const float* __restrict__ in,
                                                      bf16* __restrict__ out,
                                                      int R, int Cc)
{
    __shared__ float t[32][33];
    int e = blockIdx.z;
    const float* ip = in  + (size_t)e*R*Cc;
    bf16* op        = out + (size_t)e*R*Cc;
    int c0 = blockIdx.x*32, r0 = blockIdx.y*32;
    int tx = threadIdx.x, ty = threadIdx.y;
#pragma unroll
    for (int j=0;j<32;j+=8)
        t[ty+j][tx] = ip[(size_t)(r0+ty+j)*Cc + c0+tx];
    __syncthreads();
#pragma unroll
    for (int j=0;j<32;j+=8)
        op[(size_t)(c0+ty+j)*R + r0+tx] = __float2bfloat16_rn(t[tx][ty+j]);
}

// ---------------------------------------------------------------------------
// Routing scan: smem-staged, warp 0 does exact token-order scan.
// ---------------------------------------------------------------------------
__global__ __launch_bounds__(1024) void scan_kernel(const unsigned char* __restrict__ pad)
{
    __shared__ unsigned char sc[Ntok];
    __shared__ int base[8];
    int tid = threadIdx.x;
    for (int i = tid; i < SLOTS; i += 1024) g_tok[i] = -1;
    for (int i = tid; i < Ntok; i += 1024)
        sc[i] = (unsigned char)(g_eidx[i] | (pad[i] ? 0 : 16));
    if (tid < 8) base[tid] = 0;
    __syncthreads();
    if (tid < 32) {
        int lane = tid;
        for (int c = 0; c < Ntok/32; c++) {
            int i = c*32 + lane;
            int code = sc[i];
            int e = code & 7;
            bool valid = (code & 16) != 0;
            unsigned peers = __match_any_sync(0xffffffffu, e);
            unsigned vmask = __ballot_sync(0xffffffffu, valid);
            unsigned pv = peers & vmask;
            int myrank = __popc(pv & ((1u << lane) - 1u));
            int b0 = base[e];
            __syncwarp();
            int pos = b0 + myrank;
            bool keep = valid && (pos < CAP);
            if (keep) g_tok[e*CAP + pos] = i;
            if (valid && lane == (__ffs(pv) - 1)) base[e] = b0 + __popc(pv);
            __syncwarp();
        }
        if (lane < 8) g_cnt[lane] = base[lane];
    }
}

// ---------------------------------------------------------------------------
// Loss reduction
// ---------------------------------------------------------------------------
__global__ __launch_bounds__(256) void loss_kernel(const unsigned char* __restrict__ pad,
                                                   float* __restrict__ out)
{
    int tid = threadIdx.x;
    float zs = 0.f, ps[8];
    int cnt = 0;
#pragma unroll
    for (int e=0;e<8;e++) ps[e]=0.f;
    for (int n = tid; n < Ntok; n += 256) {
        if (pad[n] == 0) cnt++;
        zs += g_zterm[n];
#pragma unroll
        for (int e=0;e<8;e++) ps[e] += g_probs[n*8+e];
    }
    __shared__ float red[256];
    __shared__ float res[10];
    float vals[10];
    vals[0] = (float)cnt; vals[1] = zs;
    for (int e=0;e<8;e++) vals[2+e] = ps[e];
    for (int q=0;q<10;q++) {
        red[tid] = vals[q]; __syncthreads();
        for (int st=128; st; st>>=1) {
            if (tid < st) red[tid] += red[tid+st];
            __syncthreads();
        }
        if (tid == 0) res[q] = red[0];
        __syncthreads();
    }
    if (tid == 0) {
        float denom = fmaxf(res[0], 1.f);
        float lb = 0.f;
        for (int e=0;e<8;e++) lb += ((float)g_cnt[e]/denom) * (res[2+e]/denom);
        lb *= (float)Ee;
        out[(size_t)Ntok*Dm]     = lb;
        out[(size_t)Ntok*Dm + 1] = res[1]/denom;
    }
}

// ---------------------------------------------------------------------------
// Launch
// ---------------------------------------------------------------------------
extern "C" void kernel_launch(void* const* d_in, const int* in_sizes, int n_in,
                              void* d_out, int out_size)
{
    const float* src  = (const float*)d_in[0];
    const unsigned char* pad = (const unsigned char*)d_in[1];
    const float* ln1g = (const float*)d_in[2];
    const float* ln1b = (const float*)d_in[3];
    const float* ipw  = (const float*)d_in[4];
    const float* ipb  = (const float*)d_in[5];
    const float* opw  = (const float*)d_in[6];
    const float* opb  = (const float*)d_in[7];
    const float* ln2g = (const float*)d_in[8];
    const float* ln2b = (const float*)d_in[9];
    const float* rw   = (const float*)d_in[10];
    const float* rb   = (const float*)d_in[11];
    const float* w1   = (const float*)d_in[12];
    const float* b1   = (const float*)d_in[13];
    const float* w2   = (const float*)d_in[14];
    const float* b2   = (const float*)d_in[15];
    float* out = (float*)d_out;

    bf16 *xln, *qkv, *attn, *x2b, *hb, *ipw16, *opw16, *w1t, *w2t;
    float *src1, *gate;
    int *tok;
    cudaGetSymbolAddress((void**)&xln,  g_xln);
    cudaGetSymbolAddress((void**)&qkv,  g_qkv);
    cudaGetSymbolAddress((void**)&attn, g_attn);
    cudaGetSymbolAddress((void**)&src1, g_src1);
    cudaGetSymbolAddress((void**)&x2b,  g_x2b);
    cudaGetSymbolAddress((void**)&hb,   g_hbuf);
    cudaGetSymbolAddress((void**)&ipw16, g_ipw16);
    cudaGetSymbolAddress((void**)&opw16, g_opw16);
    cudaGetSymbolAddress((void**)&w1t,  g_w1t);
    cudaGetSymbolAddress((void**)&w2t,  g_w2t);
    cudaGetSymbolAddress((void**)&tok,  g_tok);
    cudaGetSymbolAddress((void**)&gate, g_gate);

    cudaFuncSetAttribute(attn_mma, cudaFuncAttributeMaxDynamicSharedMemorySize, AT_SMEM);
    cudaFuncSetAttribute(gemm_mma<bf16,false,false,false,false,false>, cudaFuncAttributeMaxDynamicSharedMemorySize, GEMM_SMEM);
    cudaFuncSetAttribute(gemm_mma<float,false,true,false,false,true>,  cudaFuncAttributeMaxDynamicSharedMemorySize, GEMM_SMEM);
    cudaFuncSetAttribute(gemm_mma<bf16,true,false,true,false,false>,   cudaFuncAttributeMaxDynamicSharedMemorySize, GEMM_SMEM);
    cudaFuncSetAttribute(gemm_mma<float,false,false,false,true,false>, cudaFuncAttributeMaxDynamicSharedMemorySize, GEMM_SMEM);

    // Weight prep
    bf16_copy<<<(3*Dm*Dm/4 + 255)/256, 256>>>(ipw, ipw16, 3*Dm*Dm/4);
    bf16_copy<<<(Dm*Dm/4 + 255)/256, 256>>>(opw, opw16, Dm*Dm/4);
    transpose_bf16<<<dim3(Ff/32, Dm/32, Ee), dim3(32,8)>>>(w1, w1t, Dm, Ff);
    transpose_bf16<<<dim3(Dm/32, Ff/32, Ee), dim3(32,8)>>>(w2, w2t, Ff, Dm);

    // 1. LN1 -> bf16
    ln_kernel<<<Ntok, 256>>>(src, ln1g, ln1b, xln);
    // 2. QKV -> bf16
    gemm_mma<bf16,false,false,false,false,false><<<dim3(3072/BN, Ntok/BM), 256, GEMM_SMEM>>>(
        xln, ipw16, ipb, nullptr, qkv, nullptr, 3072, 1024, 1<<30, 0, 0, nullptr, nullptr);
    // 3. Attention -> bf16
    attn_mma<<<dim3(Sq/128, Bc*Hh), 256, AT_SMEM>>>(qkv, pad, attn);
    // 4. out_proj + residual(src) -> src1 AND out (dual store)
    gemm_mma<float,false,true,false,false,true><<<dim3(1024/BN, Ntok/BM), 256, GEMM_SMEM>>>(
        attn, opw16, opb, src, src1, out, 1024, 1024, 1<<30, 0, 0, nullptr, nullptr);
    // 5. LN2 + router fused
    ln2_router<<<Ntok, 256>>>(src1, ln2g, ln2b, x2b, rw, rb, pad);
    // 6. Scan
    scan_kernel<<<1, 1024>>>(pad);
    // 7. FFN1 (gathered A, relu, empty-tile skip) -> bf16 hbuf
    gemm_mma<bf16,true,false,true,false,false><<<dim3(Ff/BN, SLOTS/BM), 256, GEMM_SMEM>>>(
        x2b, w1t, b1, nullptr, hb, nullptr, Ff, 1024, CAP, (long long)Dm*Ff, Ff, tok, nullptr);
    // 8. FFN2 (scatter-add into out with gate, empty-tile skip)
    gemm_mma<float,false,false,false,true,false><<<dim3(Dm/BN, SLOTS/BM), 256, GEMM_SMEM>>>(
        hb, w2t, b2, nullptr, out, nullptr, Dm, Ff, CAP, (long long)Ff*Dm, Dm, tok, gate);
    // 9. Losses
    loss_kernel<<<1, 256>>>(pad, out);
}

// round 8
// speedup vs baseline: 6.4034x; 1.0188x over previous
#include <cuda_runtime.h>
#include <cuda_bf16.h>
#include <math.h>
#include <stdint.h>

// ---------------------------------------------------------------------------
// Problem constants
// ---------------------------------------------------------------------------
#define Bc   4
#define Sq   2048
#define Dm   1024
#define Hh   16
#define Ee   8
#define Ff   4096
#define Ntok (Bc*Sq)          // 8192
#define CAP  1280
#define SLOTS (Ee*CAP)        // 10240

typedef __nv_bfloat16 bf16;
typedef __nv_bfloat162 bf162;

// ---------------------------------------------------------------------------
// Device scratch
// ---------------------------------------------------------------------------
__device__ bf16  g_xln [Ntok*Dm];
__device__ bf16  g_qkv [Ntok*3*Dm];
__device__ bf16  g_attn[Ntok*Dm];
__device__ float g_src1[Ntok*Dm];
__device__ bf16  g_x2b [Ntok*Dm];
__device__ bf16  g_hbuf[(size_t)SLOTS*Ff];
__device__ float g_probs[Ntok*Ee];
__device__ float g_zterm[Ntok];
__device__ float g_gate [Ntok];
__device__ int   g_eidx [Ntok];
__device__ int   g_tok  [SLOTS];
__device__ int   g_cnt  [Ee];
// bf16 weight copies / transposes ([N,K] layouts)
__device__ bf16 g_ipw16[3*Dm*Dm];
__device__ bf16 g_opw16[Dm*Dm];
__device__ bf16 g_w1t [(size_t)Ee*Ff*Dm];   // [E][F][D]
__device__ bf16 g_w2t [(size_t)Ee*Dm*Ff];   // [E][D][F]

// ---------------------------------------------------------------------------
// Helpers
// ---------------------------------------------------------------------------
__device__ __forceinline__ uint32_t smem_u32(const void* p) {
    uint32_t a;
    asm("{ .reg .u64 t; cvta.to.shared.u64 t, %1; cvt.u32.u64 %0, t; }"
        : "=r"(a) : "l"(p));
    return a;
}
__device__ __forceinline__ void cp16(uint32_t dst, const void* src) {
    asm volatile("cp.async.cg.shared.global [%0], [%1], 16;" :: "r"(dst), "l"(src));
}
__device__ __forceinline__ void cp16z(uint32_t dst, const void* src, uint32_t sz) {
    asm volatile("cp.async.cg.shared.global [%0], [%1], 16, %2;"
                 :: "r"(dst), "l"(src), "r"(sz));
}
__device__ __forceinline__ void ldm_x4(uint32_t* r, uint32_t addr) {
    asm volatile("ldmatrix.sync.aligned.m8n8.x4.shared.b16 {%0,%1,%2,%3}, [%4];"
        : "=r"(r[0]), "=r"(r[1]), "=r"(r[2]), "=r"(r[3]) : "r"(addr));
}
__device__ __forceinline__ void ldm_x4t(uint32_t* r, uint32_t addr) {
    asm volatile("ldmatrix.sync.aligned.m8n8.x4.trans.shared.b16 {%0,%1,%2,%3}, [%4];"
        : "=r"(r[0]), "=r"(r[1]), "=r"(r[2]), "=r"(r[3]) : "r"(addr));
}
__device__ __forceinline__ void mma_bf16(float* d, const uint32_t* a,
                                         uint32_t b0, uint32_t b1) {
    asm volatile(
        "mma.sync.aligned.m16n8k16.row.col.f32.bf16.bf16.f32 "
        "{%0,%1,%2,%3}, {%4,%5,%6,%7}, {%8,%9}, {%0,%1,%2,%3};"
        : "+f"(d[0]), "+f"(d[1]), "+f"(d[2]), "+f"(d[3])
        : "r"(a[0]), "r"(a[1]), "r"(a[2]), "r"(a[3]), "r"(b0), "r"(b1));
}
__device__ __forceinline__ uint32_t pack_bf(float lo, float hi) {
    bf162 v = __float22bfloat162_rn(make_float2(lo, hi));
    return *(uint32_t*)&v;
}
// fast exp via exp2 polynomial on the FMA pipe (MUFU is slow on B300)
__device__ __forceinline__ float expp(float x) {
    float y = fmaxf(x * 1.4426950408889634f, -120.f);
    float t = y + 12582912.f;
    int   e = __float_as_int(t);
    float r = t - 12582912.f;
    float f = y - r;
    float p = 1.3333558146e-3f;
    p = fmaf(p, f, 9.6181291076e-3f);
    p = fmaf(p, f, 5.5504108664e-2f);
    p = fmaf(p, f, 2.4022650696e-1f);
    p = fmaf(p, f, 6.9314718056e-1f);
    p = fmaf(p, f, 1.0f);
    float sc = __int_as_float((e - 0x4b400000 + 127) << 23);
    return p * sc;
}

__device__ __forceinline__ void store_pair(float* C, size_t off, float v0, float v1) {
    *(float2*)(C + off) = make_float2(v0, v1);
}
__device__ __forceinline__ void store_pair(bf16* C, size_t off, float v0, float v1) {
    *(bf162*)(C + off) = __float22bfloat162_rn(make_float2(v0, v1));
}

// ---------------------------------------------------------------------------
// bf16 mma GEMM: C[M,N] = A[M,K] @ B[N,K]^T (+bias, relu, residual)
// 128x256 block tile, 64-half k-chunk (144B padded rows), 3-stage cp.async,
// 8 warps (2m x 4n), warp tile 64x64.
// GATHER: A rows indirected through tokIdx (negative -> zero row).
// SCATTER: epilogue does out[tok[row]] += gate[tok] * (acc + bias).
// Empty-tile early exit when all 128 row tokens are -1.
// DUAL: additionally store results to C2 (fp32 path only).
// ---------------------------------------------------------------------------
#define BM 128
#define BN 256
#define RSTR 144
#define STAGE_B ((BM+BN)*RSTR)      // 55296 bytes
#define GEMM_SMEM (3*STAGE_B + 512)

template<typename TO, bool RELU, bool RES, bool GATHER, bool SCATTER, bool DUAL>
__global__ __launch_bounds__(256, 1) void gemm_mma(
    const bf16* __restrict__ A, const bf16* __restrict__ Bm,
    const float* __restrict__ bias, const float* __restrict__ Res,
    TO* __restrict__ C, float* __restrict__ C2, int Nld, int K,
    int rowsPerExpert, long long bExpStride, int biasExpStride,
    const int* __restrict__ tokIdx, const float* __restrict__ gate)
{
    extern __shared__ char smem[];
    const uint32_t sb0 = smem_u32(smem);
    int* stok = (int*)(smem + 3*STAGE_B);
    const int tid = threadIdx.x;
    const int wid = tid >> 5, lane = tid & 31;
    const int j8 = lane & 7, gi = lane >> 3;
    const int lr = lane >> 2, lc = lane & 3;
    const int row0 = blockIdx.y * BM, col0 = blockIdx.x * BN;
    const int expert = row0 / rowsPerExpert;
    const bf16* Bexp = Bm + (long long)expert * bExpStride;
    const float* bb  = bias + (long long)expert * biasExpStride;
    const int m0 = (wid & 1) * 64, n0 = (wid >> 1) * 64;

    const bf16* Abase = GATHER ? A : A + (size_t)row0 * K;
    const bf16* Bbase = Bexp + (size_t)col0 * K;

    if (GATHER || SCATTER) {
        int v = 0;
        if (tid < BM) {
            int t = tokIdx[row0 + tid];
            stok[tid] = t;
            v = (t >= 0);
        }
        if (!__syncthreads_or(v)) return;   // whole tile empty -> no effect
    }

    const int arow = j8 + (gi & 1) * 8;
    const int aoff = (gi >> 1) * 16;
    const int brow = j8 + (gi >> 1) * 8;
    const int boff = (gi & 1) * 16;

    float acc[4][8][4];
#pragma unroll
    for (int mt = 0; mt < 4; mt++)
#pragma unroll
        for (int t = 0; t < 8; t++)
#pragma unroll
            for (int q = 0; q < 4; q++) acc[mt][t][q] = 0.f;

    const int nch = K / 64;

    auto load_stage = [&](int s, int ch) {
        const uint32_t sa  = sb0 + (uint32_t)s * STAGE_B;
        const uint32_t sbm = sa + BM * RSTR;
        const bf16* Bcp = Bbase + ch * 64;
#pragma unroll
        for (int q = 0; q < 4; q++) {          // A: 1024 segs of 16B
            int seg = tid + 256 * q;
            int r = seg >> 3, c = seg & 7;
            if (GATHER) {
                int t = stok[r];
                uint32_t sz = (t >= 0) ? 16u : 0u;
                const bf16* srcp = Abase + (size_t)(t >= 0 ? t : 0) * K + ch * 64 + c * 8;
                cp16z(sa + (uint32_t)(r * RSTR + c * 16), srcp, sz);
            } else {
                cp16(sa + (uint32_t)(r * RSTR + c * 16),
                     Abase + (size_t)r * K + ch * 64 + c * 8);
            }
        }
#pragma unroll
        for (int q = 0; q < 8; q++) {          // B: 2048 segs of 16B
            int seg = tid + 256 * q;
            int r = seg >> 3, c = seg & 7;
            cp16(sbm + (uint32_t)(r * RSTR + c * 16), Bcp + (size_t)r * K + c * 8);
        }
    };

    load_stage(0, 0);
    asm volatile("cp.async.commit_group;");
    load_stage(1, 1);
    asm volatile("cp.async.commit_group;");

    for (int i = 0; i < nch; i++) {
        if (i + 2 < nch) load_stage((i + 2) % 3, i + 2);
        asm volatile("cp.async.commit_group;");
        asm volatile("cp.async.wait_group 2;");
        __syncthreads();

        const uint32_t sa  = sb0 + (uint32_t)(i % 3) * STAGE_B;
        const uint32_t sbm = sa + BM * RSTR;
#pragma unroll
        for (int kk = 0; kk < 4; kk++) {
            uint32_t af[4][4];
#pragma unroll
            for (int mt = 0; mt < 4; mt++)
                ldm_x4(af[mt], sa + (uint32_t)((m0 + mt * 16 + arow) * RSTR + kk * 32 + aoff));
#pragma unroll
            for (int nt = 0; nt < 4; nt++) {
                uint32_t bfr[4];
                ldm_x4(bfr, sbm + (uint32_t)((n0 + nt * 16 + brow) * RSTR + kk * 32 + boff));
#pragma unroll
                for (int mt = 0; mt < 4; mt++) {
                    mma_bf16(acc[mt][nt * 2 + 0], af[mt], bfr[0], bfr[1]);
                    mma_bf16(acc[mt][nt * 2 + 1], af[mt], bfr[2], bfr[3]);
                }
            }
        }
        __syncthreads();
    }

    // epilogue
#pragma unroll
    for (int mt = 0; mt < 4; mt++) {
        const int gr = row0 + m0 + mt * 16 + lr;
        int t0 = 0, t1 = 0;
        float g0 = 0.f, g1 = 0.f;
        if (SCATTER) {
            t0 = stok[m0 + mt * 16 + lr]; t1 = stok[m0 + mt * 16 + lr + 8];
            g0 = (t0 >= 0) ? gate[t0] : 0.f;
            g1 = (t1 >= 0) ? gate[t1] : 0.f;
        }
#pragma unroll
        for (int nt = 0; nt < 4; nt++) {
#pragma unroll
            for (int pr = 0; pr < 2; pr++) {
                const int gc = col0 + n0 + nt * 16 + pr * 8 + lc * 2;
                float* d = acc[mt][nt * 2 + pr];
                float b0 = bb[gc], b1 = bb[gc + 1];
                float v0 = d[0] + b0, v1 = d[1] + b1;
                float v2 = d[2] + b0, v3 = d[3] + b1;
                if (RELU) {
                    v0 = fmaxf(v0, 0.f); v1 = fmaxf(v1, 0.f);
                    v2 = fmaxf(v2, 0.f); v3 = fmaxf(v3, 0.f);
                }
                if (RES) {
                    float2 r0 = *(const float2*)(Res + (size_t)gr * Nld + gc);
                    float2 r1 = *(const float2*)(Res + (size_t)(gr + 8) * Nld + gc);
                    v0 += r0.x; v1 += r0.y; v2 += r1.x; v3 += r1.y;
                }
                if (SCATTER) {
                    if (t0 >= 0) {
                        float2 cur = *(float2*)((float*)C + (size_t)t0 * Nld + gc);
                        *(float2*)((float*)C + (size_t)t0 * Nld + gc) =
                            make_float2(cur.x + g0 * v0, cur.y + g0 * v1);
                    }
                    if (t1 >= 0) {
                        float2 cur = *(float2*)((float*)C + (size_t)t1 * Nld + gc);
                        *(float2*)((float*)C + (size_t)t1 * Nld + gc) =
                            make_float2(cur.x + g1 * v2, cur.y + g1 * v3);
                    }
                } else {
                    store_pair(C, (size_t)gr * Nld + gc, v0, v1);
                    store_pair(C, (size_t)(gr + 8) * Nld + gc, v2, v3);
                    if (DUAL) {
                        store_pair(C2, (size_t)gr * Nld + gc, v0, v1);
                        store_pair(C2, (size_t)(gr + 8) * Nld + gc, v2, v3);
                    }
                }
            }
        }
    }
}

// ---------------------------------------------------------------------------
// Flash attention, bf16 mma. 256 threads (8 warps), q-tile 128, k-tiles of 64.
// ---------------------------------------------------------------------------
#define AT_SMEM (18432 + 9216*4 + 512)

__global__ __launch_bounds__(256) void attn_mma(
    const bf16* __restrict__ qkv,
    const unsigned char* __restrict__ pad,
    bf16* __restrict__ outp)
{
    extern __shared__ char smem[];
    const uint32_t sQ  = smem_u32(smem);
    const uint32_t sK0 = sQ + 18432;
    const uint32_t sV0 = sK0 + 9216 * 2;
    float* mkp = (float*)(smem + 18432 + 9216 * 4);

    const int tid = threadIdx.x;
    const int wid = tid >> 5, lane = tid & 31;
    const int j8 = lane & 7, gi = lane >> 3;
    const int lc = lane & 3, lr = lane >> 2;
    const int bh = blockIdx.y, b = bh >> 4, h = bh & 15;
    const int q0 = blockIdx.x * 128;
    const size_t tokBase = (size_t)b * Sq;

    {
        const bf16* qb = qkv + (tokBase + q0) * 3072 + h * 64;
#pragma unroll
        for (int q = 0; q < 4; q++) {
            int seg = tid + 256 * q;
            int r = seg >> 3, c = seg & 7;
            cp16(sQ + (uint32_t)(r * 144 + c * 16), qb + (size_t)r * 3072 + c * 8);
        }
    }
    asm volatile("cp.async.commit_group;");

    auto prefetch = [&](int st, int kt) {
        const int k0 = kt * 64;
        const bf16* kb = qkv + (tokBase + k0) * 3072 + 1024 + h * 64;
        const bf16* vb = qkv + (tokBase + k0) * 3072 + 2048 + h * 64;
        const uint32_t sk = sK0 + (uint32_t)st * 9216, sv = sV0 + (uint32_t)st * 9216;
#pragma unroll
        for (int q = 0; q < 2; q++) {
            int seg = tid + 256 * q;
            int r = seg >> 3, c = seg & 7;
            cp16(sk + (uint32_t)(r * 144 + c * 16), kb + (size_t)r * 3072 + c * 8);
            cp16(sv + (uint32_t)(r * 144 + c * 16), vb + (size_t)r * 3072 + c * 8);
        }
        if (tid < 64) mkp[st * 64 + tid] = pad[tokBase + k0 + tid] ? -1e9f : 0.f;
    };

    prefetch(0, 0);
    asm volatile("cp.async.commit_group;");
    asm volatile("cp.async.wait_group 1;");
    __syncthreads();

    const int arow = j8 + (gi & 1) * 8, aoff = (gi >> 1) * 16;
    const int brow = j8 + (gi >> 1) * 8, boff = (gi & 1) * 16;

    uint32_t qa[4][4];
#pragma unroll
    for (int kd = 0; kd < 4; kd++)
        ldm_x4(qa[kd], sQ + (uint32_t)((wid * 16 + arow) * 144 + kd * 32 + aoff));

    float m0v = -1e30f, m1v = -1e30f, l0 = 0.f, l1 = 0.f;
    float o[8][4];
#pragma unroll
    for (int dt = 0; dt < 8; dt++)
#pragma unroll
        for (int q = 0; q < 4; q++) o[dt][q] = 0.f;

    for (int kt = 0; kt < Sq / 64; kt++) {
        const int st = kt & 1;
        if (kt + 1 < Sq / 64) prefetch(st ^ 1, kt + 1);
        asm volatile("cp.async.commit_group;");
        asm volatile("cp.async.wait_group 1;");
        __syncthreads();

        const uint32_t sk = sK0 + (uint32_t)st * 9216, sv = sV0 + (uint32_t)st * 9216;
        float s[8][4];
#pragma unroll
        for (int j = 0; j < 8; j++)
#pragma unroll
            for (int q = 0; q < 4; q++) s[j][q] = 0.f;

#pragma unroll
        for (int jp = 0; jp < 4; jp++) {
#pragma unroll
            for (int kd = 0; kd < 4; kd++) {
                uint32_t bfr[4];
                ldm_x4(bfr, sk + (uint32_t)((jp * 16 + brow) * 144 + kd * 32 + boff));
                mma_bf16(s[2 * jp],     qa[kd], bfr[0], bfr[1]);
                mma_bf16(s[2 * jp + 1], qa[kd], bfr[2], bfr[3]);
            }
        }

        float rmax0 = -1e30f, rmax1 = -1e30f;
#pragma unroll
        for (int j = 0; j < 8; j++) {
            float mka = mkp[st * 64 + j * 8 + 2 * lc];
            float mkb = mkp[st * 64 + j * 8 + 2 * lc + 1];
            s[j][0] = fmaf(s[j][0], 0.125f, mka);
            s[j][1] = fmaf(s[j][1], 0.125f, mkb);
            s[j][2] = fmaf(s[j][2], 0.125f, mka);
            s[j][3] = fmaf(s[j][3], 0.125f, mkb);
            rmax0 = fmaxf(rmax0, fmaxf(s[j][0], s[j][1]));
            rmax1 = fmaxf(rmax1, fmaxf(s[j][2], s[j][3]));
        }
        rmax0 = fmaxf(rmax0, __shfl_xor_sync(0xffffffffu, rmax0, 1));
        rmax0 = fmaxf(rmax0, __shfl_xor_sync(0xffffffffu, rmax0, 2));
        rmax1 = fmaxf(rmax1, __shfl_xor_sync(0xffffffffu, rmax1, 1));
        rmax1 = fmaxf(rmax1, __shfl_xor_sync(0xffffffffu, rmax1, 2));
        float nm0 = fmaxf(m0v, rmax0), nm1 = fmaxf(m1v, rmax1);
        float c0 = expp(m0v - nm0), c1 = expp(m1v - nm1);
        m0v = nm0; m1v = nm1;
        float rs0 = 0.f, rs1 = 0.f;
#pragma unroll
        for (int j = 0; j < 8; j++) {
            s[j][0] = expp(s[j][0] - nm0); s[j][1] = expp(s[j][1] - nm0);
            s[j][2] = expp(s[j][2] - nm1); s[j][3] = expp(s[j][3] - nm1);
            rs0 += s[j][0] + s[j][1];
            rs1 += s[j][2] + s[j][3];
        }
        rs0 += __shfl_xor_sync(0xffffffffu, rs0, 1);
        rs0 += __shfl_xor_sync(0xffffffffu, rs0, 2);
        rs1 += __shfl_xor_sync(0xffffffffu, rs1, 1);
        rs1 += __shfl_xor_sync(0xffffffffu, rs1, 2);
        l0 = l0 * c0 + rs0; l1 = l1 * c1 + rs1;
#pragma unroll
        for (int dt = 0; dt < 8; dt++) {
            o[dt][0] *= c0; o[dt][1] *= c0; o[dt][2] *= c1; o[dt][3] *= c1;
        }

        uint32_t pa[4][4];
#pragma unroll
        for (int t = 0; t < 4; t++) {
            pa[t][0] = pack_bf(s[2 * t][0],     s[2 * t][1]);
            pa[t][1] = pack_bf(s[2 * t][2],     s[2 * t][3]);
            pa[t][2] = pack_bf(s[2 * t + 1][0], s[2 * t + 1][1]);
            pa[t][3] = pack_bf(s[2 * t + 1][2], s[2 * t + 1][3]);
        }
#pragma unroll
        for (int t = 0; t < 4; t++) {
#pragma unroll
            for (int dp = 0; dp < 4; dp++) {
                uint32_t vf[4];
                ldm_x4t(vf, sv + (uint32_t)((t * 16 + arow) * 144 + dp * 32 + aoff));
                mma_bf16(o[2 * dp],     pa[t], vf[0], vf[1]);
                mma_bf16(o[2 * dp + 1], pa[t], vf[2], vf[3]);
            }
        }
        __syncthreads();
    }

    float inv0 = 1.f / l0, inv1 = 1.f / l1;
    const int rg = q0 + wid * 16 + lr;
    bf16* ob = outp + (tokBase + rg) * Dm + h * 64;
#pragma unroll
    for (int dt = 0; dt < 8; dt++) {
        *(bf162*)(ob + dt * 8 + 2 * lc) =
            __float22bfloat162_rn(make_float2(o[dt][0] * inv0, o[dt][1] * inv0));
        *(bf162*)(ob + (size_t)8 * Dm + dt * 8 + 2 * lc) =
            __float22bfloat162_rn(make_float2(o[dt][2] * inv1, o[dt][3] * inv1));
    }
}

// ---------------------------------------------------------------------------
// LayerNorm (bf16 out, for LN1)
// ---------------------------------------------------------------------------
__global__ __launch_bounds__(256) void ln_kernel(const float* __restrict__ in,
                                                 const float* __restrict__ g,
                                                 const float* __restrict__ b,
                                                 bf16* __restrict__ out)
{
    int n = blockIdx.x, tid = threadIdx.x;
    float4 v = ((const float4*)(in + (size_t)n*Dm))[tid];
    float s  = v.x+v.y+v.z+v.w;
    float s2 = v.x*v.x+v.y*v.y+v.z*v.z+v.w*v.w;
    __shared__ float r1[256], r2[256];
    r1[tid]=s; r2[tid]=s2; __syncthreads();
    for (int st=128; st; st>>=1) {
        if (tid<st) { r1[tid]+=r1[tid+st]; r2[tid]+=r2[tid+st]; }
        __syncthreads();
    }
    float mean = r1[0]*(1.0f/Dm);
    float var  = r2[0]*(1.0f/Dm) - mean*mean;
    float rstd = rsqrtf(var + 1e-5f);
    float4 gg = ((const float4*)g)[tid];
    float4 bb = ((const float4*)b)[tid];
    float o0 = (v.x-mean)*rstd*gg.x + bb.x;
    float o1 = (v.y-mean)*rstd*gg.y + bb.y;
    float o2 = (v.z-mean)*rstd*gg.z + bb.z;
    float o3 = (v.w-mean)*rstd*gg.w + bb.w;
    size_t base = (size_t)n*Dm + tid*4;
    store_pair(out, base, o0, o1);
    store_pair(out, base + 2, o2, o3);
}

// ---------------------------------------------------------------------------
// LN2 + router fused
// ---------------------------------------------------------------------------
__global__ __launch_bounds__(256) void ln2_router(const float* __restrict__ in,
                                                  const float* __restrict__ g,
                                                  const float* __restrict__ b,
                                                  bf16* __restrict__ outh,
                                                  const float* __restrict__ rw,
                                                  const float* __restrict__ rb,
                                                  const unsigned char* __restrict__ pad)
{
    int n = blockIdx.x, tid = threadIdx.x;
    __shared__ float r1[256], r2[256];
    __shared__ float xs[1024];
    __shared__ float lg[8];
    float4 v = ((const float4*)(in + (size_t)n*Dm))[tid];
    float s  = v.x+v.y+v.z+v.w;
    float s2 = v.x*v.x+v.y*v.y+v.z*v.z+v.w*v.w;
    r1[tid]=s; r2[tid]=s2; __syncthreads();
    for (int st=128; st; st>>=1) {
        if (tid<st) { r1[tid]+=r1[tid+st]; r2[tid]+=r2[tid+st]; }
        __syncthreads();
    }
    float mean = r1[0]*(1.0f/Dm);
    float var  = r2[0]*(1.0f/Dm) - mean*mean;
    float rstd = rsqrtf(var + 1e-5f);
    float4 gg = ((const float4*)g)[tid];
    float4 bb = ((const float4*)b)[tid];
    float4 o;
    o.x = (v.x-mean)*rstd*gg.x + bb.x;
    o.y = (v.y-mean)*rstd*gg.y + bb.y;
    o.z = (v.z-mean)*rstd*gg.z + bb.z;
    o.w = (v.w-mean)*rstd*gg.w + bb.w;
    bf162* hp = (bf162*)(outh + (size_t)n*Dm);
    hp[tid*2]   = __float22bfloat162_rn(make_float2(o.x, o.y));
    hp[tid*2+1] = __float22bfloat162_rn(make_float2(o.z, o.w));
    ((float4*)xs)[tid] = o;
    __syncthreads();
    int w = tid >> 5, lane = tid & 31;
    float acc = 0.f;
    for (int i = lane; i < 1024; i += 32) acc += xs[i] * rw[i*8 + w];
    for (int off=16; off; off>>=1) acc += __shfl_xor_sync(0xffffffffu, acc, off);
    if (lane == 0) lg[w] = acc + rb[w];
    __syncthreads();
    if (tid == 0) {
        float mx = lg[0]; int ei = 0;
        for (int e=1;e<8;e++) if (lg[e] > mx) { mx = lg[e]; ei = e; }
        float pr[8], se = 0.f;
        for (int e=0;e<8;e++) { pr[e] = expf(lg[e]-mx); se += pr[e]; }
        float inv = 1.f/se;
        bool valid = (pad[n] == 0);
        float tm = valid ? 1.f : 0.f;
        for (int e=0;e<8;e++) g_probs[n*8+e] = pr[e]*inv*tm;
        g_gate[n] = pr[ei]*inv;
        g_eidx[n] = ei;
        float lse = mx + logf(se);
        g_zterm[n] = lse*lse*tm;
    }
}

// ---------------------------------------------------------------------------
// Weight prep
// ---------------------------------------------------------------------------
__global__ __launch_bounds__(256) void bf16_copy(const float* __restrict__ in,
                                                 bf16* __restrict__ out, int n4)
{
    int i = blockIdx.x*256 + threadIdx.x;
    if (i < n4) {
        float4 v = ((const float4*)in)[i];
        ((bf162*)out)[i*2]   = __float22bfloat162_rn(make_float2(v.x, v.y));
        ((bf162*)out)[i*2+1] = __float22bfloat162_rn(make_float2(v.z, v.w));
    }
}

__global__ __launch_bounds__(256) void transpose_bf16(const float* __restrict__ in,
                                                      bf16* __restrict__ out,
                                                      int R, int Cc)
{
    __shared__ float t[32][33];
    int e = blockIdx.z;
    const float* ip = in  + (size_t)e*R*Cc;
    bf16* op        = out + (size_t)e*R*Cc;
    int c0 = blockIdx.x*32, r0 = blockIdx.y*32;
    int tx = threadIdx.x, ty = threadIdx.y;
#pragma unroll
    for (int j=0;j<32;j+=8)
        t[ty+j][tx] = ip[(size_t)(r0+ty+j)*Cc + c0+tx];
    __syncthreads();
#pragma unroll
    for (int j=0;j<32;j+=8)
        op[(size_t)(c0+ty+j)*R + r0+tx] = __float2bfloat16_rn(t[tx][ty+j]);
}

// ---------------------------------------------------------------------------
// Routing scan: smem-staged, warp 0 does exact token-order scan.
// ---------------------------------------------------------------------------
__global__ __launch_bounds__(1024) void scan_kernel(const unsigned char* __restrict__ pad)
{
    __shared__ unsigned char sc[Ntok];
    __shared__ int base[8];
    int tid = threadIdx.x;
    for (int i = tid; i < SLOTS; i += 1024) g_tok[i] = -1;
    for (int i = tid; i < Ntok; i += 1024)
        sc[i] = (unsigned char)(g_eidx[i] | (pad[i] ? 0 : 16));
    if (tid < 8) base[tid] = 0;
    __syncthreads();
    if (tid < 32) {
        int lane = tid;
        for (int c = 0; c < Ntok/32; c++) {
            int i = c*32 + lane;
            int code = sc[i];
            int e = code & 7;
            bool valid = (code & 16) != 0;
            unsigned peers = __match_any_sync(0xffffffffu, e);
            unsigned vmask = __ballot_sync(0xffffffffu, valid);
            unsigned pv = peers & vmask;
            int myrank = __popc(pv & ((1u << lane) - 1u));
            int b0 = base[e];
            __syncwarp();
            int pos = b0 + myrank;
            bool keep = valid && (pos < CAP);
            if (keep) g_tok[e*CAP + pos] = i;
            if (valid && lane == (__ffs(pv) - 1)) base[e] = b0 + __popc(pv);
            __syncwarp();
        }
        if (lane < 8) g_cnt[lane] = base[lane];
    }
}

// ---------------------------------------------------------------------------
// Loss reduction
// ---------------------------------------------------------------------------
__global__ __launch_bounds__(256) void loss_kernel(const unsigned char* __restrict__ pad,
                                                   float* __restrict__ out)
{
    int tid = threadIdx.x;
    float zs = 0.f, ps[8];
    int cnt = 0;
#pragma unroll
    for (int e=0;e<8;e++) ps[e]=0.f;
    for (int n = tid; n < Ntok; n += 256) {
        if (pad[n] == 0) cnt++;
        zs += g_zterm[n];
#pragma unroll
        for (int e=0;e<8;e++) ps[e] += g_probs[n*8+e];
    }
    __shared__ float red[256];
    __shared__ float res[10];
    float vals[10];
    vals[0] = (float)cnt; vals[1] = zs;
    for (int e=0;e<8;e++) vals[2+e] = ps[e];
    for (int q=0;q<10;q++) {
        red[tid] = vals[q]; __syncthreads();
        for (int st=128; st; st>>=1) {
            if (tid < st) red[tid] += red[tid+st];
            __syncthreads();
        }
        if (tid == 0) res[q] = red[0];
        __syncthreads();
    }
    if (tid == 0) {
        float denom = fmaxf(res[0], 1.f);
        float lb = 0.f;
        for (int e=0;e<8;e++) lb += ((float)g_cnt[e]/denom) * (res[2+e]/denom);
        lb *= (float)Ee;
        out[(size_t)Ntok*Dm]     = lb;
        out[(size_t)Ntok*Dm + 1] = res[1]/denom;
    }
}

// ---------------------------------------------------------------------------
// Launch
// ---------------------------------------------------------------------------
extern "C" void kernel_launch(void* const* d_in, const int* in_sizes, int n_in,
                              void* d_out, int out_size)
{
    const float* src  = (const float*)d_in[0];
    const unsigned char* pad = (const unsigned char*)d_in[1];
    const float* ln1g = (const float*)d_in[2];
    const float* ln1b = (const float*)d_in[3];
    const float* ipw  = (const float*)d_in[4];
    const float* ipb  = (const float*)d_in[5];
    const float* opw  = (const float*)d_in[6];
    const float* opb  = (const float*)d_in[7];
    const float* ln2g = (const float*)d_in[8];
    const float* ln2b = (const float*)d_in[9];
    const float* rw   = (const float*)d_in[10];
    const float* rb   = (const float*)d_in[11];
    const float* w1   = (const float*)d_in[12];
    const float* b1   = (const float*)d_in[13];
    const float* w2   = (const float*)d_in[14];
    const float* b2   = (const float*)d_in[15];
    float* out = (float*)d_out;

    bf16 *xln, *qkv, *attn, *x2b, *hb, *ipw16, *opw16, *w1t, *w2t;
    float *src1, *gate;
    int *tok;
    cudaGetSymbolAddress((void**)&xln,  g_xln);
    cudaGetSymbolAddress((void**)&qkv,  g_qkv);
    cudaGetSymbolAddress((void**)&attn, g_attn);
    cudaGetSymbolAddress((void**)&src1, g_src1);
    cudaGetSymbolAddress((void**)&x2b,  g_x2b);
    cudaGetSymbolAddress((void**)&hb,   g_hbuf);
    cudaGetSymbolAddress((void**)&ipw16, g_ipw16);
    cudaGetSymbolAddress((void**)&opw16, g_opw16);
    cudaGetSymbolAddress((void**)&w1t,  g_w1t);
    cudaGetSymbolAddress((void**)&w2t,  g_w2t);
    cudaGetSymbolAddress((void**)&tok,  g_tok);
    cudaGetSymbolAddress((void**)&gate, g_gate);

    // Lazily-created side stream + events (host objects; no device memory).
    static cudaStream_t s2 = nullptr;
    static cudaEvent_t ev0 = nullptr, ev1 = nullptr, ev2 = nullptr, ev3 = nullptr;
    if (!s2) {
        cudaStreamCreateWithFlags(&s2, cudaStreamNonBlocking);
        cudaEventCreateWithFlags(&ev0, cudaEventDisableTiming);
        cudaEventCreateWithFlags(&ev1, cudaEventDisableTiming);
        cudaEventCreateWithFlags(&ev2, cudaEventDisableTiming);
        cudaEventCreateWithFlags(&ev3, cudaEventDisableTiming);
    }

    cudaFuncSetAttribute(attn_mma, cudaFuncAttributeMaxDynamicSharedMemorySize, AT_SMEM);
    cudaFuncSetAttribute(gemm_mma<bf16,false,false,false,false,false>, cudaFuncAttributeMaxDynamicSharedMemorySize, GEMM_SMEM);
    cudaFuncSetAttribute(gemm_mma<float,false,true,false,false,true>,  cudaFuncAttributeMaxDynamicSharedMemorySize, GEMM_SMEM);
    cudaFuncSetAttribute(gemm_mma<bf16,true,false,true,false,false>,   cudaFuncAttributeMaxDynamicSharedMemorySize, GEMM_SMEM);
    cudaFuncSetAttribute(gemm_mma<float,false,false,false,true,false>, cudaFuncAttributeMaxDynamicSharedMemorySize, GEMM_SMEM);

    // Fork: side stream does the weight prep not needed until out_proj/FFN.
    cudaEventRecord(ev0, 0);
    cudaStreamWaitEvent(s2, ev0, 0);
    bf16_copy<<<(Dm*Dm/4 + 255)/256, 256, 0, s2>>>(opw, opw16, Dm*Dm/4);
    transpose_bf16<<<dim3(Ff/32, Dm/32, Ee), dim3(32,8), 0, s2>>>(w1, w1t, Dm, Ff);
    transpose_bf16<<<dim3(Dm/32, Ff/32, Ee), dim3(32,8), 0, s2>>>(w2, w2t, Ff, Dm);
    cudaEventRecord(ev1, s2);

    // Main stream: ipw copy (needed by QKV) + compute chain.
    bf16_copy<<<(3*Dm*Dm/4 + 255)/256, 256>>>(ipw, ipw16, 3*Dm*Dm/4);
    // 1. LN1 -> bf16
    ln_kernel<<<Ntok, 256>>>(src, ln1g, ln1b, xln);
    // 2. QKV -> bf16
    gemm_mma<bf16,false,false,false,false,false><<<dim3(3072/BN, Ntok/BM), 256, GEMM_SMEM>>>(
        xln, ipw16, ipb, nullptr, qkv, nullptr, 3072, 1024, 1<<30, 0, 0, nullptr, nullptr);
    // 3. Attention -> bf16
    attn_mma<<<dim3(Sq/128, Bc*Hh), 256, AT_SMEM>>>(qkv, pad, attn);
    // Join prep before out_proj (opw16) / FFN (w1t/w2t).
    cudaStreamWaitEvent(0, ev1, 0);
    // 4. out_proj + residual(src) -> src1 AND out (dual store)
    gemm_mma<float,false,true,false,false,true><<<dim3(1024/BN, Ntok/BM), 256, GEMM_SMEM>>>(
        attn, opw16, opb, src, src1, out, 1024, 1024, 1<<30, 0, 0, nullptr, nullptr);
    // 5. LN2 + router fused
    ln2_router<<<Ntok, 256>>>(src1, ln2g, ln2b, x2b, rw, rb, pad);
    // 6. Scan
    scan_kernel<<<1, 1024>>>(pad);
    // Fork: loss depends only on router outputs + g_cnt; writes out tail only.
    cudaEventRecord(ev2, 0);
    cudaStreamWaitEvent(s2, ev2, 0);
    loss_kernel<<<1, 256, 0, s2>>>(pad, out);
    cudaEventRecord(ev3, s2);
    // 7. FFN1 (gathered A, relu, empty-tile skip) -> bf16 hbuf
    gemm_mma<bf16,true,false,true,false,false><<<dim3(Ff/BN, SLOTS/BM), 256, GEMM_SMEM>>>(
        x2b, w1t, b1, nullptr, hb, nullptr, Ff, 1024, CAP, (long long)Dm*Ff, Ff, tok, nullptr);
    // 8. FFN2 (scatter-add into out with gate, empty-tile skip)
    gemm_mma<float,false,false,false,true,false><<<dim3(Dm/BN, SLOTS/BM), 256, GEMM_SMEM>>>(
        hb, w2t, b2, nullptr, out, nullptr, Dm, Ff, CAP, (long long)Ff*Dm, Dm, tok, gate);
    // Join loss back into main stream.
    cudaStreamWaitEvent(0, ev3, 0);
}

// round 9
// speedup vs baseline: 6.6935x; 1.0453x over previous
#include <cuda_runtime.h>
#include <cuda_bf16.h>
#include <math.h>
#include <stdint.h>

// ---------------------------------------------------------------------------
// Problem constants
// ---------------------------------------------------------------------------
#define Bc   4
#define Sq   2048
#define Dm   1024
#define Hh   16
#define Ee   8
#define Ff   4096
#define Ntok (Bc*Sq)          // 8192
#define CAP  1280
#define SLOTS (Ee*CAP)        // 10240

typedef __nv_bfloat16 bf16;
typedef __nv_bfloat162 bf162;

// ---------------------------------------------------------------------------
// Device scratch
// ---------------------------------------------------------------------------
__device__ bf16  g_xln [Ntok*Dm];
__device__ bf16  g_qkv [Ntok*3*Dm];
__device__ bf16  g_attn[Ntok*Dm];
__device__ float g_src1[Ntok*Dm];
__device__ bf16  g_x2b [Ntok*Dm];
__device__ bf16  g_hbuf[(size_t)SLOTS*Ff];
__device__ float g_probs[Ntok*Ee];
__device__ float g_zterm[Ntok];
__device__ float g_gate [Ntok];
__device__ int   g_eidx [Ntok];
__device__ int   g_tok  [SLOTS];
__device__ int   g_cnt  [Ee];
// bf16 weight copies / transposes ([N,K] layouts)
__device__ bf16 g_ipw16[3*Dm*Dm];
__device__ bf16 g_opw16[Dm*Dm];
__device__ bf16 g_w1t [(size_t)Ee*Ff*Dm];   // [E][F][D]
__device__ bf16 g_w2t [(size_t)Ee*Dm*Ff];   // [E][D][F]

// ---------------------------------------------------------------------------
// Helpers
// ---------------------------------------------------------------------------
__device__ __forceinline__ uint32_t smem_u32(const void* p) {
    uint32_t a;
    asm("{ .reg .u64 t; cvta.to.shared.u64 t, %1; cvt.u32.u64 %0, t; }"
        : "=r"(a) : "l"(p));
    return a;
}
__device__ __forceinline__ void cp16(uint32_t dst, const void* src) {
    asm volatile("cp.async.cg.shared.global [%0], [%1], 16;" :: "r"(dst), "l"(src));
}
__device__ __forceinline__ void cp16z(uint32_t dst, const void* src, uint32_t sz) {
    asm volatile("cp.async.cg.shared.global [%0], [%1], 16, %2;"
                 :: "r"(dst), "l"(src), "r"(sz));
}
__device__ __forceinline__ void ldm_x4(uint32_t* r, uint32_t addr) {
    asm volatile("ldmatrix.sync.aligned.m8n8.x4.shared.b16 {%0,%1,%2,%3}, [%4];"
        : "=r"(r[0]), "=r"(r[1]), "=r"(r[2]), "=r"(r[3]) : "r"(addr));
}
__device__ __forceinline__ void ldm_x4t(uint32_t* r, uint32_t addr) {
    asm volatile("ldmatrix.sync.aligned.m8n8.x4.trans.shared.b16 {%0,%1,%2,%3}, [%4];"
        : "=r"(r[0]), "=r"(r[1]), "=r"(r[2]), "=r"(r[3]) : "r"(addr));
}
__device__ __forceinline__ void mma_bf16(float* d, const uint32_t* a,
                                         uint32_t b0, uint32_t b1) {
    asm volatile(
        "mma.sync.aligned.m16n8k16.row.col.f32.bf16.bf16.f32 "
        "{%0,%1,%2,%3}, {%4,%5,%6,%7}, {%8,%9}, {%0,%1,%2,%3};"
        : "+f"(d[0]), "+f"(d[1]), "+f"(d[2]), "+f"(d[3])
        : "r"(a[0]), "r"(a[1]), "r"(a[2]), "r"(a[3]), "r"(b0), "r"(b1));
}
__device__ __forceinline__ uint32_t pack_bf(float lo, float hi) {
    bf162 v = __float22bfloat162_rn(make_float2(lo, hi));
    return *(uint32_t*)&v;
}
// fast exp via exp2 polynomial on the FMA pipe (MUFU is slow on B300)
__device__ __forceinline__ float expp(float x) {
    float y = fmaxf(x * 1.4426950408889634f, -120.f);
    float t = y + 12582912.f;
    int   e = __float_as_int(t);
    float r = t - 12582912.f;
    float f = y - r;
    float p = 1.3333558146e-3f;
    p = fmaf(p, f, 9.6181291076e-3f);
    p = fmaf(p, f, 5.5504108664e-2f);
    p = fmaf(p, f, 2.4022650696e-1f);
    p = fmaf(p, f, 6.9314718056e-1f);
    p = fmaf(p, f, 1.0f);
    float sc = __int_as_float((e - 0x4b400000 + 127) << 23);
    return p * sc;
}

__device__ __forceinline__ void store_pair(float* C, size_t off, float v0, float v1) {
    *(float2*)(C + off) = make_float2(v0, v1);
}
__device__ __forceinline__ void store_pair(bf16* C, size_t off, float v0, float v1) {
    *(bf162*)(C + off) = __float22bfloat162_rn(make_float2(v0, v1));
}

// ---------------------------------------------------------------------------
// bf16 mma GEMM: C[M,N] = A[M,K] @ B[N,K]^T (+bias, relu, residual)
// 128x256 block tile, 64-half k-chunk (144B padded rows), 3-stage cp.async,
// 8 warps (2m x 4n), warp tile 64x64. ONE __syncthreads per k-chunk:
//   wait_group(own) -> sync(visibility + reader handoff) -> load next -> mma.
// ---------------------------------------------------------------------------
#define BM 128
#define BN 256
#define RSTR 144
#define STAGE_B ((BM+BN)*RSTR)      // 55296 bytes
#define GEMM_SMEM (3*STAGE_B + 512)

template<typename TO, bool RELU, bool RES, bool GATHER, bool SCATTER, bool DUAL>
__global__ __launch_bounds__(256, 1) void gemm_mma(
    const bf16* __restrict__ A, const bf16* __restrict__ Bm,
    const float* __restrict__ bias, const float* __restrict__ Res,
    TO* __restrict__ C, float* __restrict__ C2, int Nld, int K,
    int rowsPerExpert, long long bExpStride, int biasExpStride,
    const int* __restrict__ tokIdx, const float* __restrict__ gate)
{
    extern __shared__ char smem[];
    const uint32_t sb0 = smem_u32(smem);
    int* stok = (int*)(smem + 3*STAGE_B);
    const int tid = threadIdx.x;
    const int wid = tid >> 5, lane = tid & 31;
    const int j8 = lane & 7, gi = lane >> 3;
    const int lr = lane >> 2, lc = lane & 3;
    const int row0 = blockIdx.y * BM, col0 = blockIdx.x * BN;
    const int expert = row0 / rowsPerExpert;
    const bf16* Bexp = Bm + (long long)expert * bExpStride;
    const float* bb  = bias + (long long)expert * biasExpStride;
    const int m0 = (wid & 1) * 64, n0 = (wid >> 1) * 64;

    const bf16* Abase = GATHER ? A : A + (size_t)row0 * K;
    const bf16* Bbase = Bexp + (size_t)col0 * K;

    if (GATHER || SCATTER) {
        int v = 0;
        if (tid < BM) {
            int t = tokIdx[row0 + tid];
            stok[tid] = t;
            v = (t >= 0);
        }
        if (!__syncthreads_or(v)) return;   // whole tile empty -> no effect
    }

    const int arow = j8 + (gi & 1) * 8;
    const int aoff = (gi >> 1) * 16;
    const int brow = j8 + (gi >> 1) * 8;
    const int boff = (gi & 1) * 16;

    float acc[4][8][4];
#pragma unroll
    for (int mt = 0; mt < 4; mt++)
#pragma unroll
        for (int t = 0; t < 8; t++)
#pragma unroll
            for (int q = 0; q < 4; q++) acc[mt][t][q] = 0.f;

    const int nch = K / 64;

    auto load_stage = [&](int s, int ch) {
        const uint32_t sa  = sb0 + (uint32_t)s * STAGE_B;
        const uint32_t sbm = sa + BM * RSTR;
        const bf16* Bcp = Bbase + ch * 64;
#pragma unroll
        for (int q = 0; q < 4; q++) {          // A: 1024 segs of 16B
            int seg = tid + 256 * q;
            int r = seg >> 3, c = seg & 7;
            if (GATHER) {
                int t = stok[r];
                uint32_t sz = (t >= 0) ? 16u : 0u;
                const bf16* srcp = Abase + (size_t)(t >= 0 ? t : 0) * K + ch * 64 + c * 8;
                cp16z(sa + (uint32_t)(r * RSTR + c * 16), srcp, sz);
            } else {
                cp16(sa + (uint32_t)(r * RSTR + c * 16),
                     Abase + (size_t)r * K + ch * 64 + c * 8);
            }
        }
#pragma unroll
        for (int q = 0; q < 8; q++) {          // B: 2048 segs of 16B
            int seg = tid + 256 * q;
            int r = seg >> 3, c = seg & 7;
            cp16(sbm + (uint32_t)(r * RSTR + c * 16), Bcp + (size_t)r * K + c * 8);
        }
    };

    load_stage(0, 0);
    asm volatile("cp.async.commit_group;");
    load_stage(1, 1);
    asm volatile("cp.async.commit_group;");

    for (int i = 0; i < nch; i++) {
        // own chunk-i copies complete (pending: chunk i+1 only)
        asm volatile("cp.async.wait_group 1;");
        // all threads' waits done -> chunk i visible; stage (i+2)%3 readers done
        __syncthreads();
        if (i + 2 < nch) load_stage((i + 2) % 3, i + 2);
        asm volatile("cp.async.commit_group;");

        const uint32_t sa  = sb0 + (uint32_t)(i % 3) * STAGE_B;
        const uint32_t sbm = sa + BM * RSTR;
#pragma unroll
        for (int kk = 0; kk < 4; kk++) {
            uint32_t af[4][4];
#pragma unroll
            for (int mt = 0; mt < 4; mt++)
                ldm_x4(af[mt], sa + (uint32_t)((m0 + mt * 16 + arow) * RSTR + kk * 32 + aoff));
#pragma unroll
            for (int nt = 0; nt < 4; nt++) {
                uint32_t bfr[4];
                ldm_x4(bfr, sbm + (uint32_t)((n0 + nt * 16 + brow) * RSTR + kk * 32 + boff));
#pragma unroll
                for (int mt = 0; mt < 4; mt++) {
                    mma_bf16(acc[mt][nt * 2 + 0], af[mt], bfr[0], bfr[1]);
                    mma_bf16(acc[mt][nt * 2 + 1], af[mt], bfr[2], bfr[3]);
                }
            }
        }
    }

    // epilogue
#pragma unroll
    for (int mt = 0; mt < 4; mt++) {
        const int gr = row0 + m0 + mt * 16 + lr;
        int t0 = 0, t1 = 0;
        float g0 = 0.f, g1 = 0.f;
        if (SCATTER) {
            t0 = stok[m0 + mt * 16 + lr]; t1 = stok[m0 + mt * 16 + lr + 8];
            g0 = (t0 >= 0) ? gate[t0] : 0.f;
            g1 = (t1 >= 0) ? gate[t1] : 0.f;
        }
#pragma unroll
        for (int nt = 0; nt < 4; nt++) {
#pragma unroll
            for (int pr = 0; pr < 2; pr++) {
                const int gc = col0 + n0 + nt * 16 + pr * 8 + lc * 2;
                float* d = acc[mt][nt * 2 + pr];
                float b0 = bb[gc], b1 = bb[gc + 1];
                float v0 = d[0] + b0, v1 = d[1] + b1;
                float v2 = d[2] + b0, v3 = d[3] + b1;
                if (RELU) {
                    v0 = fmaxf(v0, 0.f); v1 = fmaxf(v1, 0.f);
                    v2 = fmaxf(v2, 0.f); v3 = fmaxf(v3, 0.f);
                }
                if (RES) {
                    float2 r0 = *(const float2*)(Res + (size_t)gr * Nld + gc);
                    float2 r1 = *(const float2*)(Res + (size_t)(gr + 8) * Nld + gc);
                    v0 += r0.x; v1 += r0.y; v2 += r1.x; v3 += r1.y;
                }
                if (SCATTER) {
                    if (t0 >= 0) {
                        float2 cur = *(float2*)((float*)C + (size_t)t0 * Nld + gc);
                        *(float2*)((float*)C + (size_t)t0 * Nld + gc) =
                            make_float2(cur.x + g0 * v0, cur.y + g0 * v1);
                    }
                    if (t1 >= 0) {
                        float2 cur = *(float2*)((float*)C + (size_t)t1 * Nld + gc);
                        *(float2*)((float*)C + (size_t)t1 * Nld + gc) =
                            make_float2(cur.x + g1 * v2, cur.y + g1 * v3);
                    }
                } else {
                    store_pair(C, (size_t)gr * Nld + gc, v0, v1);
                    store_pair(C, (size_t)(gr + 8) * Nld + gc, v2, v3);
                    if (DUAL) {
                        store_pair(C2, (size_t)gr * Nld + gc, v0, v1);
                        store_pair(C2, (size_t)(gr + 8) * Nld + gc, v2, v3);
                    }
                }
            }
        }
    }
}

// ---------------------------------------------------------------------------
// Flash attention, bf16 mma. 256 threads (8 warps), q-tile 128, k-tiles of 64.
// ONE __syncthreads per k-tile (wait -> sync -> prefetch -> compute).
// ---------------------------------------------------------------------------
#define AT_SMEM (18432 + 9216*4 + 512)

__global__ __launch_bounds__(256) void attn_mma(
    const bf16* __restrict__ qkv,
    const unsigned char* __restrict__ pad,
    bf16* __restrict__ outp)
{
    extern __shared__ char smem[];
    const uint32_t sQ  = smem_u32(smem);
    const uint32_t sK0 = sQ + 18432;
    const uint32_t sV0 = sK0 + 9216 * 2;
    float* mkp = (float*)(smem + 18432 + 9216 * 4);

    const int tid = threadIdx.x;
    const int wid = tid >> 5, lane = tid & 31;
    const int j8 = lane & 7, gi = lane >> 3;
    const int lc = lane & 3, lr = lane >> 2;
    const int bh = blockIdx.y, b = bh >> 4, h = bh & 15;
    const int q0 = blockIdx.x * 128;
    const size_t tokBase = (size_t)b * Sq;

    {
        const bf16* qb = qkv + (tokBase + q0) * 3072 + h * 64;
#pragma unroll
        for (int q = 0; q < 4; q++) {
            int seg = tid + 256 * q;
            int r = seg >> 3, c = seg & 7;
            cp16(sQ + (uint32_t)(r * 144 + c * 16), qb + (size_t)r * 3072 + c * 8);
        }
    }
    asm volatile("cp.async.commit_group;");

    auto prefetch = [&](int st, int kt) {
        const int k0 = kt * 64;
        const bf16* kb = qkv + (tokBase + k0) * 3072 + 1024 + h * 64;
        const bf16* vb = qkv + (tokBase + k0) * 3072 + 2048 + h * 64;
        const uint32_t sk = sK0 + (uint32_t)st * 9216, sv = sV0 + (uint32_t)st * 9216;
#pragma unroll
        for (int q = 0; q < 2; q++) {
            int seg = tid + 256 * q;
            int r = seg >> 3, c = seg & 7;
            cp16(sk + (uint32_t)(r * 144 + c * 16), kb + (size_t)r * 3072 + c * 8);
            cp16(sv + (uint32_t)(r * 144 + c * 16), vb + (size_t)r * 3072 + c * 8);
        }
        if (tid < 64) mkp[st * 64 + tid] = pad[tokBase + k0 + tid] ? -1e9f : 0.f;
    };

    prefetch(0, 0);
    asm volatile("cp.async.commit_group;");
    asm volatile("cp.async.wait_group 1;");   // Q done (k-tile 0 may be pending)
    __syncthreads();

    const int arow = j8 + (gi & 1) * 8, aoff = (gi >> 1) * 16;
    const int brow = j8 + (gi >> 1) * 8, boff = (gi & 1) * 16;

    uint32_t qa[4][4];
#pragma unroll
    for (int kd = 0; kd < 4; kd++)
        ldm_x4(qa[kd], sQ + (uint32_t)((wid * 16 + arow) * 144 + kd * 32 + aoff));

    float m0v = -1e30f, m1v = -1e30f, l0 = 0.f, l1 = 0.f;
    float o[8][4];
#pragma unroll
    for (int dt = 0; dt < 8; dt++)
#pragma unroll
        for (int q = 0; q < 4; q++) o[dt][q] = 0.f;

    for (int kt = 0; kt < Sq / 64; kt++) {
        const int st = kt & 1;
        asm volatile("cp.async.wait_group 0;");   // k-tile kt complete (own)
        __syncthreads();                          // visibility + buffer handoff
        if (kt + 1 < Sq / 64) prefetch(st ^ 1, kt + 1);
        asm volatile("cp.async.commit_group;");

        const uint32_t sk = sK0 + (uint32_t)st * 9216, sv = sV0 + (uint32_t)st * 9216;
        float s[8][4];
#pragma unroll
        for (int j = 0; j < 8; j++)
#pragma unroll
            for (int q = 0; q < 4; q++) s[j][q] = 0.f;

#pragma unroll
        for (int jp = 0; jp < 4; jp++) {
#pragma unroll
            for (int kd = 0; kd < 4; kd++) {
                uint32_t bfr[4];
                ldm_x4(bfr, sk + (uint32_t)((jp * 16 + brow) * 144 + kd * 32 + boff));
                mma_bf16(s[2 * jp],     qa[kd], bfr[0], bfr[1]);
                mma_bf16(s[2 * jp + 1], qa[kd], bfr[2], bfr[3]);
            }
        }

        float rmax0 = -1e30f, rmax1 = -1e30f;
#pragma unroll
        for (int j = 0; j < 8; j++) {
            float mka = mkp[st * 64 + j * 8 + 2 * lc];
            float mkb = mkp[st * 64 + j * 8 + 2 * lc + 1];
            s[j][0] = fmaf(s[j][0], 0.125f, mka);
            s[j][1] = fmaf(s[j][1], 0.125f, mkb);
            s[j][2] = fmaf(s[j][2], 0.125f, mka);
            s[j][3] = fmaf(s[j][3], 0.125f, mkb);
            rmax0 = fmaxf(rmax0, fmaxf(s[j][0], s[j][1]));
            rmax1 = fmaxf(rmax1, fmaxf(s[j][2], s[j][3]));
        }
        rmax0 = fmaxf(rmax0, __shfl_xor_sync(0xffffffffu, rmax0, 1));
        rmax0 = fmaxf(rmax0, __shfl_xor_sync(0xffffffffu, rmax0, 2));
        rmax1 = fmaxf(rmax1, __shfl_xor_sync(0xffffffffu, rmax1, 1));
        rmax1 = fmaxf(rmax1, __shfl_xor_sync(0xffffffffu, rmax1, 2));
        float nm0 = fmaxf(m0v, rmax0), nm1 = fmaxf(m1v, rmax1);
        float c0 = expp(m0v - nm0), c1 = expp(m1v - nm1);
        m0v = nm0; m1v = nm1;
        float rs0 = 0.f, rs1 = 0.f;
#pragma unroll
        for (int j = 0; j < 8; j++) {
            s[j][0] = expp(s[j][0] - nm0); s[j][1] = expp(s[j][1] - nm0);
            s[j][2] = expp(s[j][2] - nm1); s[j][3] = expp(s[j][3] - nm1);
            rs0 += s[j][0] + s[j][1];
            rs1 += s[j][2] + s[j][3];
        }
        rs0 += __shfl_xor_sync(0xffffffffu, rs0, 1);
        rs0 += __shfl_xor_sync(0xffffffffu, rs0, 2);
        rs1 += __shfl_xor_sync(0xffffffffu, rs1, 1);
        rs1 += __shfl_xor_sync(0xffffffffu, rs1, 2);
        l0 = l0 * c0 + rs0; l1 = l1 * c1 + rs1;
#pragma unroll
        for (int dt = 0; dt < 8; dt++) {
            o[dt][0] *= c0; o[dt][1] *= c0; o[dt][2] *= c1; o[dt][3] *= c1;
        }

        uint32_t pa[4][4];
#pragma unroll
        for (int t = 0; t < 4; t++) {
            pa[t][0] = pack_bf(s[2 * t][0],     s[2 * t][1]);
            pa[t][1] = pack_bf(s[2 * t][2],     s[2 * t][3]);
            pa[t][2] = pack_bf(s[2 * t + 1][0], s[2 * t + 1][1]);
            pa[t][3] = pack_bf(s[2 * t + 1][2], s[2 * t + 1][3]);
        }
#pragma unroll
        for (int t = 0; t < 4; t++) {
#pragma unroll
            for (int dp = 0; dp < 4; dp++) {
                uint32_t vf[4];
                ldm_x4t(vf, sv + (uint32_t)((t * 16 + arow) * 144 + dp * 32 + aoff));
                mma_bf16(o[2 * dp],     pa[t], vf[0], vf[1]);
                mma_bf16(o[2 * dp + 1], pa[t], vf[2], vf[3]);
            }
        }
    }

    float inv0 = 1.f / l0, inv1 = 1.f / l1;
    const int rg = q0 + wid * 16 + lr;
    bf16* ob = outp + (tokBase + rg) * Dm + h * 64;
#pragma unroll
    for (int dt = 0; dt < 8; dt++) {
        *(bf162*)(ob + dt * 8 + 2 * lc) =
            __float22bfloat162_rn(make_float2(o[dt][0] * inv0, o[dt][1] * inv0));
        *(bf162*)(ob + (size_t)8 * Dm + dt * 8 + 2 * lc) =
            __float22bfloat162_rn(make_float2(o[dt][2] * inv1, o[dt][3] * inv1));
    }
}

// ---------------------------------------------------------------------------
// LayerNorm (bf16 out, for LN1)
// ---------------------------------------------------------------------------
__global__ __launch_bounds__(256) void ln_kernel(const float* __restrict__ in,
                                                 const float* __restrict__ g,
                                                 const float* __restrict__ b,
                                                 bf16* __restrict__ out)
{
    int n = blockIdx.x, tid = threadIdx.x;
    float4 v = ((const float4*)(in + (size_t)n*Dm))[tid];
    float s  = v.x+v.y+v.z+v.w;
    float s2 = v.x*v.x+v.y*v.y+v.z*v.z+v.w*v.w;
    __shared__ float r1[256], r2[256];
    r1[tid]=s; r2[tid]=s2; __syncthreads();
    for (int st=128; st; st>>=1) {
        if (tid<st) { r1[tid]+=r1[tid+st]; r2[tid]+=r2[tid+st]; }
        __syncthreads();
    }
    float mean = r1[0]*(1.0f/Dm);
    float var  = r2[0]*(1.0f/Dm) - mean*mean;
    float rstd = rsqrtf(var + 1e-5f);
    float4 gg = ((const float4*)g)[tid];
    float4 bb = ((const float4*)b)[tid];
    float o0 = (v.x-mean)*rstd*gg.x + bb.x;
    float o1 = (v.y-mean)*rstd*gg.y + bb.y;
    float o2 = (v.z-mean)*rstd*gg.z + bb.z;
    float o3 = (v.w-mean)*rstd*gg.w + bb.w;
    size_t base = (size_t)n*Dm + tid*4;
    store_pair(out, base, o0, o1);
    store_pair(out, base + 2, o2, o3);
}

// ---------------------------------------------------------------------------
// LN2 + router fused
// ---------------------------------------------------------------------------
__global__ __launch_bounds__(256) void ln2_router(const float* __restrict__ in,
                                                  const float* __restrict__ g,
                                                  const float* __restrict__ b,
                                                  bf16* __restrict__ outh,
                                                  const float* __restrict__ rw,
                                                  const float* __restrict__ rb,
                                                  const unsigned char* __restrict__ pad)
{
    int n = blockIdx.x, tid = threadIdx.x;
    __shared__ float r1[256], r2[256];
    __shared__ float xs[1024];
    __shared__ float lg[8];
    float4 v = ((const float4*)(in + (size_t)n*Dm))[tid];
    float s  = v.x+v.y+v.z+v.w;
    float s2 = v.x*v.x+v.y*v.y+v.z*v.z+v.w*v.w;
    r1[tid]=s; r2[tid]=s2; __syncthreads();
    for (int st=128; st; st>>=1) {
        if (tid<st) { r1[tid]+=r1[tid+st]; r2[tid]+=r2[tid+st]; }
        __syncthreads();
    }
    float mean = r1[0]*(1.0f/Dm);
    float var  = r2[0]*(1.0f/Dm) - mean*mean;
    float rstd = rsqrtf(var + 1e-5f);
    float4 gg = ((const float4*)g)[tid];
    float4 bb = ((const float4*)b)[tid];
    float4 o;
    o.x = (v.x-mean)*rstd*gg.x + bb.x;
    o.y = (v.y-mean)*rstd*gg.y + bb.y;
    o.z = (v.z-mean)*rstd*gg.z + bb.z;
    o.w = (v.w-mean)*rstd*gg.w + bb.w;
    bf162* hp = (bf162*)(outh + (size_t)n*Dm);
    hp[tid*2]   = __float22bfloat162_rn(make_float2(o.x, o.y));
    hp[tid*2+1] = __float22bfloat162_rn(make_float2(o.z, o.w));
    ((float4*)xs)[tid] = o;
    __syncthreads();
    int w = tid >> 5, lane = tid & 31;
    float acc = 0.f;
    for (int i = lane; i < 1024; i += 32) acc += xs[i] * rw[i*8 + w];
    for (int off=16; off; off>>=1) acc += __shfl_xor_sync(0xffffffffu, acc, off);
    if (lane == 0) lg[w] = acc + rb[w];
    __syncthreads();
    if (tid == 0) {
        float mx = lg[0]; int ei = 0;
        for (int e=1;e<8;e++) if (lg[e] > mx) { mx = lg[e]; ei = e; }
        float pr[8], se = 0.f;
        for (int e=0;e<8;e++) { pr[e] = expf(lg[e]-mx); se += pr[e]; }
        float inv = 1.f/se;
        bool valid = (pad[n] == 0);
        float tm = valid ? 1.f : 0.f;
        for (int e=0;e<8;e++) g_probs[n*8+e] = pr[e]*inv*tm;
        g_gate[n] = pr[ei]*inv;
        g_eidx[n] = ei;
        float lse = mx + logf(se);
        g_zterm[n] = lse*lse*tm;
    }
}

// ---------------------------------------------------------------------------
// Weight prep
// ---------------------------------------------------------------------------
__global__ __launch_bounds__(256) void bf16_copy(const float* __restrict__ in,
                                                 bf16* __restrict__ out, int n4)
{
    int i = blockIdx.x*256 + threadIdx.x;
    if (i < n4) {
        float4 v = ((const float4*)in)[i];
        ((bf162*)out)[i*2]   = __float22bfloat162_rn(make_float2(v.x, v.y));
        ((bf162*)out)[i*2+1] = __float22bfloat162_rn(make_float2(v.z, v.w));
    }
}

__global__ __launch_bounds__(256) void transpose_bf16(const float* __restrict__ in,
                                                      bf16* __restrict__ out,
                                                      int R, int Cc)
{
    __shared__ float t[32][33];
    int e = blockIdx.z;
    const float* ip = in  + (size_t)e*R*Cc;
    bf16* op        = out + (size_t)e*R*Cc;
    int c0 = blockIdx.x*32, r0 = blockIdx.y*32;
    int tx = threadIdx.x, ty = threadIdx.y;
#pragma unroll
    for (int j=0;j<32;j+=8)
        t[ty+j][tx] = ip[(size_t)(r0+ty+j)*Cc + c0+tx];
    __syncthreads();
#pragma unroll
    for (int j=0;j<32;j+=8)
        op[(size_t)(c0+ty+j)*R + r0+tx] = __float2bfloat16_rn(t[tx][ty+j]);
}

// ---------------------------------------------------------------------------
// Routing scan: smem-staged, warp 0 does exact token-order scan.
// ---------------------------------------------------------------------------
__global__ __launch_bounds__(1024) void scan_kernel(const unsigned char* __restrict__ pad)
{
    __shared__ unsigned char sc[Ntok];
    __shared__ int base[8];
    int tid = threadIdx.x;
    for (int i = tid; i < SLOTS; i += 1024) g_tok[i] = -1;
    for (int i = tid; i < Ntok; i += 1024)
        sc[i] = (unsigned char)(g_eidx[i] | (pad[i] ? 0 : 16));
    if (tid < 8) base[tid] = 0;
    __syncthreads();
    if (tid < 32) {
        int lane = tid;
        for (int c = 0; c < Ntok/32; c++) {
            int i = c*32 + lane;
            int code = sc[i];
            int e = code & 7;
            bool valid = (code & 16) != 0;
            unsigned peers = __match_any_sync(0xffffffffu, e);
            unsigned vmask = __ballot_sync(0xffffffffu, valid);
            unsigned pv = peers & vmask;
            int myrank = __popc(pv & ((1u << lane) - 1u));
            int b0 = base[e];
            __syncwarp();
            int pos = b0 + myrank;
            bool keep = valid && (pos < CAP);
            if (keep) g_tok[e*CAP + pos] = i;
            if (valid && lane == (__ffs(pv) - 1)) base[e] = b0 + __popc(pv);
            __syncwarp();
        }
        if (lane < 8) g_cnt[lane] = base[lane];
    }
}

// ---------------------------------------------------------------------------
// Loss reduction
// ---------------------------------------------------------------------------
__global__ __launch_bounds__(256) void loss_kernel(const unsigned char* __restrict__ pad,
                                                   float* __restrict__ out)
{
    int tid = threadIdx.x;
    float zs = 0.f, ps[8];
    int cnt = 0;
#pragma unroll
    for (int e=0;e<8;e++) ps[e]=0.f;
    for (int n = tid; n < Ntok; n += 256) {
        if (pad[n] == 0) cnt++;
        zs += g_zterm[n];
#pragma unroll
        for (int e=0;e<8;e++) ps[e] += g_probs[n*8+e];
    }
    __shared__ float red[256];
    __shared__ float res[10];
    float vals[10];
    vals[0] = (float)cnt; vals[1] = zs;
    for (int e=0;e<8;e++) vals[2+e] = ps[e];
    for (int q=0;q<10;q++) {
        red[tid] = vals[q]; __syncthreads();
        for (int st=128; st; st>>=1) {
            if (tid < st) red[tid] += red[tid+st];
            __syncthreads();
        }
        if (tid == 0) res[q] = red[0];
        __syncthreads();
    }
    if (tid == 0) {
        float denom = fmaxf(res[0], 1.f);
        float lb = 0.f;
        for (int e=0;e<8;e++) lb += ((float)g_cnt[e]/denom) * (res[2+e]/denom);
        lb *= (float)Ee;
        out[(size_t)Ntok*Dm]     = lb;
        out[(size_t)Ntok*Dm + 1] = res[1]/denom;
    }
}

// ---------------------------------------------------------------------------
// Launch
// ---------------------------------------------------------------------------
extern "C" void kernel_launch(void* const* d_in, const int* in_sizes, int n_in,
                              void* d_out, int out_size)
{
    const float* src  = (const float*)d_in[0];
    const unsigned char* pad = (const unsigned char*)d_in[1];
    const float* ln1g = (const float*)d_in[2];
    const float* ln1b = (const float*)d_in[3];
    const float* ipw  = (const float*)d_in[4];
    const float* ipb  = (const float*)d_in[5];
    const float* opw  = (const float*)d_in[6];
    const float* opb  = (const float*)d_in[7];
    const float* ln2g = (const float*)d_in[8];
    const float* ln2b = (const float*)d_in[9];
    const float* rw   = (const float*)d_in[10];
    const float* rb   = (const float*)d_in[11];
    const float* w1   = (const float*)d_in[12];
    const float* b1   = (const float*)d_in[13];
    const float* w2   = (const float*)d_in[14];
    const float* b2   = (const float*)d_in[15];
    float* out = (float*)d_out;

    bf16 *xln, *qkv, *attn, *x2b, *hb, *ipw16, *opw16, *w1t, *w2t;
    float *src1, *gate;
    int *tok;
    cudaGetSymbolAddress((void**)&xln,  g_xln);
    cudaGetSymbolAddress((void**)&qkv,  g_qkv);
    cudaGetSymbolAddress((void**)&attn, g_attn);
    cudaGetSymbolAddress((void**)&src1, g_src1);
    cudaGetSymbolAddress((void**)&x2b,  g_x2b);
    cudaGetSymbolAddress((void**)&hb,   g_hbuf);
    cudaGetSymbolAddress((void**)&ipw16, g_ipw16);
    cudaGetSymbolAddress((void**)&opw16, g_opw16);
    cudaGetSymbolAddress((void**)&w1t,  g_w1t);
    cudaGetSymbolAddress((void**)&w2t,  g_w2t);
    cudaGetSymbolAddress((void**)&tok,  g_tok);
    cudaGetSymbolAddress((void**)&gate, g_gate);

    // Lazily-created side stream + events (host objects; no device memory).
    static cudaStream_t s2 = nullptr;
    static cudaEvent_t ev0 = nullptr, evA = nullptr, ev1 = nullptr,
                       ev2 = nullptr, ev3 = nullptr;
    if (!s2) {
        cudaStreamCreateWithFlags(&s2, cudaStreamNonBlocking);
        cudaEventCreateWithFlags(&ev0, cudaEventDisableTiming);
        cudaEventCreateWithFlags(&evA, cudaEventDisableTiming);
        cudaEventCreateWithFlags(&ev1, cudaEventDisableTiming);
        cudaEventCreateWithFlags(&ev2, cudaEventDisableTiming);
        cudaEventCreateWithFlags(&ev3, cudaEventDisableTiming);
    }

    cudaFuncSetAttribute(attn_mma, cudaFuncAttributeMaxDynamicSharedMemorySize, AT_SMEM);
    cudaFuncSetAttribute(gemm_mma<bf16,false,false,false,false,false>, cudaFuncAttributeMaxDynamicSharedMemorySize, GEMM_SMEM);
    cudaFuncSetAttribute(gemm_mma<float,false,true,false,false,true>,  cudaFuncAttributeMaxDynamicSharedMemorySize, GEMM_SMEM);
    cudaFuncSetAttribute(gemm_mma<bf16,true,false,true,false,false>,   cudaFuncAttributeMaxDynamicSharedMemorySize, GEMM_SMEM);
    cudaFuncSetAttribute(gemm_mma<float,false,false,false,true,false>, cudaFuncAttributeMaxDynamicSharedMemorySize, GEMM_SMEM);

    // Fork: ALL weight prep on side stream. ipw16 first (QKV gates on evA).
    cudaEventRecord(ev0, 0);
    cudaStreamWaitEvent(s2, ev0, 0);
    bf16_copy<<<(3*Dm*Dm/4 + 255)/256, 256, 0, s2>>>(ipw, ipw16, 3*Dm*Dm/4);
    cudaEventRecord(evA, s2);
    bf16_copy<<<(Dm*Dm/4 + 255)/256, 256, 0, s2>>>(opw, opw16, Dm*Dm/4);
    transpose_bf16<<<dim3(Ff/32, Dm/32, Ee), dim3(32,8), 0, s2>>>(w1, w1t, Dm, Ff);
    transpose_bf16<<<dim3(Dm/32, Ff/32, Ee), dim3(32,8), 0, s2>>>(w2, w2t, Ff, Dm);
    cudaEventRecord(ev1, s2);

    // Main stream: LN1 overlaps ipw copy.
    ln_kernel<<<Ntok, 256>>>(src, ln1g, ln1b, xln);
    cudaStreamWaitEvent(0, evA, 0);
    // 2. QKV -> bf16
    gemm_mma<bf16,false,false,false,false,false><<<dim3(3072/BN, Ntok/BM), 256, GEMM_SMEM>>>(
        xln, ipw16, ipb, nullptr, qkv, nullptr, 3072, 1024, 1<<30, 0, 0, nullptr, nullptr);
    // 3. Attention -> bf16
    attn_mma<<<dim3(Sq/128, Bc*Hh), 256, AT_SMEM>>>(qkv, pad, attn);
    // Join prep before out_proj (opw16) / FFN (w1t/w2t).
    cudaStreamWaitEvent(0, ev1, 0);
    // 4. out_proj + residual(src) -> src1 AND out (dual store)
    gemm_mma<float,false,true,false,false,true><<<dim3(1024/BN, Ntok/BM), 256, GEMM_SMEM>>>(
        attn, opw16, opb, src, src1, out, 1024, 1024, 1<<30, 0, 0, nullptr, nullptr);
    // 5. LN2 + router fused
    ln2_router<<<Ntok, 256>>>(src1, ln2g, ln2b, x2b, rw, rb, pad);
    // 6. Scan
    scan_kernel<<<1, 1024>>>(pad);
    // Fork: loss on side stream (writes out tail elements only).
    cudaEventRecord(ev2, 0);
    cudaStreamWaitEvent(s2, ev2, 0);
    loss_kernel<<<1, 256, 0, s2>>>(pad, out);
    cudaEventRecord(ev3, s2);
    // 7. FFN1 (gathered A, relu, empty-tile skip) -> bf16 hbuf
    gemm_mma<bf16,true,false,true,false,false><<<dim3(Ff/BN, SLOTS/BM), 256, GEMM_SMEM>>>(
        x2b, w1t, b1, nullptr, hb, nullptr, Ff, 1024, CAP, (long long)Dm*Ff, Ff, tok, nullptr);
    // 8. FFN2 (scatter-add into out with gate, empty-tile skip)
    gemm_mma<float,false,false,false,true,false><<<dim3(Dm/BN, SLOTS/BM), 256, GEMM_SMEM>>>(
        hb, w2t, b2, nullptr, out, nullptr, Dm, Ff, CAP, (long long)Ff*Dm, Dm, tok, gate);
    // Join loss back into main stream.
    cudaStreamWaitEvent(0, ev3, 0);
}